// round 1
// baseline (speedup 1.0000x reference)
#include <cuda_runtime.h>

// Problem constants
#define BB   16
#define CC   256
#define LL   4096
#define NHH  8
#define HCC  32
#define FH   512
#define FH2  1024
#define NPIX (BB*LL)
#define NSPLIT 32

// ---------------------------------------------------------------------------
// Scratch (static __device__ arrays; no runtime allocation allowed)
// ---------------------------------------------------------------------------
__device__ __align__(128) float g_Wgq[CC*CC];
__device__ __align__(128) float g_Wgk[CC*CC];
__device__ __align__(128) float g_Wgv[CC*CC];
__device__ __align__(128) float g_Wg1[FH2*CC];
__device__ float g_wsq[CC], g_wbq[CC];
__device__ float g_wsk[CC], g_wbk[CC];
__device__ float g_wsv[CC], g_wbv[CC];
__device__ float g_ws1[FH2], g_wb1v[FH2];
__device__ float g_mu_o[NPIX], g_rs_o[NPIX];
__device__ float g_mu_s[NPIX], g_rs_s[NPIX];
__device__ float g_mu_x[NPIX], g_rs_x[NPIX];
__device__ __align__(128) float g_q[BB*CC*LL];
__device__ __align__(128) float g_k[BB*CC*LL];
__device__ __align__(128) float g_v[BB*CC*LL];
__device__ __align__(128) float g_attn[BB*CC*LL];
__device__ __align__(128) float g_x[BB*CC*LL];
__device__ __align__(128) float g_hg[BB*FH*LL];
__device__ __align__(128) float g_Sp[BB*NHH*NSPLIT*HCC*HCC];
__device__ __align__(128) float g_A[BB*NHH*HCC*HCC];

// ---------------------------------------------------------------------------
// Weight prep: fold LN gain into W, compute rowsum(W*g) and W@beta (+b1)
// ---------------------------------------------------------------------------
__global__ void prep_kernel(const float* __restrict__ Wq, const float* __restrict__ Wk,
                            const float* __restrict__ Wv, const float* __restrict__ W1,
                            const float* __restrict__ gopt, const float* __restrict__ bopt,
                            const float* __restrict__ gsar, const float* __restrict__ bsar,
                            const float* __restrict__ gffn, const float* __restrict__ bffn,
                            const float* __restrict__ b1)
{
    int row = blockIdx.x;   // 0..1791
    int c   = threadIdx.x;  // 0..255
    const float* W; float* Wg; float* ws; float* wb;
    const float* gg; const float* bb; int m; float extra = 0.f;
    if (row < 256)      { W=Wq; Wg=g_Wgq; ws=g_wsq; wb=g_wbq; gg=gopt; bb=bopt; m=row; }
    else if (row < 512) { W=Wk; Wg=g_Wgk; ws=g_wsk; wb=g_wbk; gg=gsar; bb=bsar; m=row-256; }
    else if (row < 768) { W=Wv; Wg=g_Wgv; ws=g_wsv; wb=g_wbv; gg=gsar; bb=bsar; m=row-512; }
    else                { W=W1; Wg=g_Wg1; ws=g_ws1; wb=g_wb1v; gg=gffn; bb=bffn; m=row-768;
                          extra = b1[row-768]; }
    float w  = W[m*CC + c];
    float wg = w * gg[c];
    Wg[m*CC + c] = wg;
    __shared__ float s1[256], s2[256];
    s1[c] = wg; s2[c] = w * bb[c];
    __syncthreads();
    for (int off = 128; off > 0; off >>= 1) {
        if (c < off) { s1[c] += s1[c+off]; s2[c] += s2[c+off]; }
        __syncthreads();
    }
    if (c == 0) { ws[m] = s1[0]; wb[m] = s2[0] + extra; }
}

// ---------------------------------------------------------------------------
// Per-pixel LN stats over channel axis (biased var, eps=1e-5)
// ---------------------------------------------------------------------------
__global__ void ln_stats_kernel(const float* __restrict__ x,
                                float* __restrict__ mu, float* __restrict__ rs)
{
    int p = blockIdx.x * blockDim.x + threadIdx.x;
    if (p >= NPIX) return;
    int b = p >> 12, l = p & (LL-1);
    const float* base = x + (size_t)b*CC*LL + l;
    float s = 0.f, s2 = 0.f;
#pragma unroll 8
    for (int c = 0; c < CC; c++) {
        float v = __ldg(base + (size_t)c*LL);
        s += v; s2 = fmaf(v, v, s2);
    }
    float m   = s * (1.f/CC);
    float var = fmaf(-m, m, s2 * (1.f/CC));
    mu[p] = m;
    rs[p] = rsqrtf(var + 1e-5f);
}

// ---------------------------------------------------------------------------
// Generic tiled SGEMM: Y[b] = A(MDxKD) @ X[b](KDxLL)
// MODE 0: epilogue y = rs[p]*(acc - mu[p]*wsum[m]) + wb[m]          (LN-folded)
// MODE 1: y = acc + res                                              (Wo + residual)
// MODE 2: y = acc + bias[m] + res                                    (W2 + b2 + residual)
// ---------------------------------------------------------------------------
template<int MODE, int KD, int MD>
__global__ __launch_bounds__(256, 2)
void gemm_kernel(const float* __restrict__ A, const float* __restrict__ X,
                 float* __restrict__ Y,
                 const float* __restrict__ mu, const float* __restrict__ rs,
                 const float* __restrict__ wsum, const float* __restrict__ wb,
                 const float* __restrict__ res, const float* __restrict__ bias)
{
    __shared__ float As[8][128];
    __shared__ float Bs[8][128];
    int tid = threadIdx.x;
    int bx = blockIdx.x, by = blockIdx.y, b = blockIdx.z;
    int m0 = by*128, n0 = bx*128;
    const float* Ap = A + (size_t)m0*KD;
    const float* Xp = X + (size_t)b*KD*LL + n0;
    int arow = tid >> 1,  acol = (tid & 1)*4;
    int brow = tid >> 5,  bcol = (tid & 31)*4;
    int tx = tid & 15, ty = tid >> 4;
    float acc[8][8];
#pragma unroll
    for (int i=0;i<8;i++)
#pragma unroll
        for (int j=0;j<8;j++) acc[i][j]=0.f;

    for (int k0 = 0; k0 < KD; k0 += 8) {
        float4 av = *(const float4*)(Ap + (size_t)arow*KD + k0 + acol);
        float4 bv = *(const float4*)(Xp + (size_t)(k0 + brow)*LL + bcol);
        __syncthreads();
        As[acol+0][arow]=av.x; As[acol+1][arow]=av.y;
        As[acol+2][arow]=av.z; As[acol+3][arow]=av.w;
        *(float4*)&Bs[brow][bcol] = bv;
        __syncthreads();
#pragma unroll
        for (int kk=0; kk<8; kk++) {
            float af[8], bf[8];
            *(float4*)af     = *(const float4*)&As[kk][ty*8];
            *(float4*)(af+4) = *(const float4*)&As[kk][ty*8+4];
            *(float4*)bf     = *(const float4*)&Bs[kk][tx*8];
            *(float4*)(bf+4) = *(const float4*)&Bs[kk][tx*8+4];
#pragma unroll
            for (int i=0;i<8;i++)
#pragma unroll
                for (int j=0;j<8;j++)
                    acc[i][j] = fmaf(af[i], bf[j], acc[i][j]);
        }
    }

    int pb = b*LL + n0 + tx*8;
    float muv[8], rsv[8];
    if (MODE == 0) {
#pragma unroll
        for (int j=0;j<8;j++){ muv[j]=mu[pb+j]; rsv[j]=rs[pb+j]; }
    }
#pragma unroll
    for (int i=0;i<8;i++) {
        int m = m0 + ty*8 + i;
        float wsv = (MODE==0) ? wsum[m] : 0.f;
        float wbv = (MODE==0) ? wb[m] : (MODE==2 ? bias[m] : 0.f);
        float* yp = Y + (size_t)b*MD*LL + (size_t)m*LL + n0 + tx*8;
        const float* rp = (MODE>=1) ? (res + (size_t)b*MD*LL + (size_t)m*LL + n0 + tx*8) : (const float*)0;
#pragma unroll
        for (int j=0;j<8;j++) {
            float v = acc[i][j];
            if (MODE==0)      v = rsv[j]*(v - muv[j]*wsv) + wbv;
            else if (MODE==1) v = v + rp[j];
            else              v = v + wbv + rp[j];
            yp[j] = v;
        }
    }
}

// ---------------------------------------------------------------------------
// W1 GEMM with LN fold + fused SimpleGate: hg = h[0:512] * h[512:1024]
// Each block computes a 64x128 tile of BOTH halves and writes the product.
// ---------------------------------------------------------------------------
__global__ __launch_bounds__(256, 2)
void gemm_gated_kernel(const float* __restrict__ X)
{
    __shared__ float As1[8][64], As2[8][64], Bs[8][128];
    int tid = threadIdx.x;
    int bx = blockIdx.x, by = blockIdx.y, b = blockIdx.z;
    int m0 = by*64, n0 = bx*128;
    const float* Xp = X + (size_t)b*CC*LL + n0;
    int brow = tid >> 5, bcol = (tid & 31)*4;
    int ar = (tid & 127) >> 1, acl = (tid & 1)*4;
    bool second = (tid >= 128);
    const float* Ap = g_Wg1 + (size_t)(m0 + (second ? FH : 0) + ar)*CC + acl;
    int tx = tid & 15, ty = tid >> 4;
    float acc1[4][8], acc2[4][8];
#pragma unroll
    for (int i=0;i<4;i++)
#pragma unroll
        for (int j=0;j<8;j++){ acc1[i][j]=0.f; acc2[i][j]=0.f; }

    for (int k0 = 0; k0 < CC; k0 += 8) {
        float4 av = *(const float4*)(Ap + k0);
        float4 bv = *(const float4*)(Xp + (size_t)(k0 + brow)*LL + bcol);
        __syncthreads();
        float (*Asel)[64] = second ? As2 : As1;
        Asel[acl+0][ar]=av.x; Asel[acl+1][ar]=av.y;
        Asel[acl+2][ar]=av.z; Asel[acl+3][ar]=av.w;
        *(float4*)&Bs[brow][bcol] = bv;
        __syncthreads();
#pragma unroll
        for (int kk=0; kk<8; kk++) {
            float a1[4], a2[4], bf[8];
            *(float4*)a1     = *(const float4*)&As1[kk][ty*4];
            *(float4*)a2     = *(const float4*)&As2[kk][ty*4];
            *(float4*)bf     = *(const float4*)&Bs[kk][tx*8];
            *(float4*)(bf+4) = *(const float4*)&Bs[kk][tx*8+4];
#pragma unroll
            for (int i=0;i<4;i++)
#pragma unroll
                for (int j=0;j<8;j++) {
                    acc1[i][j] = fmaf(a1[i], bf[j], acc1[i][j]);
                    acc2[i][j] = fmaf(a2[i], bf[j], acc2[i][j]);
                }
        }
    }

    int pb = b*LL + n0 + tx*8;
    float muv[8], rsv[8];
#pragma unroll
    for (int j=0;j<8;j++){ muv[j]=g_mu_x[pb+j]; rsv[j]=g_rs_x[pb+j]; }
#pragma unroll
    for (int i=0;i<4;i++) {
        int m  = m0 + ty*4 + i;
        int m2 = m + FH;
        float ws1 = g_ws1[m],  wb1 = g_wb1v[m];
        float ws2 = g_ws1[m2], wb2 = g_wb1v[m2];
        float* yp = g_hg + (size_t)b*FH*LL + (size_t)m*LL + n0 + tx*8;
#pragma unroll
        for (int j=0;j<8;j++) {
            float e1 = rsv[j]*(acc1[i][j] - muv[j]*ws1) + wb1;
            float e2 = rsv[j]*(acc2[i][j] - muv[j]*ws2) + wb2;
            yp[j] = e1*e2;
        }
    }
}

// ---------------------------------------------------------------------------
// Attention: S partials (32x32 per (b,h), split over L), softmax, A@V
// ---------------------------------------------------------------------------
__global__ __launch_bounds__(128)
void attn_s_kernel()
{
    __shared__ float qs[HCC][129];
    __shared__ float ks[HCC][129];
    int bh = blockIdx.x, sp = blockIdx.y;
    int b = bh >> 3, h = bh & 7;
    int l0 = sp * 128;
    int tid = threadIdx.x;
    const float* qp = g_q + (size_t)b*CC*LL + (size_t)(h*HCC)*LL + l0;
    const float* kp = g_k + (size_t)b*CC*LL + (size_t)(h*HCC)*LL + l0;
    for (int idx = tid; idx < HCC*128; idx += 128) {
        int r = idx >> 7, ci = idx & 127;
        qs[r][ci] = qp[(size_t)r*LL + ci];
        ks[r][ci] = kp[(size_t)r*LL + ci];
    }
    __syncthreads();
    int d2 = tid & 15, cy = tid >> 4;
    float acc[2][4] = {{0.f,0.f,0.f,0.f},{0.f,0.f,0.f,0.f}};
#pragma unroll 4
    for (int l = 0; l < 128; l++) {
        float k0v = ks[2*d2][l], k1v = ks[2*d2+1][l];
#pragma unroll
        for (int i=0;i<4;i++) {
            float qv = qs[cy + 8*i][l];
            acc[0][i] = fmaf(qv, k0v, acc[0][i]);
            acc[1][i] = fmaf(qv, k1v, acc[1][i]);
        }
    }
    float* out = g_Sp + ((size_t)bh*NSPLIT + sp)*1024;
#pragma unroll
    for (int i=0;i<4;i++) {
        int c = cy + 8*i;
        out[c*32 + 2*d2]   = acc[0][i];
        out[c*32 + 2*d2+1] = acc[1][i];
    }
}

__global__ void attn_softmax_kernel()
{
    int bh = blockIdx.x, t = threadIdx.x;  // t = c*32 + d ; lane = d
    float s = 0.f;
    const float* sp = g_Sp + (size_t)bh*NSPLIT*1024 + t;
#pragma unroll
    for (int i=0;i<NSPLIT;i++) s += sp[(size_t)i*1024];
    s *= 0.17677669529663687f;  // 32^-0.5
    float mx = s;
#pragma unroll
    for (int o=16;o>0;o>>=1) mx = fmaxf(mx, __shfl_xor_sync(0xffffffffu, mx, o));
    float e = expf(s - mx);
    float sum = e;
#pragma unroll
    for (int o=16;o>0;o>>=1) sum += __shfl_xor_sync(0xffffffffu, sum, o);
    g_A[(size_t)bh*1024 + t] = e / sum;
}

__global__ __launch_bounds__(256)
void attn_av_kernel()
{
    __shared__ float As[1024];
    int bh = blockIdx.x;
    int b = bh >> 3, h = bh & 7;
    int tid = threadIdx.x;
#pragma unroll
    for (int i=0;i<4;i++) As[tid + 256*i] = g_A[(size_t)bh*1024 + tid + 256*i];
    __syncthreads();
    int l = blockIdx.y*512 + tid;
    const float* vp = g_v + (size_t)b*CC*LL + (size_t)(h*HCC)*LL + l;
    float acc0[32], acc1[32];
#pragma unroll
    for (int c=0;c<32;c++){ acc0[c]=0.f; acc1[c]=0.f; }
#pragma unroll 4
    for (int d=0; d<32; d++) {
        float v0 = vp[(size_t)d*LL];
        float v1 = vp[(size_t)d*LL + 256];
#pragma unroll
        for (int c=0;c<32;c++) {
            float a = As[c*32+d];
            acc0[c] = fmaf(a, v0, acc0[c]);
            acc1[c] = fmaf(a, v1, acc1[c]);
        }
    }
    float* op = g_attn + (size_t)b*CC*LL + (size_t)(h*HCC)*LL + l;
#pragma unroll
    for (int c=0;c<32;c++) {
        op[(size_t)c*LL]       = acc0[c];
        op[(size_t)c*LL + 256] = acc1[c];
    }
}

// ---------------------------------------------------------------------------
// Launcher
// ---------------------------------------------------------------------------
extern "C" void kernel_launch(void* const* d_in, const int* in_sizes, int n_in,
                              void* d_out, int out_size)
{
    (void)in_sizes; (void)n_in; (void)out_size;
    const float* optical = (const float*)d_in[0];
    const float* sar     = (const float*)d_in[1];
    const float* gopt    = (const float*)d_in[2];
    const float* bopt    = (const float*)d_in[3];
    const float* gsar    = (const float*)d_in[4];
    const float* bsar    = (const float*)d_in[5];
    const float* Wq      = (const float*)d_in[6];
    const float* Wk      = (const float*)d_in[7];
    const float* Wv      = (const float*)d_in[8];
    const float* Wo      = (const float*)d_in[9];
    const float* gffn    = (const float*)d_in[10];
    const float* bffn    = (const float*)d_in[11];
    const float* W1      = (const float*)d_in[12];
    const float* b1      = (const float*)d_in[13];
    const float* W2      = (const float*)d_in[14];
    const float* b2      = (const float*)d_in[15];
    float* out = (float*)d_out;

    float *p_Wgq, *p_Wgk, *p_Wgv;
    float *p_wsq, *p_wbq, *p_wsk, *p_wbk, *p_wsv, *p_wbv;
    float *p_mu_o, *p_rs_o, *p_mu_s, *p_rs_s, *p_mu_x, *p_rs_x;
    float *p_q, *p_k, *p_v, *p_attn, *p_x, *p_hg;
    cudaGetSymbolAddress((void**)&p_Wgq, g_Wgq);
    cudaGetSymbolAddress((void**)&p_Wgk, g_Wgk);
    cudaGetSymbolAddress((void**)&p_Wgv, g_Wgv);
    cudaGetSymbolAddress((void**)&p_wsq, g_wsq);
    cudaGetSymbolAddress((void**)&p_wbq, g_wbq);
    cudaGetSymbolAddress((void**)&p_wsk, g_wsk);
    cudaGetSymbolAddress((void**)&p_wbk, g_wbk);
    cudaGetSymbolAddress((void**)&p_wsv, g_wsv);
    cudaGetSymbolAddress((void**)&p_wbv, g_wbv);
    cudaGetSymbolAddress((void**)&p_mu_o, g_mu_o);
    cudaGetSymbolAddress((void**)&p_rs_o, g_rs_o);
    cudaGetSymbolAddress((void**)&p_mu_s, g_mu_s);
    cudaGetSymbolAddress((void**)&p_rs_s, g_rs_s);
    cudaGetSymbolAddress((void**)&p_mu_x, g_mu_x);
    cudaGetSymbolAddress((void**)&p_rs_x, g_rs_x);
    cudaGetSymbolAddress((void**)&p_q, g_q);
    cudaGetSymbolAddress((void**)&p_k, g_k);
    cudaGetSymbolAddress((void**)&p_v, g_v);
    cudaGetSymbolAddress((void**)&p_attn, g_attn);
    cudaGetSymbolAddress((void**)&p_x, g_x);
    cudaGetSymbolAddress((void**)&p_hg, g_hg);

    // 1) weight prep (LN fold)
    prep_kernel<<<1792, 256>>>(Wq, Wk, Wv, W1, gopt, bopt, gsar, bsar, gffn, bffn, b1);

    // 2) LN stats for optical / sar
    ln_stats_kernel<<<NPIX/128, 128>>>(optical, p_mu_o, p_rs_o);
    ln_stats_kernel<<<NPIX/128, 128>>>(sar,     p_mu_s, p_rs_s);

    // 3) Q/K/V projections with folded LN epilogue
    dim3 gp(LL/128, CC/128, BB);
    gemm_kernel<0,256,256><<<gp,256>>>(p_Wgq, optical, p_q, p_mu_o, p_rs_o, p_wsq, p_wbq, 0, 0);
    gemm_kernel<0,256,256><<<gp,256>>>(p_Wgk, sar,     p_k, p_mu_s, p_rs_s, p_wsk, p_wbk, 0, 0);
    gemm_kernel<0,256,256><<<gp,256>>>(p_Wgv, sar,     p_v, p_mu_s, p_rs_s, p_wsv, p_wbv, 0, 0);

    // 4) channel attention
    attn_s_kernel<<<dim3(BB*NHH, NSPLIT), 128>>>();
    attn_softmax_kernel<<<BB*NHH, 1024>>>();
    attn_av_kernel<<<dim3(BB*NHH, LL/512), 256>>>();

    // 5) Wo projection + residual -> x
    gemm_kernel<1,256,256><<<gp,256>>>(Wo, p_attn, p_x, 0, 0, 0, 0, optical, 0);

    // 6) LN stats on x
    ln_stats_kernel<<<NPIX/128, 128>>>(p_x, p_mu_x, p_rs_x);

    // 7) W1 GEMM (LN fold + b1 fold) + fused SimpleGate -> hg
    gemm_gated_kernel<<<dim3(LL/128, FH/64, BB), 256>>>(p_x);

    // 8) W2 GEMM + b2 + residual -> out
    gemm_kernel<2,512,256><<<gp,256>>>(W2, p_hg, out, 0, 0, 0, 0, p_x, b2);
}

// round 3
// speedup vs baseline: 1.6374x; 1.6374x over previous
#include <cuda_runtime.h>
#include <cuda_bf16.h>

typedef unsigned int u32;
typedef unsigned long long u64;

#define BB   16
#define CC   256
#define LL   4096
#define NHH  8
#define HCC  32
#define FH   512
#define FH2  1024
#define NPIX (BB*LL)
#define NSPLIT 32

// ---------------------------------------------------------------------------
// Scratch (static __device__; no runtime allocation allowed)
// ---------------------------------------------------------------------------
__device__ float g_wsq[CC], g_wbq[CC];
__device__ float g_wsk[CC], g_wbk[CC];
__device__ float g_wsv[CC], g_wbv[CC];
__device__ float g_ws1[FH2], g_wb1v[FH2];
__device__ float g_mu_o[NPIX], g_rs_o[NPIX];
__device__ float g_mu_s[NPIX], g_rs_s[NPIX];
__device__ float g_mu_x[NPIX], g_rs_x[NPIX];
// packed bf16x2 (element k even in low 16 bits) == bf16[M][K] row-major
__device__ __align__(128) u32 g_Aqh[CC*128],  g_Aql[CC*128];
__device__ __align__(128) u32 g_Akh[CC*128],  g_Akl[CC*128];
__device__ __align__(128) u32 g_Avh[CC*128],  g_Avl[CC*128];
__device__ __align__(128) u32 g_A1h[FH2*128], g_A1l[FH2*128];
__device__ __align__(128) u32 g_Aoh[CC*128],  g_Aol[CC*128];
__device__ __align__(128) u32 g_A2h[CC*256],  g_A2l[CC*256];
__device__ __align__(128) float g_q[BB*CC*LL];
__device__ __align__(128) float g_k[BB*CC*LL];
__device__ __align__(128) float g_v[BB*CC*LL];
__device__ __align__(128) float g_attn[BB*CC*LL];
__device__ __align__(128) float g_x[BB*CC*LL];
__device__ __align__(128) float g_h[BB*FH2*LL];     // pre-gate FFN activations
__device__ __align__(128) float g_Sp[BB*NHH*NSPLIT*HCC*HCC];
__device__ __align__(128) float g_A[BB*NHH*HCC*HCC];

// ---------------------------------------------------------------------------
// mma.sync / ldmatrix helpers (sm_80+ ISA, legal on compute_100)
// ---------------------------------------------------------------------------
__device__ __forceinline__ u32 smem_u32(const void* p) {
    u32 a;
    asm("{ .reg .u64 t; cvta.to.shared.u64 t, %1; cvt.u32.u64 %0, t; }" : "=r"(a) : "l"(p));
    return a;
}
#define LDSM_X4(r0,r1,r2,r3,addr) \
    asm volatile("ldmatrix.sync.aligned.m8n8.x4.shared.b16 {%0,%1,%2,%3}, [%4];" \
        : "=r"(r0),"=r"(r1),"=r"(r2),"=r"(r3) : "r"(addr))
#define LDSM_X4_T(r0,r1,r2,r3,addr) \
    asm volatile("ldmatrix.sync.aligned.m8n8.x4.trans.shared.b16 {%0,%1,%2,%3}, [%4];" \
        : "=r"(r0),"=r"(r1),"=r"(r2),"=r"(r3) : "r"(addr))
#define MMA_BF16(d, a, b0, b1) \
    asm volatile("mma.sync.aligned.m16n8k16.row.col.f32.bf16.bf16.f32 " \
        "{%0,%1,%2,%3}, {%4,%5,%6,%7}, {%8,%9}, {%0,%1,%2,%3};" \
        : "+f"((d)[0]),"+f"((d)[1]),"+f"((d)[2]),"+f"((d)[3]) \
        : "r"((a)[0]),"r"((a)[1]),"r"((a)[2]),"r"((a)[3]), "r"(b0),"r"(b1))

__device__ __forceinline__ u32 pack_hi2(float a, float b) {
    __nv_bfloat16 ha = __float2bfloat16(a), hb = __float2bfloat16(b);
    return (u32)__bfloat16_as_ushort(ha) | ((u32)__bfloat16_as_ushort(hb) << 16);
}
__device__ __forceinline__ u32 pack_lo2(float a, float b) {
    __nv_bfloat16 ha = __float2bfloat16(a), hb = __float2bfloat16(b);
    float la = a - __bfloat162float(ha), lb = b - __bfloat162float(hb);
    __nv_bfloat16 xa = __float2bfloat16(la), xb = __float2bfloat16(lb);
    return (u32)__bfloat16_as_ushort(xa) | ((u32)__bfloat16_as_ushort(xb) << 16);
}

// ---------------------------------------------------------------------------
// Prep: fold LN gain into W (Wq/Wk/Wv/W1), rowsum(W*g), W@beta (+b1); split hi/lo
// ---------------------------------------------------------------------------
__global__ void prep_fold(const float* __restrict__ Wq, const float* __restrict__ Wk,
                          const float* __restrict__ Wv, const float* __restrict__ W1,
                          const float* __restrict__ gopt, const float* __restrict__ bopt,
                          const float* __restrict__ gsar, const float* __restrict__ bsar,
                          const float* __restrict__ gffn, const float* __restrict__ bffn,
                          const float* __restrict__ b1)
{
    int row = blockIdx.x;   // 0..1791
    int c   = threadIdx.x;  // 0..255
    const float* W; float* ws; float* wb; u32* Ah; u32* Al;
    const float* gg; const float* bb; int m; float extra = 0.f;
    if (row < 256)      { W=Wq; ws=g_wsq; wb=g_wbq; Ah=g_Aqh; Al=g_Aql; gg=gopt; bb=bopt; m=row; }
    else if (row < 512) { W=Wk; ws=g_wsk; wb=g_wbk; Ah=g_Akh; Al=g_Akl; gg=gsar; bb=bsar; m=row-256; }
    else if (row < 768) { W=Wv; ws=g_wsv; wb=g_wbv; Ah=g_Avh; Al=g_Avl; gg=gsar; bb=bsar; m=row-512; }
    else                { W=W1; ws=g_ws1; wb=g_wb1v; Ah=g_A1h; Al=g_A1l; gg=gffn; bb=bffn; m=row-768;
                          extra = b1[row-768]; }
    float w  = W[m*CC + c];
    float wg = w * gg[c];
    __nv_bfloat16 h = __float2bfloat16(wg);
    float hf = __bfloat162float(h);
    __nv_bfloat16 l = __float2bfloat16(wg - hf);
    u32 hu = (u32)__bfloat16_as_ushort(h);
    u32 lu = (u32)__bfloat16_as_ushort(l);
    u32 hp = __shfl_xor_sync(0xffffffffu, hu, 1);
    u32 lp = __shfl_xor_sync(0xffffffffu, lu, 1);
    if (!(c & 1)) {
        Ah[m*128 + (c>>1)] = hu | (hp << 16);
        Al[m*128 + (c>>1)] = lu | (lp << 16);
    }
    __shared__ float s1[256], s2[256];
    s1[c] = wg; s2[c] = w * bb[c];
    __syncthreads();
    for (int off = 128; off > 0; off >>= 1) {
        if (c < off) { s1[c] += s1[c+off]; s2[c] += s2[c+off]; }
        __syncthreads();
    }
    if (c == 0) { ws[m] = s1[0]; wb[m] = s2[0] + extra; }
}

__global__ void prep_plain(const float* __restrict__ W, u32* __restrict__ Ah,
                           u32* __restrict__ Al, int K)
{
    int m = blockIdx.x, c0 = threadIdx.x;
    for (int k0 = 0; k0 < K; k0 += 256) {
        int c = k0 + c0;
        float w = W[(size_t)m*K + c];
        __nv_bfloat16 h = __float2bfloat16(w);
        float hf = __bfloat162float(h);
        __nv_bfloat16 l = __float2bfloat16(w - hf);
        u32 hu = (u32)__bfloat16_as_ushort(h);
        u32 lu = (u32)__bfloat16_as_ushort(l);
        u32 hp = __shfl_xor_sync(0xffffffffu, hu, 1);
        u32 lp = __shfl_xor_sync(0xffffffffu, lu, 1);
        if (!(c0 & 1)) {
            Ah[(size_t)m*(K/2) + (c>>1)] = hu | (hp << 16);
            Al[(size_t)m*(K/2) + (c>>1)] = lu | (lp << 16);
        }
    }
}

// ---------------------------------------------------------------------------
// LN stats (channel axis, biased var, eps=1e-5)
// ---------------------------------------------------------------------------
__global__ void ln_stats_kernel(const float* __restrict__ x,
                                float* __restrict__ mu, float* __restrict__ rs)
{
    int p = blockIdx.x * blockDim.x + threadIdx.x;
    if (p >= NPIX) return;
    int b = p >> 12, l = p & (LL-1);
    const float* base = x + (size_t)b*CC*LL + l;
    float s = 0.f, s2 = 0.f;
#pragma unroll 8
    for (int c = 0; c < CC; c++) {
        float v = __ldg(base + (size_t)c*LL);
        s += v; s2 = fmaf(v, v, s2);
    }
    float m   = s * (1.f/CC);
    float var = fmaf(-m, m, s2 * (1.f/CC));
    mu[p] = m;
    rs[p] = rsqrtf(var + 1e-5f);
}

// ---------------------------------------------------------------------------
// bf16x3-split GEMM via mma.sync: Y[b](MD x LL) = W(MD x KD) @ X[b](KD x LL)
// CTA tile 128x128, K chunk 32, 8 warps of 64x32.
// MODE 0: LN-folded epilogue; 1: +res; 2: +bias +res.  GATED: B = h1*h2 on the fly.
// ---------------------------------------------------------------------------
#define A_STR 80
#define B_STR 272
#define AS_H  0
#define AS_L  10240
#define BS_H  20480
#define BS_L  29184
#define SMEM_TOT 37888

template<int MODE, int KD, int MD, int GATED>
__global__ __launch_bounds__(256, 1)
void gemm_mma(const u32* __restrict__ Ah, const u32* __restrict__ Al,
              const float* __restrict__ X, float* __restrict__ Y,
              const float* __restrict__ mu, const float* __restrict__ rs,
              const float* __restrict__ wsum, const float* __restrict__ wb,
              const float* __restrict__ res, const float* __restrict__ bias)
{
    __shared__ __align__(128) char smem[SMEM_TOT];
    const u32 sbase = smem_u32(smem);

    int tid = threadIdx.x, lane = tid & 31, wid = tid >> 5;
    int n0 = blockIdx.x * 128, m0 = blockIdx.y * 128, b = blockIdx.z;
    int wm = wid >> 2, wn = wid & 3;

    float acc[4][4][4];
#pragma unroll
    for (int i=0;i<4;i++)
#pragma unroll
        for (int j=0;j<4;j++)
#pragma unroll
            for (int r=0;r<4;r++) acc[i][j][r]=0.f;

    const float* Xb = X + (size_t)b*(GATED ? 2*KD : KD)*LL + n0;
    // A store: thread -> (m = tid&127, part = tid>>7) covering bytes part*32..+32
    int am = tid & 127, apart = tid >> 7;
    // ldmatrix fragment smem addresses (precompute lane-dependent parts)
    u32 a_lm_base = sbase + (u32)((wm*64 + (lane & 15)) * A_STR) + ((lane & 16) ? 16u : 0u);
    u32 b_lm_base = sbase + BS_H + (u32)((lane & 15) * B_STR)
                  + (u32)((wn*32 + ((lane & 16) ? 8 : 0)) * 2);

#pragma unroll 1
    for (int kc = 0; kc < KD; kc += 32) {
        __syncthreads();
        // ---- A chunk -> smem (hi & lo), rows m0..m0+127, 32 bf16 each
        {
            const u32* srch = Ah + (size_t)(m0+am)*(KD/2) + (kc>>1) + apart*8;
            const u32* srcl = Al + (size_t)(m0+am)*(KD/2) + (kc>>1) + apart*8;
            uint4 v0 = *(const uint4*)srch;
            uint4 v1 = *(const uint4*)(srch+4);
            char* dh = smem + AS_H + am*A_STR + apart*32;
            *(uint4*)dh = v0; *(uint4*)(dh+16) = v1;
            uint4 w0 = *(const uint4*)srcl;
            uint4 w1 = *(const uint4*)(srcl+4);
            char* dl = smem + AS_L + am*A_STR + apart*32;
            *(uint4*)dl = w0; *(uint4*)(dl+16) = w1;
        }
        // ---- B chunk: 32 k-rows x 128 n, fp32 -> bf16 hi/lo
#pragma unroll
        for (int it = 0; it < 4; it++) {
            int idx = it*256 + tid;          // 0..1023
            int k = idx >> 5, n4 = idx & 31;
            float4 v;
            if (GATED) {
                const float* p1 = Xb + (size_t)(kc+k)*LL + n4*4;
                float4 a = *(const float4*)p1;
                float4 c = *(const float4*)(p1 + (size_t)FH*LL);
                v = make_float4(a.x*c.x, a.y*c.y, a.z*c.z, a.w*c.w);
            } else {
                v = *(const float4*)(Xb + (size_t)(kc+k)*LL + n4*4);
            }
            u32 h0 = pack_hi2(v.x, v.y), h1 = pack_hi2(v.z, v.w);
            u32 l0 = pack_lo2(v.x, v.y), l1 = pack_lo2(v.z, v.w);
            *(uint2*)(smem + BS_H + k*B_STR + n4*8) = make_uint2(h0, h1);
            *(uint2*)(smem + BS_L + k*B_STR + n4*8) = make_uint2(l0, l1);
        }
        __syncthreads();
        // ---- 2 k16 steps
#pragma unroll
        for (int ks = 0; ks < 32; ks += 16) {
            u32 ah[4][4], al[4][4], bh[4][2], bl[4][2];
            u32 ab = a_lm_base + (u32)(ks*2);
#pragma unroll
            for (int i = 0; i < 4; i++) {
                LDSM_X4(ah[i][0], ah[i][1], ah[i][2], ah[i][3], ab + AS_H + (u32)(i*16*A_STR));
                LDSM_X4(al[i][0], al[i][1], al[i][2], al[i][3], ab + AS_L + (u32)(i*16*A_STR));
            }
            u32 bb0 = b_lm_base + (u32)(ks*B_STR);
#pragma unroll
            for (int j2 = 0; j2 < 2; j2++) {
                LDSM_X4_T(bh[j2*2][0], bh[j2*2][1], bh[j2*2+1][0], bh[j2*2+1][1], bb0 + (u32)(j2*32));
                LDSM_X4_T(bl[j2*2][0], bl[j2*2][1], bl[j2*2+1][0], bl[j2*2+1][1], bb0 + (u32)(BS_L - BS_H + j2*32));
            }
#pragma unroll
            for (int i = 0; i < 4; i++)
#pragma unroll
                for (int j = 0; j < 4; j++) {
                    MMA_BF16(acc[i][j], ah[i], bh[j][0], bh[j][1]);
                    MMA_BF16(acc[i][j], ah[i], bl[j][0], bl[j][1]);
                    MMA_BF16(acc[i][j], al[i], bh[j][0], bh[j][1]);
                }
        }
    }

    // ---- epilogue: c-frag (row = lane>>2 [+8], col = 2*(lane&3) [+1])
#pragma unroll
    for (int i = 0; i < 4; i++) {
        int r0 = m0 + wm*64 + i*16 + (lane >> 2);
        int r1 = r0 + 8;
        float ws0, wb0, ws1v, wb1;
        if (MODE == 0) { ws0 = wsum[r0]; wb0 = wb[r0]; ws1v = wsum[r1]; wb1 = wb[r1]; }
        float bv0 = 0.f, bv1 = 0.f;
        if (MODE == 2) { bv0 = bias[r0]; bv1 = bias[r1]; }
#pragma unroll
        for (int j = 0; j < 4; j++) {
            int c0 = n0 + wn*32 + j*8 + 2*(lane & 3);
            float v00 = acc[i][j][0], v01 = acc[i][j][1];
            float v10 = acc[i][j][2], v11 = acc[i][j][3];
            float* y0 = Y + (size_t)b*MD*LL + (size_t)r0*LL + c0;
            float* y1 = Y + (size_t)b*MD*LL + (size_t)r1*LL + c0;
            if (MODE == 0) {
                int p0 = b*LL + c0;
                float2 m2 = *(const float2*)(mu + p0);
                float2 s2 = *(const float2*)(rs + p0);
                float2 o0 = make_float2(s2.x*(v00 - m2.x*ws0) + wb0,
                                        s2.y*(v01 - m2.y*ws0) + wb0);
                float2 o1 = make_float2(s2.x*(v10 - m2.x*ws1v) + wb1,
                                        s2.y*(v11 - m2.y*ws1v) + wb1);
                *(float2*)y0 = o0; *(float2*)y1 = o1;
            } else if (MODE == 1) {
                const float* q0 = res + (size_t)b*MD*LL + (size_t)r0*LL + c0;
                const float* q1 = res + (size_t)b*MD*LL + (size_t)r1*LL + c0;
                float2 a0 = *(const float2*)q0, a1 = *(const float2*)q1;
                *(float2*)y0 = make_float2(v00 + a0.x, v01 + a0.y);
                *(float2*)y1 = make_float2(v10 + a1.x, v11 + a1.y);
            } else {
                const float* q0 = res + (size_t)b*MD*LL + (size_t)r0*LL + c0;
                const float* q1 = res + (size_t)b*MD*LL + (size_t)r1*LL + c0;
                float2 a0 = *(const float2*)q0, a1 = *(const float2*)q1;
                *(float2*)y0 = make_float2(v00 + bv0 + a0.x, v01 + bv0 + a0.y);
                *(float2*)y1 = make_float2(v10 + bv1 + a1.x, v11 + bv1 + a1.y);
            }
        }
    }
}

// ---------------------------------------------------------------------------
// Attention: S partials, softmax, A@V (fp32)
// ---------------------------------------------------------------------------
__global__ __launch_bounds__(128)
void attn_s_kernel()
{
    __shared__ float qs[HCC][129];
    __shared__ float ks[HCC][129];
    int bh = blockIdx.x, sp = blockIdx.y;
    int b = bh >> 3, h = bh & 7;
    int l0 = sp * 128;
    int tid = threadIdx.x;
    const float* qp = g_q + (size_t)b*CC*LL + (size_t)(h*HCC)*LL + l0;
    const float* kp = g_k + (size_t)b*CC*LL + (size_t)(h*HCC)*LL + l0;
    for (int idx = tid; idx < HCC*128; idx += 128) {
        int r = idx >> 7, ci = idx & 127;
        qs[r][ci] = qp[(size_t)r*LL + ci];
        ks[r][ci] = kp[(size_t)r*LL + ci];
    }
    __syncthreads();
    int d2 = tid & 15, cy = tid >> 4;
    float acc[2][4] = {{0.f,0.f,0.f,0.f},{0.f,0.f,0.f,0.f}};
#pragma unroll 4
    for (int l = 0; l < 128; l++) {
        float k0v = ks[2*d2][l], k1v = ks[2*d2+1][l];
#pragma unroll
        for (int i = 0; i < 4; i++) {
            float qv = qs[cy + 8*i][l];
            acc[0][i] = fmaf(qv, k0v, acc[0][i]);
            acc[1][i] = fmaf(qv, k1v, acc[1][i]);
        }
    }
    float* out = g_Sp + ((size_t)bh*NSPLIT + sp)*1024;
#pragma unroll
    for (int i = 0; i < 4; i++) {
        int c = cy + 8*i;
        out[c*32 + 2*d2]   = acc[0][i];
        out[c*32 + 2*d2+1] = acc[1][i];
    }
}

__global__ void attn_softmax_kernel()
{
    int bh = blockIdx.x, t = threadIdx.x;
    float s = 0.f;
    const float* sp = g_Sp + (size_t)bh*NSPLIT*1024 + t;
#pragma unroll
    for (int i = 0; i < NSPLIT; i++) s += sp[(size_t)i*1024];
    s *= 0.17677669529663687f;
    float mx = s;
#pragma unroll
    for (int o = 16; o > 0; o >>= 1) mx = fmaxf(mx, __shfl_xor_sync(0xffffffffu, mx, o));
    float e = expf(s - mx);
    float sum = e;
#pragma unroll
    for (int o = 16; o > 0; o >>= 1) sum += __shfl_xor_sync(0xffffffffu, sum, o);
    g_A[(size_t)bh*1024 + t] = e / sum;
}

__global__ __launch_bounds__(256)
void attn_av_kernel()
{
    __shared__ float As[1024];
    int bh = blockIdx.x;
    int b = bh >> 3, h = bh & 7;
    int tid = threadIdx.x;
#pragma unroll
    for (int i = 0; i < 4; i++) As[tid + 256*i] = g_A[(size_t)bh*1024 + tid + 256*i];
    __syncthreads();
    int l = blockIdx.y*512 + tid;
    const float* vp = g_v + (size_t)b*CC*LL + (size_t)(h*HCC)*LL + l;
    float acc0[32], acc1[32];
#pragma unroll
    for (int c = 0; c < 32; c++) { acc0[c]=0.f; acc1[c]=0.f; }
#pragma unroll 4
    for (int d = 0; d < 32; d++) {
        float v0 = vp[(size_t)d*LL];
        float v1 = vp[(size_t)d*LL + 256];
#pragma unroll
        for (int c = 0; c < 32; c++) {
            float a = As[c*32+d];
            acc0[c] = fmaf(a, v0, acc0[c]);
            acc1[c] = fmaf(a, v1, acc1[c]);
        }
    }
    float* op = g_attn + (size_t)b*CC*LL + (size_t)(h*HCC)*LL + l;
#pragma unroll
    for (int c = 0; c < 32; c++) {
        op[(size_t)c*LL]       = acc0[c];
        op[(size_t)c*LL + 256] = acc1[c];
    }
}

// ---------------------------------------------------------------------------
// Launcher
// ---------------------------------------------------------------------------
extern "C" void kernel_launch(void* const* d_in, const int* in_sizes, int n_in,
                              void* d_out, int out_size)
{
    (void)in_sizes; (void)n_in; (void)out_size;
    const float* optical = (const float*)d_in[0];
    const float* sar     = (const float*)d_in[1];
    const float* gopt    = (const float*)d_in[2];
    const float* bopt    = (const float*)d_in[3];
    const float* gsar    = (const float*)d_in[4];
    const float* bsar    = (const float*)d_in[5];
    const float* Wq      = (const float*)d_in[6];
    const float* Wk      = (const float*)d_in[7];
    const float* Wv      = (const float*)d_in[8];
    const float* Wo      = (const float*)d_in[9];
    const float* gffn    = (const float*)d_in[10];
    const float* bffn    = (const float*)d_in[11];
    const float* W1      = (const float*)d_in[12];
    const float* b1      = (const float*)d_in[13];
    const float* W2      = (const float*)d_in[14];
    const float* b2      = (const float*)d_in[15];
    float* out = (float*)d_out;

    float *p_wsq,*p_wbq,*p_wsk,*p_wbk,*p_wsv,*p_wbv,*p_ws1,*p_wb1;
    float *p_mu_o,*p_rs_o,*p_mu_s,*p_rs_s,*p_mu_x,*p_rs_x;
    float *p_q,*p_k,*p_v,*p_attn,*p_x,*p_h;
    u32 *p_Aqh,*p_Aql,*p_Akh,*p_Akl,*p_Avh,*p_Avl,*p_A1h,*p_A1l,*p_Aoh,*p_Aol,*p_A2h,*p_A2l;
    cudaGetSymbolAddress((void**)&p_wsq, g_wsq);   cudaGetSymbolAddress((void**)&p_wbq, g_wbq);
    cudaGetSymbolAddress((void**)&p_wsk, g_wsk);   cudaGetSymbolAddress((void**)&p_wbk, g_wbk);
    cudaGetSymbolAddress((void**)&p_wsv, g_wsv);   cudaGetSymbolAddress((void**)&p_wbv, g_wbv);
    cudaGetSymbolAddress((void**)&p_ws1, g_ws1);   cudaGetSymbolAddress((void**)&p_wb1, g_wb1v);
    cudaGetSymbolAddress((void**)&p_mu_o, g_mu_o); cudaGetSymbolAddress((void**)&p_rs_o, g_rs_o);
    cudaGetSymbolAddress((void**)&p_mu_s, g_mu_s); cudaGetSymbolAddress((void**)&p_rs_s, g_rs_s);
    cudaGetSymbolAddress((void**)&p_mu_x, g_mu_x); cudaGetSymbolAddress((void**)&p_rs_x, g_rs_x);
    cudaGetSymbolAddress((void**)&p_q, g_q);       cudaGetSymbolAddress((void**)&p_k, g_k);
    cudaGetSymbolAddress((void**)&p_v, g_v);       cudaGetSymbolAddress((void**)&p_attn, g_attn);
    cudaGetSymbolAddress((void**)&p_x, g_x);       cudaGetSymbolAddress((void**)&p_h, g_h);
    cudaGetSymbolAddress((void**)&p_Aqh, g_Aqh);   cudaGetSymbolAddress((void**)&p_Aql, g_Aql);
    cudaGetSymbolAddress((void**)&p_Akh, g_Akh);   cudaGetSymbolAddress((void**)&p_Akl, g_Akl);
    cudaGetSymbolAddress((void**)&p_Avh, g_Avh);   cudaGetSymbolAddress((void**)&p_Avl, g_Avl);
    cudaGetSymbolAddress((void**)&p_A1h, g_A1h);   cudaGetSymbolAddress((void**)&p_A1l, g_A1l);
    cudaGetSymbolAddress((void**)&p_Aoh, g_Aoh);   cudaGetSymbolAddress((void**)&p_Aol, g_Aol);
    cudaGetSymbolAddress((void**)&p_A2h, g_A2h);   cudaGetSymbolAddress((void**)&p_A2l, g_A2l);

    // 1) weight prep
    prep_fold<<<1792, 256>>>(Wq, Wk, Wv, W1, gopt, bopt, gsar, bsar, gffn, bffn, b1);
    prep_plain<<<256, 256>>>(Wo, p_Aoh, p_Aol, 256);
    prep_plain<<<256, 256>>>(W2, p_A2h, p_A2l, 512);

    // 2) LN stats
    ln_stats_kernel<<<NPIX/128, 128>>>(optical, p_mu_o, p_rs_o);
    ln_stats_kernel<<<NPIX/128, 128>>>(sar,     p_mu_s, p_rs_s);

    // 3) Q/K/V projections (mma.sync bf16x3, LN-folded epilogue)
    dim3 gp(LL/128, CC/128, BB);
    gemm_mma<0,256,256,0><<<gp,256>>>(p_Aqh, p_Aql, optical, p_q, p_mu_o, p_rs_o, p_wsq, p_wbq, 0, 0);
    gemm_mma<0,256,256,0><<<gp,256>>>(p_Akh, p_Akl, sar,     p_k, p_mu_s, p_rs_s, p_wsk, p_wbk, 0, 0);
    gemm_mma<0,256,256,0><<<gp,256>>>(p_Avh, p_Avl, sar,     p_v, p_mu_s, p_rs_s, p_wsv, p_wbv, 0, 0);

    // 4) channel attention
    attn_s_kernel<<<dim3(BB*NHH, NSPLIT), 128>>>();
    attn_softmax_kernel<<<BB*NHH, 1024>>>();
    attn_av_kernel<<<dim3(BB*NHH, LL/512), 256>>>();

    // 5) Wo + residual -> x
    gemm_mma<1,256,256,0><<<gp,256>>>(p_Aoh, p_Aol, p_attn, p_x, 0, 0, 0, 0, optical, 0);

    // 6) LN stats on x
    ln_stats_kernel<<<NPIX/128, 128>>>(p_x, p_mu_x, p_rs_x);

    // 7) W1 (LN+b1 folded) -> h (1024 ch)
    dim3 gp1(LL/128, FH2/128, BB);
    gemm_mma<0,256,1024,0><<<gp1,256>>>(p_A1h, p_A1l, p_x, p_h, p_mu_x, p_rs_x, p_ws1, p_wb1, 0, 0);

    // 8) W2 with fused SimpleGate B-fill (+b2 +residual) -> out
    gemm_mma<2,512,256,1><<<gp,256>>>(p_A2h, p_A2l, p_h, out, 0, 0, 0, 0, p_x, b2);
}

// round 4
// speedup vs baseline: 1.8592x; 1.1354x over previous
#include <cuda_runtime.h>
#include <cuda_bf16.h>

typedef unsigned int u32;
typedef unsigned long long u64;

#define BB   16
#define CC   256
#define LL   4096
#define NHH  8
#define HCC  32
#define FH   512
#define FH2  1024
#define NPIX (BB*LL)
#define NSPLIT 32

// ---------------------------------------------------------------------------
// Scratch
// ---------------------------------------------------------------------------
__device__ float g_wsq[CC], g_wbq[CC];
__device__ float g_wsk[CC], g_wbk[CC];
__device__ float g_wsv[CC], g_wbv[CC];
__device__ float g_ws1[FH2], g_wb1v[FH2];     // permuted order (see prep_fold)
__device__ float g_mu_o[NPIX], g_rs_o[NPIX];
__device__ float g_mu_s[NPIX], g_rs_s[NPIX];
__device__ float g_mu_x[NPIX], g_rs_x[NPIX];
// packed bf16x2 (element k even in low 16 bits) == bf16[M][K] row-major
__device__ __align__(128) u32 g_Aqh[CC*128],  g_Aql[CC*128];
__device__ __align__(128) u32 g_Akh[CC*128],  g_Akl[CC*128];
__device__ __align__(128) u32 g_Avh[CC*128],  g_Avl[CC*128];
__device__ __align__(128) u32 g_A1h[FH2*128], g_A1l[FH2*128];   // permuted rows
__device__ __align__(128) u32 g_Aoh[CC*128],  g_Aol[CC*128];
__device__ __align__(128) u32 g_A2h[CC*256],  g_A2l[CC*256];
__device__ __align__(128) float g_q[BB*CC*LL];
__device__ __align__(128) float g_k[BB*CC*LL];
__device__ __align__(128) float g_v[BB*CC*LL];
__device__ __align__(128) float g_attn[BB*CC*LL];
__device__ __align__(128) float g_x[BB*CC*LL];
__device__ __align__(128) u32 g_hgh[BB*FH*(LL/2)];   // gated FFN act, bf16 hi packed
__device__ __align__(128) u32 g_hgl[BB*FH*(LL/2)];   // bf16 lo packed
__device__ __align__(128) float g_Sp[BB*NHH*NSPLIT*HCC*HCC];
__device__ __align__(128) float g_A[BB*NHH*HCC*HCC];

// ---------------------------------------------------------------------------
// mma.sync / ldmatrix helpers
// ---------------------------------------------------------------------------
__device__ __forceinline__ u32 smem_u32(const void* p) {
    u32 a;
    asm("{ .reg .u64 t; cvta.to.shared.u64 t, %1; cvt.u32.u64 %0, t; }" : "=r"(a) : "l"(p));
    return a;
}
#define LDSM_X4(r0,r1,r2,r3,addr) \
    asm volatile("ldmatrix.sync.aligned.m8n8.x4.shared.b16 {%0,%1,%2,%3}, [%4];" \
        : "=r"(r0),"=r"(r1),"=r"(r2),"=r"(r3) : "r"(addr))
#define LDSM_X4_T(r0,r1,r2,r3,addr) \
    asm volatile("ldmatrix.sync.aligned.m8n8.x4.trans.shared.b16 {%0,%1,%2,%3}, [%4];" \
        : "=r"(r0),"=r"(r1),"=r"(r2),"=r"(r3) : "r"(addr))
#define MMA_BF16(d, a, b0, b1) \
    asm volatile("mma.sync.aligned.m16n8k16.row.col.f32.bf16.bf16.f32 " \
        "{%0,%1,%2,%3}, {%4,%5,%6,%7}, {%8,%9}, {%0,%1,%2,%3};" \
        : "+f"((d)[0]),"+f"((d)[1]),"+f"((d)[2]),"+f"((d)[3]) \
        : "r"((a)[0]),"r"((a)[1]),"r"((a)[2]),"r"((a)[3]), "r"(b0),"r"(b1))

__device__ __forceinline__ u32 pack_hi2(float a, float b) {
    __nv_bfloat16 ha = __float2bfloat16(a), hb = __float2bfloat16(b);
    return (u32)__bfloat16_as_ushort(ha) | ((u32)__bfloat16_as_ushort(hb) << 16);
}
__device__ __forceinline__ u32 pack_lo2(float a, float b) {
    __nv_bfloat16 ha = __float2bfloat16(a), hb = __float2bfloat16(b);
    float la = a - __bfloat162float(ha), lb = b - __bfloat162float(hb);
    __nv_bfloat16 xa = __float2bfloat16(la), xb = __float2bfloat16(lb);
    return (u32)__bfloat16_as_ushort(xa) | ((u32)__bfloat16_as_ushort(xb) << 16);
}

// ---------------------------------------------------------------------------
// Prep. W1 rows are PERMUTED so each m16 mma tile pairs h1 rows with their
// h2 gate partners: out-row t (0..511) -> perm slot (t/8)*16 + t%8,
// h2 row (t+512)     -> perm slot (t/8)*16 + t%8 + 8.
// ws/wb for W1 are stored in perm order.
// ---------------------------------------------------------------------------
__global__ void prep_fold(const float* __restrict__ Wq, const float* __restrict__ Wk,
                          const float* __restrict__ Wv, const float* __restrict__ W1,
                          const float* __restrict__ gopt, const float* __restrict__ bopt,
                          const float* __restrict__ gsar, const float* __restrict__ bsar,
                          const float* __restrict__ gffn, const float* __restrict__ bffn,
                          const float* __restrict__ b1)
{
    int row = blockIdx.x;   // 0..1791
    int c   = threadIdx.x;  // 0..255
    const float* W; float* ws; float* wb; u32* Ah; u32* Al;
    const float* gg; const float* bb; int m, mdst; float extra = 0.f;
    if (row < 256)      { W=Wq; ws=g_wsq; wb=g_wbq; Ah=g_Aqh; Al=g_Aql; gg=gopt; bb=bopt; m=row;      mdst=m; }
    else if (row < 512) { W=Wk; ws=g_wsk; wb=g_wbk; Ah=g_Akh; Al=g_Akl; gg=gsar; bb=bsar; m=row-256;  mdst=m; }
    else if (row < 768) { W=Wv; ws=g_wsv; wb=g_wbv; Ah=g_Avh; Al=g_Avl; gg=gsar; bb=bsar; m=row-512;  mdst=m; }
    else {
        W=W1; ws=g_ws1; wb=g_wb1v; Ah=g_A1h; Al=g_A1l; gg=gffn; bb=bffn; m=row-768;
        extra = b1[m];
        if (m < FH) mdst = ((m>>3)<<4) + (m&7);
        else        { int mm = m-FH; mdst = ((mm>>3)<<4) + (mm&7) + 8; }
    }
    float w  = W[m*CC + c];
    float wg = w * gg[c];
    __nv_bfloat16 h = __float2bfloat16(wg);
    float hf = __bfloat162float(h);
    __nv_bfloat16 l = __float2bfloat16(wg - hf);
    u32 hu = (u32)__bfloat16_as_ushort(h);
    u32 lu = (u32)__bfloat16_as_ushort(l);
    u32 hp = __shfl_xor_sync(0xffffffffu, hu, 1);
    u32 lp = __shfl_xor_sync(0xffffffffu, lu, 1);
    if (!(c & 1)) {
        Ah[mdst*128 + (c>>1)] = hu | (hp << 16);
        Al[mdst*128 + (c>>1)] = lu | (lp << 16);
    }
    __shared__ float s1[256], s2[256];
    s1[c] = wg; s2[c] = w * bb[c];
    __syncthreads();
    for (int off = 128; off > 0; off >>= 1) {
        if (c < off) { s1[c] += s1[c+off]; s2[c] += s2[c+off]; }
        __syncthreads();
    }
    if (c == 0) { ws[mdst] = s1[0]; wb[mdst] = s2[0] + extra; }
}

__global__ void prep_plain(const float* __restrict__ W, u32* __restrict__ Ah,
                           u32* __restrict__ Al, int K)
{
    int m = blockIdx.x, c0 = threadIdx.x;
    for (int k0 = 0; k0 < K; k0 += 256) {
        int c = k0 + c0;
        float w = W[(size_t)m*K + c];
        __nv_bfloat16 h = __float2bfloat16(w);
        float hf = __bfloat162float(h);
        __nv_bfloat16 l = __float2bfloat16(w - hf);
        u32 hu = (u32)__bfloat16_as_ushort(h);
        u32 lu = (u32)__bfloat16_as_ushort(l);
        u32 hp = __shfl_xor_sync(0xffffffffu, hu, 1);
        u32 lp = __shfl_xor_sync(0xffffffffu, lu, 1);
        if (!(c0 & 1)) {
            Ah[(size_t)m*(K/2) + (c>>1)] = hu | (hp << 16);
            Al[(size_t)m*(K/2) + (c>>1)] = lu | (lp << 16);
        }
    }
}

// ---------------------------------------------------------------------------
// LN stats
// ---------------------------------------------------------------------------
__global__ void ln_stats_kernel(const float* __restrict__ x,
                                float* __restrict__ mu, float* __restrict__ rs)
{
    int p = blockIdx.x * blockDim.x + threadIdx.x;
    if (p >= NPIX) return;
    int b = p >> 12, l = p & (LL-1);
    const float* base = x + (size_t)b*CC*LL + l;
    float s = 0.f, s2 = 0.f;
#pragma unroll 8
    for (int c = 0; c < CC; c++) {
        float v = __ldg(base + (size_t)c*LL);
        s += v; s2 = fmaf(v, v, s2);
    }
    float m   = s * (1.f/CC);
    float var = fmaf(-m, m, s2 * (1.f/CC));
    mu[p] = m;
    rs[p] = rsqrtf(var + 1e-5f);
}

// ---------------------------------------------------------------------------
// bf16x3-split GEMM via mma.sync, software-pipelined (reg prefetch).
// CTA 128x128, K chunk 32, 8 warps 64x32.
// MODE 0: LN epilogue -> fp32 Y ; 1: +res ; 2: +bias +res
// MODE 3: LN + SimpleGate (row-paired A) -> packed bf16 hi/lo (g_hgh/g_hgl)
// BSRC 0: B from fp32 X (convert on store) ; 1: B from packed bf16 Xh/Xl
// ---------------------------------------------------------------------------
#define A_STR 80
#define B_STR 272
#define AS_H  0
#define AS_L  10240
#define BS_H  20480
#define BS_L  29184
#define SMEM_TOT 37888

template<int MODE, int KD, int MD, int BSRC>
__global__ __launch_bounds__(256, 1)
void gemm_mma(const u32* __restrict__ Ah, const u32* __restrict__ Al,
              const float* __restrict__ X,
              const u32* __restrict__ Xh, const u32* __restrict__ Xl,
              float* __restrict__ Y,
              const float* __restrict__ mu, const float* __restrict__ rs,
              const float* __restrict__ wsum, const float* __restrict__ wb,
              const float* __restrict__ res, const float* __restrict__ bias)
{
    __shared__ __align__(128) char smem[SMEM_TOT];
    const u32 sbase = smem_u32(smem);

    int tid = threadIdx.x, lane = tid & 31, wid = tid >> 5;
    int n0 = blockIdx.x * 128, m0 = blockIdx.y * 128, b = blockIdx.z;
    int wm = wid >> 2, wn = wid & 3;

    float acc[4][4][4];
#pragma unroll
    for (int i=0;i<4;i++)
#pragma unroll
        for (int j=0;j<4;j++)
#pragma unroll
            for (int r=0;r<4;r++) acc[i][j][r]=0.f;

    const float* Xb  = (BSRC==0) ? (X + (size_t)b*KD*LL + n0) : (const float*)0;
    const u32*   XHb = (BSRC==1) ? (Xh + (size_t)b*KD*(LL/2) + n0/2) : (const u32*)0;
    const u32*   XLb = (BSRC==1) ? (Xl + (size_t)b*KD*(LL/2) + n0/2) : (const u32*)0;

    int am = tid & 127, apart = tid >> 7;
    const u32* ArowH = Ah + (size_t)(m0+am)*(KD/2) + apart*8;
    const u32* ArowL = Al + (size_t)(m0+am)*(KD/2) + apart*8;

    u32 a_lm_base = sbase + (u32)((wm*64 + (lane & 15)) * A_STR) + ((lane & 16) ? 16u : 0u);
    u32 b_lm_base = sbase + BS_H + (u32)((lane & 15) * B_STR)
                  + (u32)((wn*32 + ((lane & 16) ? 8 : 0)) * 2);

    // prefetch registers
    uint4 pa[4];
    float4 pf[4];
    uint2 pbh[4], pbl[4];

    // ---- load chunk 0
    {
        pa[0] = *(const uint4*)ArowH; pa[1] = *(const uint4*)(ArowH+4);
        pa[2] = *(const uint4*)ArowL; pa[3] = *(const uint4*)(ArowL+4);
#pragma unroll
        for (int it = 0; it < 4; it++) {
            int idx = it*256 + tid;
            int k = idx >> 5, n4 = idx & 31;
            if (BSRC == 0) {
                pf[it] = *(const float4*)(Xb + (size_t)k*LL + n4*4);
            } else {
                pbh[it] = *(const uint2*)(XHb + (size_t)k*(LL/2) + n4*2);
                pbl[it] = *(const uint2*)(XLb + (size_t)k*(LL/2) + n4*2);
            }
        }
    }

#pragma unroll 1
    for (int kc = 0; kc < KD; kc += 32) {
        // ---- store prefetched chunk to smem
        {
            char* dh = smem + AS_H + am*A_STR + apart*32;
            *(uint4*)dh = pa[0]; *(uint4*)(dh+16) = pa[1];
            char* dl = smem + AS_L + am*A_STR + apart*32;
            *(uint4*)dl = pa[2]; *(uint4*)(dl+16) = pa[3];
        }
#pragma unroll
        for (int it = 0; it < 4; it++) {
            int idx = it*256 + tid;
            int k = idx >> 5, n4 = idx & 31;
            if (BSRC == 0) {
                float4 v = pf[it];
                *(uint2*)(smem + BS_H + k*B_STR + n4*8) =
                    make_uint2(pack_hi2(v.x, v.y), pack_hi2(v.z, v.w));
                *(uint2*)(smem + BS_L + k*B_STR + n4*8) =
                    make_uint2(pack_lo2(v.x, v.y), pack_lo2(v.z, v.w));
            } else {
                *(uint2*)(smem + BS_H + k*B_STR + n4*8) = pbh[it];
                *(uint2*)(smem + BS_L + k*B_STR + n4*8) = pbl[it];
            }
        }
        __syncthreads();
        // ---- prefetch next chunk (overlaps with MMA below)
        if (kc + 32 < KD) {
            const u32* nH = ArowH + ((kc+32) >> 1);
            const u32* nL = ArowL + ((kc+32) >> 1);
            pa[0] = *(const uint4*)nH; pa[1] = *(const uint4*)(nH+4);
            pa[2] = *(const uint4*)nL; pa[3] = *(const uint4*)(nL+4);
#pragma unroll
            for (int it = 0; it < 4; it++) {
                int idx = it*256 + tid;
                int k = (idx >> 5) + kc + 32, n4 = idx & 31;
                if (BSRC == 0) {
                    pf[it] = *(const float4*)(Xb + (size_t)k*LL + n4*4);
                } else {
                    pbh[it] = *(const uint2*)(XHb + (size_t)k*(LL/2) + n4*2);
                    pbl[it] = *(const uint2*)(XLb + (size_t)k*(LL/2) + n4*2);
                }
            }
        }
        // ---- MMA over smem chunk
#pragma unroll
        for (int ks = 0; ks < 32; ks += 16) {
            u32 ah[4][4], al[4][4], bh[4][2], bl[4][2];
            u32 ab = a_lm_base + (u32)(ks*2);
#pragma unroll
            for (int i = 0; i < 4; i++) {
                LDSM_X4(ah[i][0], ah[i][1], ah[i][2], ah[i][3], ab + AS_H + (u32)(i*16*A_STR));
                LDSM_X4(al[i][0], al[i][1], al[i][2], al[i][3], ab + AS_L + (u32)(i*16*A_STR));
            }
            u32 bb0 = b_lm_base + (u32)(ks*B_STR);
#pragma unroll
            for (int j2 = 0; j2 < 2; j2++) {
                LDSM_X4_T(bh[j2*2][0], bh[j2*2][1], bh[j2*2+1][0], bh[j2*2+1][1], bb0 + (u32)(j2*32));
                LDSM_X4_T(bl[j2*2][0], bl[j2*2][1], bl[j2*2+1][0], bl[j2*2+1][1], bb0 + (u32)(BS_L - BS_H + j2*32));
            }
#pragma unroll
            for (int i = 0; i < 4; i++)
#pragma unroll
                for (int j = 0; j < 4; j++) {
                    MMA_BF16(acc[i][j], ah[i], bh[j][0], bh[j][1]);
                    MMA_BF16(acc[i][j], ah[i], bl[j][0], bl[j][1]);
                    MMA_BF16(acc[i][j], al[i], bh[j][0], bh[j][1]);
                }
        }
        __syncthreads();
    }

    // ---- epilogue
#pragma unroll
    for (int i = 0; i < 4; i++) {
        int r0 = m0 + wm*64 + i*16 + (lane >> 2);
        int r1 = r0 + 8;
        if (MODE == 3) {
            // r0 = perm slot of h1 row; r1 = its h2 partner. out row t:
            int t = ((r0 >> 4) << 3) + (r0 & 7);
            float ws1 = wsum[r0], wb1 = wb[r0];
            float ws2 = wsum[r1], wb2 = wb[r1];
#pragma unroll
            for (int j = 0; j < 4; j++) {
                int c0 = n0 + wn*32 + j*8 + 2*(lane & 3);
                int p0 = b*LL + c0;
                float2 m2 = *(const float2*)(mu + p0);
                float2 s2 = *(const float2*)(rs + p0);
                float e1x = s2.x*(acc[i][j][0] - m2.x*ws1) + wb1;
                float e1y = s2.y*(acc[i][j][1] - m2.y*ws1) + wb1;
                float e2x = s2.x*(acc[i][j][2] - m2.x*ws2) + wb2;
                float e2y = s2.y*(acc[i][j][3] - m2.y*ws2) + wb2;
                float gx = e1x*e2x, gy = e1y*e2y;
                size_t o = ((size_t)b*FH + t)*(LL/2) + (c0 >> 1);
                g_hgh[o] = pack_hi2(gx, gy);
                g_hgl[o] = pack_lo2(gx, gy);
            }
            continue;
        }
        float ws0, wb0, ws1v, wb1;
        if (MODE == 0) { ws0 = wsum[r0]; wb0 = wb[r0]; ws1v = wsum[r1]; wb1 = wb[r1]; }
        float bv0 = 0.f, bv1 = 0.f;
        if (MODE == 2) { bv0 = bias[r0]; bv1 = bias[r1]; }
#pragma unroll
        for (int j = 0; j < 4; j++) {
            int c0 = n0 + wn*32 + j*8 + 2*(lane & 3);
            float v00 = acc[i][j][0], v01 = acc[i][j][1];
            float v10 = acc[i][j][2], v11 = acc[i][j][3];
            float* y0 = Y + (size_t)b*MD*LL + (size_t)r0*LL + c0;
            float* y1 = Y + (size_t)b*MD*LL + (size_t)r1*LL + c0;
            if (MODE == 0) {
                int p0 = b*LL + c0;
                float2 m2 = *(const float2*)(mu + p0);
                float2 s2 = *(const float2*)(rs + p0);
                *(float2*)y0 = make_float2(s2.x*(v00 - m2.x*ws0) + wb0,
                                           s2.y*(v01 - m2.y*ws0) + wb0);
                *(float2*)y1 = make_float2(s2.x*(v10 - m2.x*ws1v) + wb1,
                                           s2.y*(v11 - m2.y*ws1v) + wb1);
            } else if (MODE == 1) {
                const float* q0 = res + (size_t)b*MD*LL + (size_t)r0*LL + c0;
                const float* q1 = res + (size_t)b*MD*LL + (size_t)r1*LL + c0;
                float2 a0 = *(const float2*)q0, a1 = *(const float2*)q1;
                *(float2*)y0 = make_float2(v00 + a0.x, v01 + a0.y);
                *(float2*)y1 = make_float2(v10 + a1.x, v11 + a1.y);
            } else {
                const float* q0 = res + (size_t)b*MD*LL + (size_t)r0*LL + c0;
                const float* q1 = res + (size_t)b*MD*LL + (size_t)r1*LL + c0;
                float2 a0 = *(const float2*)q0, a1 = *(const float2*)q1;
                *(float2*)y0 = make_float2(v00 + bv0 + a0.x, v01 + bv0 + a0.y);
                *(float2*)y1 = make_float2(v10 + bv1 + a1.x, v11 + bv1 + a1.y);
            }
        }
    }
}

// ---------------------------------------------------------------------------
// Attention
// ---------------------------------------------------------------------------
__global__ __launch_bounds__(128)
void attn_s_kernel()
{
    __shared__ float qs[HCC][129];
    __shared__ float ks[HCC][129];
    int bh = blockIdx.x, sp = blockIdx.y;
    int b = bh >> 3, h = bh & 7;
    int l0 = sp * 128;
    int tid = threadIdx.x;
    const float* qp = g_q + (size_t)b*CC*LL + (size_t)(h*HCC)*LL + l0;
    const float* kp = g_k + (size_t)b*CC*LL + (size_t)(h*HCC)*LL + l0;
    for (int idx = tid; idx < HCC*128; idx += 128) {
        int r = idx >> 7, ci = idx & 127;
        qs[r][ci] = qp[(size_t)r*LL + ci];
        ks[r][ci] = kp[(size_t)r*LL + ci];
    }
    __syncthreads();
    int d2 = tid & 15, cy = tid >> 4;
    float acc[2][4] = {{0.f,0.f,0.f,0.f},{0.f,0.f,0.f,0.f}};
#pragma unroll 4
    for (int l = 0; l < 128; l++) {
        float k0v = ks[2*d2][l], k1v = ks[2*d2+1][l];
#pragma unroll
        for (int i = 0; i < 4; i++) {
            float qv = qs[cy + 8*i][l];
            acc[0][i] = fmaf(qv, k0v, acc[0][i]);
            acc[1][i] = fmaf(qv, k1v, acc[1][i]);
        }
    }
    float* out = g_Sp + ((size_t)bh*NSPLIT + sp)*1024;
#pragma unroll
    for (int i = 0; i < 4; i++) {
        int c = cy + 8*i;
        out[c*32 + 2*d2]   = acc[0][i];
        out[c*32 + 2*d2+1] = acc[1][i];
    }
}

__global__ void attn_softmax_kernel()
{
    int bh = blockIdx.x, t = threadIdx.x;
    float s = 0.f;
    const float* sp = g_Sp + (size_t)bh*NSPLIT*1024 + t;
#pragma unroll
    for (int i = 0; i < NSPLIT; i++) s += sp[(size_t)i*1024];
    s *= 0.17677669529663687f;
    float mx = s;
#pragma unroll
    for (int o = 16; o > 0; o >>= 1) mx = fmaxf(mx, __shfl_xor_sync(0xffffffffu, mx, o));
    float e = expf(s - mx);
    float sum = e;
#pragma unroll
    for (int o = 16; o > 0; o >>= 1) sum += __shfl_xor_sync(0xffffffffu, sum, o);
    g_A[(size_t)bh*1024 + t] = e / sum;
}

__global__ __launch_bounds__(256)
void attn_av_kernel()
{
    __shared__ float As[1024];
    int bh = blockIdx.x;
    int b = bh >> 3, h = bh & 7;
    int tid = threadIdx.x;
#pragma unroll
    for (int i = 0; i < 4; i++) As[tid + 256*i] = g_A[(size_t)bh*1024 + tid + 256*i];
    __syncthreads();
    int l = blockIdx.y*512 + tid;
    const float* vp = g_v + (size_t)b*CC*LL + (size_t)(h*HCC)*LL + l;
    float acc0[32], acc1[32];
#pragma unroll
    for (int c = 0; c < 32; c++) { acc0[c]=0.f; acc1[c]=0.f; }
#pragma unroll 4
    for (int d = 0; d < 32; d++) {
        float v0 = vp[(size_t)d*LL];
        float v1 = vp[(size_t)d*LL + 256];
#pragma unroll
        for (int c = 0; c < 32; c++) {
            float a = As[c*32+d];
            acc0[c] = fmaf(a, v0, acc0[c]);
            acc1[c] = fmaf(a, v1, acc1[c]);
        }
    }
    float* op = g_attn + (size_t)b*CC*LL + (size_t)(h*HCC)*LL + l;
#pragma unroll
    for (int c = 0; c < 32; c++) {
        op[(size_t)c*LL]       = acc0[c];
        op[(size_t)c*LL + 256] = acc1[c];
    }
}

// ---------------------------------------------------------------------------
// Launcher
// ---------------------------------------------------------------------------
extern "C" void kernel_launch(void* const* d_in, const int* in_sizes, int n_in,
                              void* d_out, int out_size)
{
    (void)in_sizes; (void)n_in; (void)out_size;
    const float* optical = (const float*)d_in[0];
    const float* sar     = (const float*)d_in[1];
    const float* gopt    = (const float*)d_in[2];
    const float* bopt    = (const float*)d_in[3];
    const float* gsar    = (const float*)d_in[4];
    const float* bsar    = (const float*)d_in[5];
    const float* Wq      = (const float*)d_in[6];
    const float* Wk      = (const float*)d_in[7];
    const float* Wv      = (const float*)d_in[8];
    const float* Wo      = (const float*)d_in[9];
    const float* gffn    = (const float*)d_in[10];
    const float* bffn    = (const float*)d_in[11];
    const float* W1      = (const float*)d_in[12];
    const float* b1      = (const float*)d_in[13];
    const float* W2      = (const float*)d_in[14];
    const float* b2      = (const float*)d_in[15];
    float* out = (float*)d_out;

    float *p_wsq,*p_wbq,*p_wsk,*p_wbk,*p_wsv,*p_wbv,*p_ws1,*p_wb1;
    float *p_mu_o,*p_rs_o,*p_mu_s,*p_rs_s,*p_mu_x,*p_rs_x;
    float *p_q,*p_k,*p_v,*p_attn,*p_x;
    u32 *p_Aqh,*p_Aql,*p_Akh,*p_Akl,*p_Avh,*p_Avl,*p_A1h,*p_A1l,*p_Aoh,*p_Aol,*p_A2h,*p_A2l;
    u32 *p_hgh,*p_hgl;
    cudaGetSymbolAddress((void**)&p_wsq, g_wsq);   cudaGetSymbolAddress((void**)&p_wbq, g_wbq);
    cudaGetSymbolAddress((void**)&p_wsk, g_wsk);   cudaGetSymbolAddress((void**)&p_wbk, g_wbk);
    cudaGetSymbolAddress((void**)&p_wsv, g_wsv);   cudaGetSymbolAddress((void**)&p_wbv, g_wbv);
    cudaGetSymbolAddress((void**)&p_ws1, g_ws1);   cudaGetSymbolAddress((void**)&p_wb1, g_wb1v);
    cudaGetSymbolAddress((void**)&p_mu_o, g_mu_o); cudaGetSymbolAddress((void**)&p_rs_o, g_rs_o);
    cudaGetSymbolAddress((void**)&p_mu_s, g_mu_s); cudaGetSymbolAddress((void**)&p_rs_s, g_rs_s);
    cudaGetSymbolAddress((void**)&p_mu_x, g_mu_x); cudaGetSymbolAddress((void**)&p_rs_x, g_rs_x);
    cudaGetSymbolAddress((void**)&p_q, g_q);       cudaGetSymbolAddress((void**)&p_k, g_k);
    cudaGetSymbolAddress((void**)&p_v, g_v);       cudaGetSymbolAddress((void**)&p_attn, g_attn);
    cudaGetSymbolAddress((void**)&p_x, g_x);
    cudaGetSymbolAddress((void**)&p_hgh, g_hgh);   cudaGetSymbolAddress((void**)&p_hgl, g_hgl);
    cudaGetSymbolAddress((void**)&p_Aqh, g_Aqh);   cudaGetSymbolAddress((void**)&p_Aql, g_Aql);
    cudaGetSymbolAddress((void**)&p_Akh, g_Akh);   cudaGetSymbolAddress((void**)&p_Akl, g_Akl);
    cudaGetSymbolAddress((void**)&p_Avh, g_Avh);   cudaGetSymbolAddress((void**)&p_Avl, g_Avl);
    cudaGetSymbolAddress((void**)&p_A1h, g_A1h);   cudaGetSymbolAddress((void**)&p_A1l, g_A1l);
    cudaGetSymbolAddress((void**)&p_Aoh, g_Aoh);   cudaGetSymbolAddress((void**)&p_Aol, g_Aol);
    cudaGetSymbolAddress((void**)&p_A2h, g_A2h);   cudaGetSymbolAddress((void**)&p_A2l, g_A2l);

    // 1) weight prep
    prep_fold<<<1792, 256>>>(Wq, Wk, Wv, W1, gopt, bopt, gsar, bsar, gffn, bffn, b1);
    prep_plain<<<256, 256>>>(Wo, p_Aoh, p_Aol, 256);
    prep_plain<<<256, 256>>>(W2, p_A2h, p_A2l, 512);

    // 2) LN stats
    ln_stats_kernel<<<NPIX/128, 128>>>(optical, p_mu_o, p_rs_o);
    ln_stats_kernel<<<NPIX/128, 128>>>(sar,     p_mu_s, p_rs_s);

    // 3) Q/K/V projections
    dim3 gp(LL/128, CC/128, BB);
    gemm_mma<0,256,256,0><<<gp,256>>>(p_Aqh, p_Aql, optical, 0, 0, p_q, p_mu_o, p_rs_o, p_wsq, p_wbq, 0, 0);
    gemm_mma<0,256,256,0><<<gp,256>>>(p_Akh, p_Akl, sar,     0, 0, p_k, p_mu_s, p_rs_s, p_wsk, p_wbk, 0, 0);
    gemm_mma<0,256,256,0><<<gp,256>>>(p_Avh, p_Avl, sar,     0, 0, p_v, p_mu_s, p_rs_s, p_wsv, p_wbv, 0, 0);

    // 4) channel attention
    attn_s_kernel<<<dim3(BB*NHH, NSPLIT), 128>>>();
    attn_softmax_kernel<<<BB*NHH, 1024>>>();
    attn_av_kernel<<<dim3(BB*NHH, LL/512), 256>>>();

    // 5) Wo + residual -> x
    gemm_mma<1,256,256,0><<<gp,256>>>(p_Aoh, p_Aol, p_attn, 0, 0, p_x, 0, 0, 0, 0, optical, 0);

    // 6) LN stats on x
    ln_stats_kernel<<<NPIX/128, 128>>>(p_x, p_mu_x, p_rs_x);

    // 7) W1 (LN+b1 folded, row-paired) + fused SimpleGate -> hg (bf16 hi/lo)
    dim3 gp1(LL/128, FH2/128, BB);
    gemm_mma<3,256,FH,0><<<gp1,256>>>(p_A1h, p_A1l, p_x, 0, 0, (float*)0, p_mu_x, p_rs_x, p_ws1, p_wb1, 0, 0);

    // 8) W2 (B from bf16 hg) + b2 + residual -> out
    gemm_mma<2,512,256,1><<<gp,256>>>(p_A2h, p_A2l, 0, p_hgh, p_hgl, out, 0, 0, 0, 0, p_x, b2);
}

// round 5
// speedup vs baseline: 2.4152x; 1.2990x over previous
#include <cuda_runtime.h>
#include <cuda_bf16.h>

typedef unsigned int u32;
typedef unsigned long long u64;

#define BB   16
#define CC   256
#define LL   4096
#define NHH  8
#define HCC  32
#define FH   512
#define FH2  1024
#define NPIX (BB*LL)
#define NSPLIT 32

// ---------------------------------------------------------------------------
// Scratch
// ---------------------------------------------------------------------------
__device__ float g_wsq[CC], g_wbq[CC];
__device__ float g_wsk[CC], g_wbk[CC];
__device__ float g_wsv[CC], g_wbv[CC];
__device__ float g_ws1[FH2], g_wb1v[FH2];     // permuted order (see prep_fold)
__device__ float g_mu_o[NPIX], g_rs_o[NPIX];
__device__ float g_mu_s[NPIX], g_rs_s[NPIX];
__device__ float g_mu_x[NPIX], g_rs_x[NPIX];
// weights: packed bf16x2 (k even in low 16) == bf16[M][K] row-major
__device__ __align__(128) u32 g_Aqh[CC*128],  g_Aql[CC*128];
__device__ __align__(128) u32 g_Akh[CC*128],  g_Akl[CC*128];
__device__ __align__(128) u32 g_Avh[CC*128],  g_Avl[CC*128];
__device__ __align__(128) u32 g_A1h[FH2*128], g_A1l[FH2*128];   // permuted rows
__device__ __align__(128) u32 g_Aoh[CC*128],  g_Aol[CC*128];
__device__ __align__(128) u32 g_A2h[CC*256],  g_A2l[CC*256];
// activations fp32 (attention path + residuals)
__device__ __align__(128) float g_q[BB*CC*LL];
__device__ __align__(128) float g_k[BB*CC*LL];
__device__ __align__(128) float g_v[BB*CC*LL];
__device__ __align__(128) float g_x[BB*CC*LL];
// activations packed bf16 hi/lo (GEMM B operands), [C][L/2] u32 per batch
__device__ __align__(128) u32 g_oh[BB*CC*(LL/2)], g_ol[BB*CC*(LL/2)];
__device__ __align__(128) u32 g_sh[BB*CC*(LL/2)], g_sl[BB*CC*(LL/2)];
__device__ __align__(128) u32 g_ah[BB*CC*(LL/2)], g_al[BB*CC*(LL/2)];
__device__ __align__(128) u32 g_xh[BB*CC*(LL/2)], g_xl[BB*CC*(LL/2)];
__device__ __align__(128) u32 g_hgh[BB*FH*(LL/2)], g_hgl[BB*FH*(LL/2)];
__device__ __align__(128) float g_Sp[BB*NHH*NSPLIT*HCC*HCC];
__device__ __align__(128) float g_A[BB*NHH*HCC*HCC];

// ---------------------------------------------------------------------------
// PTX helpers
// ---------------------------------------------------------------------------
__device__ __forceinline__ u32 smem_u32(const void* p) {
    u32 a;
    asm("{ .reg .u64 t; cvta.to.shared.u64 t, %1; cvt.u32.u64 %0, t; }" : "=r"(a) : "l"(p));
    return a;
}
#define LDSM_X4(r0,r1,r2,r3,addr) \
    asm volatile("ldmatrix.sync.aligned.m8n8.x4.shared.b16 {%0,%1,%2,%3}, [%4];" \
        : "=r"(r0),"=r"(r1),"=r"(r2),"=r"(r3) : "r"(addr))
#define LDSM_X4_T(r0,r1,r2,r3,addr) \
    asm volatile("ldmatrix.sync.aligned.m8n8.x4.trans.shared.b16 {%0,%1,%2,%3}, [%4];" \
        : "=r"(r0),"=r"(r1),"=r"(r2),"=r"(r3) : "r"(addr))
#define MMA_BF16(d, a, b0, b1) \
    asm volatile("mma.sync.aligned.m16n8k16.row.col.f32.bf16.bf16.f32 " \
        "{%0,%1,%2,%3}, {%4,%5,%6,%7}, {%8,%9}, {%0,%1,%2,%3};" \
        : "+f"((d)[0]),"+f"((d)[1]),"+f"((d)[2]),"+f"((d)[3]) \
        : "r"((a)[0]),"r"((a)[1]),"r"((a)[2]),"r"((a)[3]), "r"(b0),"r"(b1))
#define CP16(dst, src) \
    asm volatile("cp.async.cg.shared.global [%0], [%1], 16;" \
        :: "r"(dst), "l"(src) : "memory")
#define CP_COMMIT() asm volatile("cp.async.commit_group;" ::: "memory")
#define CP_WAIT(n)  asm volatile("cp.async.wait_group %0;" :: "n"(n) : "memory")

__device__ __forceinline__ u32 pack_hi2(float a, float b) {
    __nv_bfloat16 ha = __float2bfloat16(a), hb = __float2bfloat16(b);
    return (u32)__bfloat16_as_ushort(ha) | ((u32)__bfloat16_as_ushort(hb) << 16);
}
__device__ __forceinline__ u32 pack_lo2(float a, float b) {
    __nv_bfloat16 ha = __float2bfloat16(a), hb = __float2bfloat16(b);
    float la = a - __bfloat162float(ha), lb = b - __bfloat162float(hb);
    __nv_bfloat16 xa = __float2bfloat16(la), xb = __float2bfloat16(lb);
    return (u32)__bfloat16_as_ushort(xa) | ((u32)__bfloat16_as_ushort(xb) << 16);
}

// ---------------------------------------------------------------------------
// Prep (W1 rows permuted for gate pairing, as R4)
// ---------------------------------------------------------------------------
__global__ void prep_fold(const float* __restrict__ Wq, const float* __restrict__ Wk,
                          const float* __restrict__ Wv, const float* __restrict__ W1,
                          const float* __restrict__ gopt, const float* __restrict__ bopt,
                          const float* __restrict__ gsar, const float* __restrict__ bsar,
                          const float* __restrict__ gffn, const float* __restrict__ bffn,
                          const float* __restrict__ b1)
{
    int row = blockIdx.x;
    int c   = threadIdx.x;
    const float* W; float* ws; float* wb; u32* Ah; u32* Al;
    const float* gg; const float* bb; int m, mdst; float extra = 0.f;
    if (row < 256)      { W=Wq; ws=g_wsq; wb=g_wbq; Ah=g_Aqh; Al=g_Aql; gg=gopt; bb=bopt; m=row;      mdst=m; }
    else if (row < 512) { W=Wk; ws=g_wsk; wb=g_wbk; Ah=g_Akh; Al=g_Akl; gg=gsar; bb=bsar; m=row-256;  mdst=m; }
    else if (row < 768) { W=Wv; ws=g_wsv; wb=g_wbv; Ah=g_Avh; Al=g_Avl; gg=gsar; bb=bsar; m=row-512;  mdst=m; }
    else {
        W=W1; ws=g_ws1; wb=g_wb1v; Ah=g_A1h; Al=g_A1l; gg=gffn; bb=bffn; m=row-768;
        extra = b1[m];
        if (m < FH) mdst = ((m>>3)<<4) + (m&7);
        else        { int mm = m-FH; mdst = ((mm>>3)<<4) + (mm&7) + 8; }
    }
    float w  = W[m*CC + c];
    float wg = w * gg[c];
    __nv_bfloat16 h = __float2bfloat16(wg);
    float hf = __bfloat162float(h);
    __nv_bfloat16 l = __float2bfloat16(wg - hf);
    u32 hu = (u32)__bfloat16_as_ushort(h);
    u32 lu = (u32)__bfloat16_as_ushort(l);
    u32 hp = __shfl_xor_sync(0xffffffffu, hu, 1);
    u32 lp = __shfl_xor_sync(0xffffffffu, lu, 1);
    if (!(c & 1)) {
        Ah[mdst*128 + (c>>1)] = hu | (hp << 16);
        Al[mdst*128 + (c>>1)] = lu | (lp << 16);
    }
    __shared__ float s1[256], s2[256];
    s1[c] = wg; s2[c] = w * bb[c];
    __syncthreads();
    for (int off = 128; off > 0; off >>= 1) {
        if (c < off) { s1[c] += s1[c+off]; s2[c] += s2[c+off]; }
        __syncthreads();
    }
    if (c == 0) { ws[mdst] = s1[0]; wb[mdst] = s2[0] + extra; }
}

__global__ void prep_plain(const float* __restrict__ W, u32* __restrict__ Ah,
                           u32* __restrict__ Al, int K)
{
    int m = blockIdx.x, c0 = threadIdx.x;
    for (int k0 = 0; k0 < K; k0 += 256) {
        int c = k0 + c0;
        float w = W[(size_t)m*K + c];
        __nv_bfloat16 h = __float2bfloat16(w);
        float hf = __bfloat162float(h);
        __nv_bfloat16 l = __float2bfloat16(w - hf);
        u32 hu = (u32)__bfloat16_as_ushort(h);
        u32 lu = (u32)__bfloat16_as_ushort(l);
        u32 hp = __shfl_xor_sync(0xffffffffu, hu, 1);
        u32 lp = __shfl_xor_sync(0xffffffffu, lu, 1);
        if (!(c0 & 1)) {
            Ah[(size_t)m*(K/2) + (c>>1)] = hu | (hp << 16);
            Al[(size_t)m*(K/2) + (c>>1)] = lu | (lp << 16);
        }
    }
}

// ---------------------------------------------------------------------------
// LN stats + bf16 hi/lo conversion (one pass). Thread owns pixel pair (2p,2p+1).
// ---------------------------------------------------------------------------
__global__ void ln_conv_kernel(const float* __restrict__ x,
                               float* __restrict__ mu, float* __restrict__ rs,
                               u32* __restrict__ xh, u32* __restrict__ xl)
{
    int p2 = blockIdx.x * blockDim.x + threadIdx.x;  // pair index, NPIX/2
    if (p2 >= NPIX/2) return;
    int b = p2 >> 11, l2 = p2 & 2047;
    const float* base = x + (size_t)b*CC*LL + 2*l2;
    u32* oh = xh + (size_t)b*CC*(LL/2) + l2;
    u32* ol = xl + (size_t)b*CC*(LL/2) + l2;
    float sx=0.f, sx2=0.f, sy=0.f, sy2=0.f;
#pragma unroll 4
    for (int c = 0; c < CC; c++) {
        float2 v = *(const float2*)(base + (size_t)c*LL);
        sx += v.x; sx2 = fmaf(v.x, v.x, sx2);
        sy += v.y; sy2 = fmaf(v.y, v.y, sy2);
        oh[(size_t)c*(LL/2)] = pack_hi2(v.x, v.y);
        ol[(size_t)c*(LL/2)] = pack_lo2(v.x, v.y);
    }
    float mx = sx*(1.f/CC), my = sy*(1.f/CC);
    int p = b*LL + 2*l2;
    mu[p]   = mx; rs[p]   = rsqrtf(fmaf(-mx, mx, sx2*(1.f/CC)) + 1e-5f);
    mu[p+1] = my; rs[p+1] = rsqrtf(fmaf(-my, my, sy2*(1.f/CC)) + 1e-5f);
}

// ---------------------------------------------------------------------------
// bf16x3-split GEMM, cp.async 2-stage pipeline, 2 CTAs/SM.
// All operands pre-packed bf16 hi/lo. CTA 128x128, K chunk 32, 8 warps 64x32.
// MODE 0: LN epilogue -> fp32 Y ; 1: +res ; 2: +bias +res
// MODE 3: LN + SimpleGate (row-paired A) -> g_hgh/g_hgl
// ---------------------------------------------------------------------------
#define A_STR 80
#define B_STR 272
#define AS_H  0
#define AS_L  10240
#define BS_H  20480
#define BS_L  29184
#define STAGE 37888
#define GSMEM (2*STAGE)

template<int MODE, int KD, int MD>
__global__ __launch_bounds__(256, 2)
void gemm_mma(const u32* __restrict__ Ah, const u32* __restrict__ Al,
              const u32* __restrict__ Xh, const u32* __restrict__ Xl,
              float* __restrict__ Y,
              const float* __restrict__ mu, const float* __restrict__ rs,
              const float* __restrict__ wsum, const float* __restrict__ wb,
              const float* __restrict__ res, const float* __restrict__ bias)
{
    extern __shared__ __align__(128) char smem[];
    const u32 sbase = smem_u32(smem);

    int tid = threadIdx.x, lane = tid & 31, wid = tid >> 5;
    int n0 = blockIdx.x * 128, m0 = blockIdx.y * 128, b = blockIdx.z;
    int wm = wid >> 2, wn = wid & 3;

    float acc[4][4][4];
#pragma unroll
    for (int i=0;i<4;i++)
#pragma unroll
        for (int j=0;j<4;j++)
#pragma unroll
            for (int r=0;r<4;r++) acc[i][j][r]=0.f;

    // cp.async source/dest precompute (2 chunks each of Ah/Al/Bh/Bl per thread)
    int ia0 = tid,        ia1 = tid + 256;
    int ar0 = ia0 >> 2,   ap0 = (ia0 & 3) * 4;     // row, u32-offset
    int ar1 = ia1 >> 2,   ap1 = (ia1 & 3) * 4;
    int br0 = ia0 >> 4,   bc0 = (ia0 & 15) * 4;
    int br1 = ia1 >> 4,   bc1 = (ia1 & 15) * 4;
    const u32* srcAh0 = Ah + (size_t)(m0+ar0)*(KD/2) + ap0;
    const u32* srcAh1 = Ah + (size_t)(m0+ar1)*(KD/2) + ap1;
    const u32* srcAl0 = Al + (size_t)(m0+ar0)*(KD/2) + ap0;
    const u32* srcAl1 = Al + (size_t)(m0+ar1)*(KD/2) + ap1;
    const u32* XHb = Xh + (size_t)b*KD*(LL/2) + (n0>>1);
    const u32* XLb = Xl + (size_t)b*KD*(LL/2) + (n0>>1);
    const u32* srcBh0 = XHb + (size_t)br0*(LL/2) + bc0;
    const u32* srcBh1 = XHb + (size_t)br1*(LL/2) + bc1;
    const u32* srcBl0 = XLb + (size_t)br0*(LL/2) + bc0;
    const u32* srcBl1 = XLb + (size_t)br1*(LL/2) + bc1;
    u32 dAh0 = sbase + AS_H + (u32)(ar0*A_STR + ap0*4);
    u32 dAh1 = sbase + AS_H + (u32)(ar1*A_STR + ap1*4);
    u32 dAl0 = sbase + AS_L + (u32)(ar0*A_STR + ap0*4);
    u32 dAl1 = sbase + AS_L + (u32)(ar1*A_STR + ap1*4);
    u32 dBh0 = sbase + BS_H + (u32)(br0*B_STR + bc0*4);
    u32 dBh1 = sbase + BS_H + (u32)(br1*B_STR + bc1*4);
    u32 dBl0 = sbase + BS_L + (u32)(br0*B_STR + bc0*4);
    u32 dBl1 = sbase + BS_L + (u32)(br1*B_STR + bc1*4);

    u32 a_lm_base = sbase + (u32)((wm*64 + (lane & 15)) * A_STR) + ((lane & 16) ? 16u : 0u);
    u32 b_lm_base = sbase + BS_H + (u32)((lane & 15) * B_STR)
                  + (u32)((wn*32 + ((lane & 16) ? 8 : 0)) * 2);

    // issue loads for stage s of K-chunk kc
#define ISSUE(st, kc) do { \
        u32 so = (u32)((st)*STAGE); \
        int ko2 = (kc) >> 1; size_t kb = (size_t)(kc)*(LL/2); \
        CP16(dAh0+so, srcAh0+ko2); CP16(dAh1+so, srcAh1+ko2); \
        CP16(dAl0+so, srcAl0+ko2); CP16(dAl1+so, srcAl1+ko2); \
        CP16(dBh0+so, srcBh0+kb);  CP16(dBh1+so, srcBh1+kb); \
        CP16(dBl0+so, srcBl0+kb);  CP16(dBl1+so, srcBl1+kb); \
        CP_COMMIT(); \
    } while(0)

    ISSUE(0, 0);

#pragma unroll 1
    for (int kc = 0; kc < KD; kc += 32) {
        int cur = (kc >> 5) & 1;
        if (kc + 32 < KD) {
            ISSUE(cur ^ 1, kc + 32);
            CP_WAIT(1);
        } else {
            CP_WAIT(0);
        }
        __syncthreads();
        u32 so = (u32)(cur * STAGE);
#pragma unroll
        for (int ks = 0; ks < 32; ks += 16) {
            u32 ah[4][4], al[4][4], bh[4][2], bl[4][2];
            u32 ab = a_lm_base + so + (u32)(ks*2);
#pragma unroll
            for (int i = 0; i < 4; i++) {
                LDSM_X4(ah[i][0], ah[i][1], ah[i][2], ah[i][3], ab + AS_H + (u32)(i*16*A_STR));
                LDSM_X4(al[i][0], al[i][1], al[i][2], al[i][3], ab + AS_L + (u32)(i*16*A_STR));
            }
            u32 bb0 = b_lm_base + so + (u32)(ks*B_STR);
#pragma unroll
            for (int j2 = 0; j2 < 2; j2++) {
                LDSM_X4_T(bh[j2*2][0], bh[j2*2][1], bh[j2*2+1][0], bh[j2*2+1][1], bb0 + (u32)(j2*32));
                LDSM_X4_T(bl[j2*2][0], bl[j2*2][1], bl[j2*2+1][0], bl[j2*2+1][1], bb0 + (u32)(BS_L - BS_H + j2*32));
            }
#pragma unroll
            for (int i = 0; i < 4; i++)
#pragma unroll
                for (int j = 0; j < 4; j++) {
                    MMA_BF16(acc[i][j], ah[i], bh[j][0], bh[j][1]);
                    MMA_BF16(acc[i][j], ah[i], bl[j][0], bl[j][1]);
                    MMA_BF16(acc[i][j], al[i], bh[j][0], bh[j][1]);
                }
        }
        __syncthreads();
    }
#undef ISSUE

    // ---- epilogue
#pragma unroll
    for (int i = 0; i < 4; i++) {
        int r0 = m0 + wm*64 + i*16 + (lane >> 2);
        int r1 = r0 + 8;
        if (MODE == 3) {
            int t = ((r0 >> 4) << 3) + (r0 & 7);
            float ws1 = wsum[r0], wb1 = wb[r0];
            float ws2 = wsum[r1], wb2 = wb[r1];
#pragma unroll
            for (int j = 0; j < 4; j++) {
                int c0 = n0 + wn*32 + j*8 + 2*(lane & 3);
                int p0 = b*LL + c0;
                float2 m2 = *(const float2*)(mu + p0);
                float2 s2 = *(const float2*)(rs + p0);
                float e1x = s2.x*(acc[i][j][0] - m2.x*ws1) + wb1;
                float e1y = s2.y*(acc[i][j][1] - m2.y*ws1) + wb1;
                float e2x = s2.x*(acc[i][j][2] - m2.x*ws2) + wb2;
                float e2y = s2.y*(acc[i][j][3] - m2.y*ws2) + wb2;
                float gx = e1x*e2x, gy = e1y*e2y;
                size_t o = ((size_t)b*FH + t)*(LL/2) + (c0 >> 1);
                g_hgh[o] = pack_hi2(gx, gy);
                g_hgl[o] = pack_lo2(gx, gy);
            }
            continue;
        }
        float ws0, wb0, ws1v, wb1;
        if (MODE == 0) { ws0 = wsum[r0]; wb0 = wb[r0]; ws1v = wsum[r1]; wb1 = wb[r1]; }
        float bv0 = 0.f, bv1 = 0.f;
        if (MODE == 2) { bv0 = bias[r0]; bv1 = bias[r1]; }
#pragma unroll
        for (int j = 0; j < 4; j++) {
            int c0 = n0 + wn*32 + j*8 + 2*(lane & 3);
            float v00 = acc[i][j][0], v01 = acc[i][j][1];
            float v10 = acc[i][j][2], v11 = acc[i][j][3];
            float* y0 = Y + (size_t)b*MD*LL + (size_t)r0*LL + c0;
            float* y1 = Y + (size_t)b*MD*LL + (size_t)r1*LL + c0;
            if (MODE == 0) {
                int p0 = b*LL + c0;
                float2 m2 = *(const float2*)(mu + p0);
                float2 s2 = *(const float2*)(rs + p0);
                *(float2*)y0 = make_float2(s2.x*(v00 - m2.x*ws0) + wb0,
                                           s2.y*(v01 - m2.y*ws0) + wb0);
                *(float2*)y1 = make_float2(s2.x*(v10 - m2.x*ws1v) + wb1,
                                           s2.y*(v11 - m2.y*ws1v) + wb1);
            } else if (MODE == 1) {
                const float* q0 = res + (size_t)b*MD*LL + (size_t)r0*LL + c0;
                const float* q1 = res + (size_t)b*MD*LL + (size_t)r1*LL + c0;
                float2 a0 = *(const float2*)q0, a1 = *(const float2*)q1;
                *(float2*)y0 = make_float2(v00 + a0.x, v01 + a0.y);
                *(float2*)y1 = make_float2(v10 + a1.x, v11 + a1.y);
            } else {
                const float* q0 = res + (size_t)b*MD*LL + (size_t)r0*LL + c0;
                const float* q1 = res + (size_t)b*MD*LL + (size_t)r1*LL + c0;
                float2 a0 = *(const float2*)q0, a1 = *(const float2*)q1;
                *(float2*)y0 = make_float2(v00 + bv0 + a0.x, v01 + bv0 + a0.y);
                *(float2*)y1 = make_float2(v10 + bv1 + a1.x, v11 + bv1 + a1.y);
            }
        }
    }
}

// ---------------------------------------------------------------------------
// Attention
// ---------------------------------------------------------------------------
__global__ __launch_bounds__(128)
void attn_s_kernel()
{
    __shared__ float qs[HCC][129];
    __shared__ float ks[HCC][129];
    int bh = blockIdx.x, sp = blockIdx.y;
    int b = bh >> 3, h = bh & 7;
    int l0 = sp * 128;
    int tid = threadIdx.x;
    const float* qp = g_q + (size_t)b*CC*LL + (size_t)(h*HCC)*LL + l0;
    const float* kp = g_k + (size_t)b*CC*LL + (size_t)(h*HCC)*LL + l0;
    for (int idx = tid; idx < HCC*128; idx += 128) {
        int r = idx >> 7, ci = idx & 127;
        qs[r][ci] = qp[(size_t)r*LL + ci];
        ks[r][ci] = kp[(size_t)r*LL + ci];
    }
    __syncthreads();
    int d2 = tid & 15, cy = tid >> 4;
    float acc[2][4] = {{0.f,0.f,0.f,0.f},{0.f,0.f,0.f,0.f}};
#pragma unroll 4
    for (int l = 0; l < 128; l++) {
        float k0v = ks[2*d2][l], k1v = ks[2*d2+1][l];
#pragma unroll
        for (int i = 0; i < 4; i++) {
            float qv = qs[cy + 8*i][l];
            acc[0][i] = fmaf(qv, k0v, acc[0][i]);
            acc[1][i] = fmaf(qv, k1v, acc[1][i]);
        }
    }
    float* out = g_Sp + ((size_t)bh*NSPLIT + sp)*1024;
#pragma unroll
    for (int i = 0; i < 4; i++) {
        int c = cy + 8*i;
        out[c*32 + 2*d2]   = acc[0][i];
        out[c*32 + 2*d2+1] = acc[1][i];
    }
}

__global__ void attn_softmax_kernel()
{
    int bh = blockIdx.x, t = threadIdx.x;
    float s = 0.f;
    const float* sp = g_Sp + (size_t)bh*NSPLIT*1024 + t;
#pragma unroll
    for (int i = 0; i < NSPLIT; i++) s += sp[(size_t)i*1024];
    s *= 0.17677669529663687f;
    float mx = s;
#pragma unroll
    for (int o = 16; o > 0; o >>= 1) mx = fmaxf(mx, __shfl_xor_sync(0xffffffffu, mx, o));
    float e = expf(s - mx);
    float sum = e;
#pragma unroll
    for (int o = 16; o > 0; o >>= 1) sum += __shfl_xor_sync(0xffffffffu, sum, o);
    g_A[(size_t)bh*1024 + t] = e / sum;
}

// A@V writing packed bf16 hi/lo directly. Thread owns adjacent column pair.
__global__ __launch_bounds__(256)
void attn_av_kernel()
{
    __shared__ float As[1024];
    int bh = blockIdx.x;
    int b = bh >> 3, h = bh & 7;
    int tid = threadIdx.x;
#pragma unroll
    for (int i = 0; i < 4; i++) As[tid + 256*i] = g_A[(size_t)bh*1024 + tid + 256*i];
    __syncthreads();
    int c2 = blockIdx.y*256 + tid;          // pair index within LL/2
    const float* vp = g_v + (size_t)b*CC*LL + (size_t)(h*HCC)*LL + 2*c2;
    float acc0[32], acc1[32];
#pragma unroll
    for (int c = 0; c < 32; c++) { acc0[c]=0.f; acc1[c]=0.f; }
#pragma unroll 4
    for (int d = 0; d < 32; d++) {
        float2 v = *(const float2*)(vp + (size_t)d*LL);
#pragma unroll
        for (int c = 0; c < 32; c++) {
            float a = As[c*32+d];
            acc0[c] = fmaf(a, v.x, acc0[c]);
            acc1[c] = fmaf(a, v.y, acc1[c]);
        }
    }
#pragma unroll
    for (int c = 0; c < 32; c++) {
        size_t o = ((size_t)b*CC + h*HCC + c)*(LL/2) + c2;
        g_ah[o] = pack_hi2(acc0[c], acc1[c]);
        g_al[o] = pack_lo2(acc0[c], acc1[c]);
    }
}

// ---------------------------------------------------------------------------
// Launcher
// ---------------------------------------------------------------------------
extern "C" void kernel_launch(void* const* d_in, const int* in_sizes, int n_in,
                              void* d_out, int out_size)
{
    (void)in_sizes; (void)n_in; (void)out_size;
    const float* optical = (const float*)d_in[0];
    const float* sar     = (const float*)d_in[1];
    const float* gopt    = (const float*)d_in[2];
    const float* bopt    = (const float*)d_in[3];
    const float* gsar    = (const float*)d_in[4];
    const float* bsar    = (const float*)d_in[5];
    const float* Wq      = (const float*)d_in[6];
    const float* Wk      = (const float*)d_in[7];
    const float* Wv      = (const float*)d_in[8];
    const float* Wo      = (const float*)d_in[9];
    const float* gffn    = (const float*)d_in[10];
    const float* bffn    = (const float*)d_in[11];
    const float* W1      = (const float*)d_in[12];
    const float* b1      = (const float*)d_in[13];
    const float* W2      = (const float*)d_in[14];
    const float* b2      = (const float*)d_in[15];
    float* out = (float*)d_out;

    float *p_wsq,*p_wbq,*p_wsk,*p_wbk,*p_wsv,*p_wbv,*p_ws1,*p_wb1;
    float *p_mu_o,*p_rs_o,*p_mu_s,*p_rs_s,*p_mu_x,*p_rs_x;
    float *p_q,*p_k,*p_v,*p_x;
    u32 *p_Aqh,*p_Aql,*p_Akh,*p_Akl,*p_Avh,*p_Avl,*p_A1h,*p_A1l,*p_Aoh,*p_Aol,*p_A2h,*p_A2l;
    u32 *p_oh,*p_ol,*p_sh,*p_sl,*p_ah,*p_al,*p_xh,*p_xl,*p_hgh,*p_hgl;
    cudaGetSymbolAddress((void**)&p_wsq, g_wsq);   cudaGetSymbolAddress((void**)&p_wbq, g_wbq);
    cudaGetSymbolAddress((void**)&p_wsk, g_wsk);   cudaGetSymbolAddress((void**)&p_wbk, g_wbk);
    cudaGetSymbolAddress((void**)&p_wsv, g_wsv);   cudaGetSymbolAddress((void**)&p_wbv, g_wbv);
    cudaGetSymbolAddress((void**)&p_ws1, g_ws1);   cudaGetSymbolAddress((void**)&p_wb1, g_wb1v);
    cudaGetSymbolAddress((void**)&p_mu_o, g_mu_o); cudaGetSymbolAddress((void**)&p_rs_o, g_rs_o);
    cudaGetSymbolAddress((void**)&p_mu_s, g_mu_s); cudaGetSymbolAddress((void**)&p_rs_s, g_rs_s);
    cudaGetSymbolAddress((void**)&p_mu_x, g_mu_x); cudaGetSymbolAddress((void**)&p_rs_x, g_rs_x);
    cudaGetSymbolAddress((void**)&p_q, g_q);       cudaGetSymbolAddress((void**)&p_k, g_k);
    cudaGetSymbolAddress((void**)&p_v, g_v);       cudaGetSymbolAddress((void**)&p_x, g_x);
    cudaGetSymbolAddress((void**)&p_oh, g_oh);     cudaGetSymbolAddress((void**)&p_ol, g_ol);
    cudaGetSymbolAddress((void**)&p_sh, g_sh);     cudaGetSymbolAddress((void**)&p_sl, g_sl);
    cudaGetSymbolAddress((void**)&p_ah, g_ah);     cudaGetSymbolAddress((void**)&p_al, g_al);
    cudaGetSymbolAddress((void**)&p_xh, g_xh);     cudaGetSymbolAddress((void**)&p_xl, g_xl);
    cudaGetSymbolAddress((void**)&p_hgh, g_hgh);   cudaGetSymbolAddress((void**)&p_hgl, g_hgl);
    cudaGetSymbolAddress((void**)&p_Aqh, g_Aqh);   cudaGetSymbolAddress((void**)&p_Aql, g_Aql);
    cudaGetSymbolAddress((void**)&p_Akh, g_Akh);   cudaGetSymbolAddress((void**)&p_Akl, g_Akl);
    cudaGetSymbolAddress((void**)&p_Avh, g_Avh);   cudaGetSymbolAddress((void**)&p_Avl, g_Avl);
    cudaGetSymbolAddress((void**)&p_A1h, g_A1h);   cudaGetSymbolAddress((void**)&p_A1l, g_A1l);
    cudaGetSymbolAddress((void**)&p_Aoh, g_Aoh);   cudaGetSymbolAddress((void**)&p_Aol, g_Aol);
    cudaGetSymbolAddress((void**)&p_A2h, g_A2h);   cudaGetSymbolAddress((void**)&p_A2l, g_A2l);

    cudaFuncSetAttribute(gemm_mma<0,256,256>, cudaFuncAttributeMaxDynamicSharedMemorySize, GSMEM);
    cudaFuncSetAttribute(gemm_mma<1,256,256>, cudaFuncAttributeMaxDynamicSharedMemorySize, GSMEM);
    cudaFuncSetAttribute(gemm_mma<2,512,256>, cudaFuncAttributeMaxDynamicSharedMemorySize, GSMEM);
    cudaFuncSetAttribute(gemm_mma<3,256,FH>,  cudaFuncAttributeMaxDynamicSharedMemorySize, GSMEM);

    // 1) weight prep
    prep_fold<<<1792, 256>>>(Wq, Wk, Wv, W1, gopt, bopt, gsar, bsar, gffn, bffn, b1);
    prep_plain<<<256, 256>>>(Wo, p_Aoh, p_Aol, 256);
    prep_plain<<<256, 256>>>(W2, p_A2h, p_A2l, 512);

    // 2) LN stats + bf16 conversion
    ln_conv_kernel<<<(NPIX/2)/128, 128>>>(optical, p_mu_o, p_rs_o, p_oh, p_ol);
    ln_conv_kernel<<<(NPIX/2)/128, 128>>>(sar,     p_mu_s, p_rs_s, p_sh, p_sl);

    // 3) Q/K/V projections
    dim3 gp(LL/128, CC/128, BB);
    gemm_mma<0,256,256><<<gp,256,GSMEM>>>(p_Aqh, p_Aql, p_oh, p_ol, p_q, p_mu_o, p_rs_o, p_wsq, p_wbq, 0, 0);
    gemm_mma<0,256,256><<<gp,256,GSMEM>>>(p_Akh, p_Akl, p_sh, p_sl, p_k, p_mu_s, p_rs_s, p_wsk, p_wbk, 0, 0);
    gemm_mma<0,256,256><<<gp,256,GSMEM>>>(p_Avh, p_Avl, p_sh, p_sl, p_v, p_mu_s, p_rs_s, p_wsv, p_wbv, 0, 0);

    // 4) channel attention (attn -> packed bf16)
    attn_s_kernel<<<dim3(BB*NHH, NSPLIT), 128>>>();
    attn_softmax_kernel<<<BB*NHH, 1024>>>();
    attn_av_kernel<<<dim3(BB*NHH, (LL/2)/256), 256>>>();

    // 5) Wo + residual -> x (fp32)
    gemm_mma<1,256,256><<<gp,256,GSMEM>>>(p_Aoh, p_Aol, p_ah, p_al, p_x, 0, 0, 0, 0, optical, 0);

    // 6) LN stats + conversion on x
    ln_conv_kernel<<<(NPIX/2)/128, 128>>>(p_x, p_mu_x, p_rs_x, p_xh, p_xl);

    // 7) W1 (LN+b1 folded, row-paired) + fused SimpleGate -> hg (bf16 hi/lo)
    dim3 gp1(LL/128, FH2/128, BB);
    gemm_mma<3,256,FH><<<gp1,256,GSMEM>>>(p_A1h, p_A1l, p_xh, p_xl, (float*)0, p_mu_x, p_rs_x, p_ws1, p_wb1, 0, 0);

    // 8) W2 + b2 + residual -> out
    gemm_mma<2,512,256><<<gp,256,GSMEM>>>(p_A2h, p_A2l, p_hgh, p_hgl, out, 0, 0, 0, 0, p_x, b2);
}

// round 6
// speedup vs baseline: 3.4414x; 1.4249x over previous
#include <cuda_runtime.h>
#include <cuda_fp16.h>

typedef unsigned int u32;
typedef unsigned long long u64;

#define BB   16
#define CC   256
#define LL   4096
#define NHH  8
#define HCC  32
#define FH   512
#define FH2  1024
#define NPIX (BB*LL)
#define NSPLIT 32

// ---------------------------------------------------------------------------
// Scratch
// ---------------------------------------------------------------------------
__device__ float g_wsq[CC],  g_wbq[CC];
__device__ float g_wskv[2*CC], g_wbkv[2*CC];
__device__ float g_ws1[FH2], g_wb1v[FH2];      // permuted order
__device__ float g_mu_o[NPIX], g_rs_o[NPIX];
__device__ float g_mu_s[NPIX], g_rs_s[NPIX];
__device__ float g_mu_x[NPIX], g_rs_x[NPIX];
// weights: packed fp16x2 (k even in low 16) == fp16[M][K] row-major, hi+lo
__device__ __align__(128) u32 g_Aqh[CC*128],    g_Aql[CC*128];
__device__ __align__(128) u32 g_Akvh[2*CC*128], g_Akvl[2*CC*128];  // Wk rows 0-255, Wv 256-511
__device__ __align__(128) u32 g_A1h[FH2*128],   g_A1l[FH2*128];    // permuted rows
__device__ __align__(128) u32 g_Aoh[CC*128],    g_Aol[CC*128];
__device__ __align__(128) u32 g_A2h[CC*256],    g_A2l[CC*256];
// fp32 activations (attention path + residuals)
__device__ __align__(128) float g_q[BB*CC*LL];
__device__ __align__(128) float g_kv[BB*2*CC*LL];   // k rows 0-255, v rows 256-511
__device__ __align__(128) float g_x[BB*CC*LL];
// fp16 activations (GEMM B operands), packed u32 [C][L/2] per batch
__device__ __align__(128) u32 g_o16[BB*CC*(LL/2)];
__device__ __align__(128) u32 g_s16[BB*CC*(LL/2)];
__device__ __align__(128) u32 g_a16[BB*CC*(LL/2)];
__device__ __align__(128) u32 g_x16[BB*CC*(LL/2)];
__device__ __align__(128) u32 g_hg[BB*FH*(LL/2)];
__device__ __align__(128) float g_Sp[BB*NHH*NSPLIT*HCC*HCC];
__device__ __align__(128) float g_A[BB*NHH*HCC*HCC];

// ---------------------------------------------------------------------------
// PTX helpers
// ---------------------------------------------------------------------------
__device__ __forceinline__ u32 smem_u32(const void* p) {
    u32 a;
    asm("{ .reg .u64 t; cvta.to.shared.u64 t, %1; cvt.u32.u64 %0, t; }" : "=r"(a) : "l"(p));
    return a;
}
#define LDSM_X4(r0,r1,r2,r3,addr) \
    asm volatile("ldmatrix.sync.aligned.m8n8.x4.shared.b16 {%0,%1,%2,%3}, [%4];" \
        : "=r"(r0),"=r"(r1),"=r"(r2),"=r"(r3) : "r"(addr))
#define LDSM_X4_T(r0,r1,r2,r3,addr) \
    asm volatile("ldmatrix.sync.aligned.m8n8.x4.trans.shared.b16 {%0,%1,%2,%3}, [%4];" \
        : "=r"(r0),"=r"(r1),"=r"(r2),"=r"(r3) : "r"(addr))
#define MMA_F16(d, a, b0, b1) \
    asm volatile("mma.sync.aligned.m16n8k16.row.col.f32.f16.f16.f32 " \
        "{%0,%1,%2,%3}, {%4,%5,%6,%7}, {%8,%9}, {%0,%1,%2,%3};" \
        : "+f"((d)[0]),"+f"((d)[1]),"+f"((d)[2]),"+f"((d)[3]) \
        : "r"((a)[0]),"r"((a)[1]),"r"((a)[2]),"r"((a)[3]), "r"(b0),"r"(b1))
#define CP16(dst, src) \
    asm volatile("cp.async.cg.shared.global [%0], [%1], 16;" \
        :: "r"(dst), "l"(src) : "memory")
#define CP_COMMIT() asm volatile("cp.async.commit_group;" ::: "memory")
#define CP_WAIT(n)  asm volatile("cp.async.wait_group %0;" :: "n"(n) : "memory")

__device__ __forceinline__ u32 packf16(float a, float b) {
    __half2 h = __floats2half2_rn(a, b);
    return *(u32*)&h;
}

// ---------------------------------------------------------------------------
// Prep: fold LN gain, compute rowsum(W*g), W@beta (+b1); fp16 hi/lo split.
// W1 rows permuted for gate pairing (as R4/R5). Wk/Wv stacked.
// ---------------------------------------------------------------------------
__global__ void prep_fold(const float* __restrict__ Wq, const float* __restrict__ Wk,
                          const float* __restrict__ Wv, const float* __restrict__ W1,
                          const float* __restrict__ gopt, const float* __restrict__ bopt,
                          const float* __restrict__ gsar, const float* __restrict__ bsar,
                          const float* __restrict__ gffn, const float* __restrict__ bffn,
                          const float* __restrict__ b1)
{
    int row = blockIdx.x;   // 0..1791
    int c   = threadIdx.x;
    const float* W; float* ws; float* wb; u32* Ah; u32* Al;
    const float* gg; const float* bb; int m, mdst; float extra = 0.f;
    if (row < 256)      { W=Wq; ws=g_wsq;  wb=g_wbq;  Ah=g_Aqh;  Al=g_Aql;  gg=gopt; bb=bopt; m=row;     mdst=m; }
    else if (row < 512) { W=Wk; ws=g_wskv; wb=g_wbkv; Ah=g_Akvh; Al=g_Akvl; gg=gsar; bb=bsar; m=row-256; mdst=m; }
    else if (row < 768) { W=Wv; ws=g_wskv; wb=g_wbkv; Ah=g_Akvh; Al=g_Akvl; gg=gsar; bb=bsar; m=row-512; mdst=m+256; }
    else {
        W=W1; ws=g_ws1; wb=g_wb1v; Ah=g_A1h; Al=g_A1l; gg=gffn; bb=bffn; m=row-768;
        extra = b1[m];
        if (m < FH) mdst = ((m>>3)<<4) + (m&7);
        else        { int mm = m-FH; mdst = ((mm>>3)<<4) + (mm&7) + 8; }
    }
    float w  = W[m*CC + c];
    float wg = w * gg[c];
    __half h = __float2half_rn(wg);
    float hf = __half2float(h);
    __half l = __float2half_rn(wg - hf);
    u32 hu = (u32)__half_as_ushort(h);
    u32 lu = (u32)__half_as_ushort(l);
    u32 hp = __shfl_xor_sync(0xffffffffu, hu, 1);
    u32 lp = __shfl_xor_sync(0xffffffffu, lu, 1);
    if (!(c & 1)) {
        Ah[mdst*128 + (c>>1)] = hu | (hp << 16);
        Al[mdst*128 + (c>>1)] = lu | (lp << 16);
    }
    __shared__ float s1[256], s2[256];
    s1[c] = wg; s2[c] = w * bb[c];
    __syncthreads();
    for (int off = 128; off > 0; off >>= 1) {
        if (c < off) { s1[c] += s1[c+off]; s2[c] += s2[c+off]; }
        __syncthreads();
    }
    if (c == 0) { ws[mdst] = s1[0]; wb[mdst] = s2[0] + extra; }
}

__global__ void prep_plain(const float* __restrict__ W, u32* __restrict__ Ah,
                           u32* __restrict__ Al, int K)
{
    int m = blockIdx.x, c0 = threadIdx.x;
    for (int k0 = 0; k0 < K; k0 += 256) {
        int c = k0 + c0;
        float w = W[(size_t)m*K + c];
        __half h = __float2half_rn(w);
        float hf = __half2float(h);
        __half l = __float2half_rn(w - hf);
        u32 hu = (u32)__half_as_ushort(h);
        u32 lu = (u32)__half_as_ushort(l);
        u32 hp = __shfl_xor_sync(0xffffffffu, hu, 1);
        u32 lp = __shfl_xor_sync(0xffffffffu, lu, 1);
        if (!(c0 & 1)) {
            Ah[(size_t)m*(K/2) + (c>>1)] = hu | (hp << 16);
            Al[(size_t)m*(K/2) + (c>>1)] = lu | (lp << 16);
        }
    }
}

// ---------------------------------------------------------------------------
// LN stats + fp16 conversion. 512 threads: 128 pixel-pairs/block, 4 threads
// per pair each covering 64 channels; smem combine for stats.
// ---------------------------------------------------------------------------
__global__ __launch_bounds__(512)
void ln_conv_kernel(const float* __restrict__ x,
                    float* __restrict__ mu, float* __restrict__ rs,
                    u32* __restrict__ x16)
{
    __shared__ float ssx[512], ssx2[512], ssy[512], ssy2[512];
    int tid = threadIdx.x;
    int pr = tid & 127, qd = tid >> 7;
    int p2 = blockIdx.x*128 + pr;
    int b = p2 >> 11, l2 = p2 & 2047;
    const float* base = x + (size_t)b*CC*LL + 2*l2;
    u32* oh = x16 + (size_t)b*CC*(LL/2) + l2;
    float sx=0.f, sx2=0.f, sy=0.f, sy2=0.f;
    int c0 = qd*64;
#pragma unroll 8
    for (int i = 0; i < 64; i++) {
        int c = c0 + i;
        float2 v = *(const float2*)(base + (size_t)c*LL);
        sx += v.x; sx2 = fmaf(v.x, v.x, sx2);
        sy += v.y; sy2 = fmaf(v.y, v.y, sy2);
        oh[(size_t)c*(LL/2)] = packf16(v.x, v.y);
    }
    ssx[tid]=sx; ssx2[tid]=sx2; ssy[tid]=sy; ssy2[tid]=sy2;
    __syncthreads();
    if (qd == 0) {
        float tx  = ssx[pr]  + ssx[pr+128]  + ssx[pr+256]  + ssx[pr+384];
        float tx2 = ssx2[pr] + ssx2[pr+128] + ssx2[pr+256] + ssx2[pr+384];
        float ty  = ssy[pr]  + ssy[pr+128]  + ssy[pr+256]  + ssy[pr+384];
        float ty2 = ssy2[pr] + ssy2[pr+128] + ssy2[pr+256] + ssy2[pr+384];
        float mx = tx*(1.f/CC), my = ty*(1.f/CC);
        int p = b*LL + 2*l2;
        mu[p]   = mx; rs[p]   = rsqrtf(fmaf(-mx, mx, tx2*(1.f/CC)) + 1e-5f);
        mu[p+1] = my; rs[p+1] = rsqrtf(fmaf(-my, my, ty2*(1.f/CC)) + 1e-5f);
    }
}

// ---------------------------------------------------------------------------
// fp16 2-term GEMM, cp.async 2-stage, 2 CTAs/SM. CTA 128x128, K chunk 32.
// A = weight hi+lo fp16 ; B = single fp16 activation.
// MODE 0: LN epilogue -> fp32 ; 1: +res ; 2: +bias +res ; 3: gate -> fp16 g_hg
// ---------------------------------------------------------------------------
#define A_STR 80
#define B_STR 272
#define AS_H  0
#define AS_L  10240
#define BS_B  20480
#define STAGE 29184
#define GSMEM (2*STAGE)

template<int MODE, int KD, int MD>
__global__ __launch_bounds__(256, 2)
void gemm_mma(const u32* __restrict__ Ah, const u32* __restrict__ Al,
              const u32* __restrict__ Xp,
              float* __restrict__ Y,
              const float* __restrict__ mu, const float* __restrict__ rs,
              const float* __restrict__ wsum, const float* __restrict__ wb,
              const float* __restrict__ res, const float* __restrict__ bias)
{
    extern __shared__ __align__(128) char smem[];
    const u32 sbase = smem_u32(smem);

    int tid = threadIdx.x, lane = tid & 31, wid = tid >> 5;
    int n0 = blockIdx.x * 128, m0 = blockIdx.y * 128, b = blockIdx.z;
    int wm = wid >> 2, wn = wid & 3;

    float acc[4][4][4];
#pragma unroll
    for (int i=0;i<4;i++)
#pragma unroll
        for (int j=0;j<4;j++)
#pragma unroll
            for (int r=0;r<4;r++) acc[i][j][r]=0.f;

    // cp.async mapping: A (hi/lo): 512 x 16B each -> 2/thread; B: 512 x 16B -> 2/thread
    int ia0 = tid, ia1 = tid + 256;
    int ar0 = ia0 >> 2, ap0 = (ia0 & 3) * 4;
    int ar1 = ia1 >> 2, ap1 = (ia1 & 3) * 4;
    int br0 = ia0 >> 4, bc0 = (ia0 & 15) * 4;
    int br1 = ia1 >> 4, bc1 = (ia1 & 15) * 4;
    const u32* srcAh0 = Ah + (size_t)(m0+ar0)*(KD/2) + ap0;
    const u32* srcAh1 = Ah + (size_t)(m0+ar1)*(KD/2) + ap1;
    const u32* srcAl0 = Al + (size_t)(m0+ar0)*(KD/2) + ap0;
    const u32* srcAl1 = Al + (size_t)(m0+ar1)*(KD/2) + ap1;
    const u32* Xb = Xp + (size_t)b*KD*(LL/2) + (n0>>1);
    const u32* srcB0 = Xb + (size_t)br0*(LL/2) + bc0;
    const u32* srcB1 = Xb + (size_t)br1*(LL/2) + bc1;
    u32 dAh0 = sbase + AS_H + (u32)(ar0*A_STR + ap0*4);
    u32 dAh1 = sbase + AS_H + (u32)(ar1*A_STR + ap1*4);
    u32 dAl0 = sbase + AS_L + (u32)(ar0*A_STR + ap0*4);
    u32 dAl1 = sbase + AS_L + (u32)(ar1*A_STR + ap1*4);
    u32 dB0  = sbase + BS_B + (u32)(br0*B_STR + bc0*4);
    u32 dB1  = sbase + BS_B + (u32)(br1*B_STR + bc1*4);

    u32 a_lm_base = sbase + (u32)((wm*64 + (lane & 15)) * A_STR) + ((lane & 16) ? 16u : 0u);
    u32 b_lm_base = sbase + BS_B + (u32)((lane & 15) * B_STR)
                  + (u32)((wn*32 + ((lane & 16) ? 8 : 0)) * 2);

#define ISSUE(st, kc) do { \
        u32 so = (u32)((st)*STAGE); \
        int ko2 = (kc) >> 1; size_t kb = (size_t)(kc)*(LL/2); \
        CP16(dAh0+so, srcAh0+ko2); CP16(dAh1+so, srcAh1+ko2); \
        CP16(dAl0+so, srcAl0+ko2); CP16(dAl1+so, srcAl1+ko2); \
        CP16(dB0+so,  srcB0+kb);   CP16(dB1+so,  srcB1+kb); \
        CP_COMMIT(); \
    } while(0)

    ISSUE(0, 0);

#pragma unroll 1
    for (int kc = 0; kc < KD; kc += 32) {
        int cur = (kc >> 5) & 1;
        if (kc + 32 < KD) {
            ISSUE(cur ^ 1, kc + 32);
            CP_WAIT(1);
        } else {
            CP_WAIT(0);
        }
        __syncthreads();
        u32 so = (u32)(cur * STAGE);
#pragma unroll
        for (int ks = 0; ks < 32; ks += 16) {
            u32 ah[4][4], al[4][4], bf[4][2];
            u32 ab = a_lm_base + so + (u32)(ks*2);
#pragma unroll
            for (int i = 0; i < 4; i++) {
                LDSM_X4(ah[i][0], ah[i][1], ah[i][2], ah[i][3], ab + AS_H + (u32)(i*16*A_STR));
                LDSM_X4(al[i][0], al[i][1], al[i][2], al[i][3], ab + AS_L + (u32)(i*16*A_STR));
            }
            u32 bb0 = b_lm_base + so + (u32)(ks*B_STR);
#pragma unroll
            for (int j2 = 0; j2 < 2; j2++)
                LDSM_X4_T(bf[j2*2][0], bf[j2*2][1], bf[j2*2+1][0], bf[j2*2+1][1], bb0 + (u32)(j2*32));
#pragma unroll
            for (int i = 0; i < 4; i++)
#pragma unroll
                for (int j = 0; j < 4; j++) {
                    MMA_F16(acc[i][j], ah[i], bf[j][0], bf[j][1]);
                    MMA_F16(acc[i][j], al[i], bf[j][0], bf[j][1]);
                }
        }
        __syncthreads();
    }
#undef ISSUE

    // ---- epilogue
#pragma unroll
    for (int i = 0; i < 4; i++) {
        int r0 = m0 + wm*64 + i*16 + (lane >> 2);
        int r1 = r0 + 8;
        if (MODE == 3) {
            int t = ((r0 >> 4) << 3) + (r0 & 7);
            float ws1 = wsum[r0], wb1 = wb[r0];
            float ws2 = wsum[r1], wb2 = wb[r1];
#pragma unroll
            for (int j = 0; j < 4; j++) {
                int c0 = n0 + wn*32 + j*8 + 2*(lane & 3);
                int p0 = b*LL + c0;
                float2 m2 = *(const float2*)(mu + p0);
                float2 s2 = *(const float2*)(rs + p0);
                float e1x = s2.x*(acc[i][j][0] - m2.x*ws1) + wb1;
                float e1y = s2.y*(acc[i][j][1] - m2.y*ws1) + wb1;
                float e2x = s2.x*(acc[i][j][2] - m2.x*ws2) + wb2;
                float e2y = s2.y*(acc[i][j][3] - m2.y*ws2) + wb2;
                g_hg[((size_t)b*FH + t)*(LL/2) + (c0 >> 1)] = packf16(e1x*e2x, e1y*e2y);
            }
            continue;
        }
        float ws0, wb0, ws1v, wb1;
        if (MODE == 0) { ws0 = wsum[r0]; wb0 = wb[r0]; ws1v = wsum[r1]; wb1 = wb[r1]; }
        float bv0 = 0.f, bv1 = 0.f;
        if (MODE == 2) { bv0 = bias[r0]; bv1 = bias[r1]; }
#pragma unroll
        for (int j = 0; j < 4; j++) {
            int c0 = n0 + wn*32 + j*8 + 2*(lane & 3);
            float v00 = acc[i][j][0], v01 = acc[i][j][1];
            float v10 = acc[i][j][2], v11 = acc[i][j][3];
            float* y0 = Y + (size_t)b*MD*LL + (size_t)r0*LL + c0;
            float* y1 = Y + (size_t)b*MD*LL + (size_t)r1*LL + c0;
            if (MODE == 0) {
                int p0 = b*LL + c0;
                float2 m2 = *(const float2*)(mu + p0);
                float2 s2 = *(const float2*)(rs + p0);
                *(float2*)y0 = make_float2(s2.x*(v00 - m2.x*ws0) + wb0,
                                           s2.y*(v01 - m2.y*ws0) + wb0);
                *(float2*)y1 = make_float2(s2.x*(v10 - m2.x*ws1v) + wb1,
                                           s2.y*(v11 - m2.y*ws1v) + wb1);
            } else if (MODE == 1) {
                const float* q0 = res + (size_t)b*MD*LL + (size_t)r0*LL + c0;
                const float* q1 = res + (size_t)b*MD*LL + (size_t)r1*LL + c0;
                float2 a0 = *(const float2*)q0, a1 = *(const float2*)q1;
                *(float2*)y0 = make_float2(v00 + a0.x, v01 + a0.y);
                *(float2*)y1 = make_float2(v10 + a1.x, v11 + a1.y);
            } else {
                const float* q0 = res + (size_t)b*MD*LL + (size_t)r0*LL + c0;
                const float* q1 = res + (size_t)b*MD*LL + (size_t)r1*LL + c0;
                float2 a0 = *(const float2*)q0, a1 = *(const float2*)q1;
                *(float2*)y0 = make_float2(v00 + bv0 + a0.x, v01 + bv0 + a0.y);
                *(float2*)y1 = make_float2(v10 + bv1 + a1.x, v11 + bv1 + a1.y);
            }
        }
    }
}

// ---------------------------------------------------------------------------
// Attention (q from g_q; k = g_kv rows 0-255; v = g_kv rows 256-511)
// ---------------------------------------------------------------------------
__global__ __launch_bounds__(128)
void attn_s_kernel()
{
    __shared__ float qs[HCC][129];
    __shared__ float ks[HCC][129];
    int bh = blockIdx.x, sp = blockIdx.y;
    int b = bh >> 3, h = bh & 7;
    int l0 = sp * 128;
    int tid = threadIdx.x;
    const float* qp = g_q  + (size_t)b*CC*LL   + (size_t)(h*HCC)*LL + l0;
    const float* kp = g_kv + (size_t)b*2*CC*LL + (size_t)(h*HCC)*LL + l0;
    for (int idx = tid; idx < HCC*128; idx += 128) {
        int r = idx >> 7, ci = idx & 127;
        qs[r][ci] = qp[(size_t)r*LL + ci];
        ks[r][ci] = kp[(size_t)r*LL + ci];
    }
    __syncthreads();
    int d2 = tid & 15, cy = tid >> 4;
    float acc[2][4] = {{0.f,0.f,0.f,0.f},{0.f,0.f,0.f,0.f}};
#pragma unroll 4
    for (int l = 0; l < 128; l++) {
        float k0v = ks[2*d2][l], k1v = ks[2*d2+1][l];
#pragma unroll
        for (int i = 0; i < 4; i++) {
            float qv = qs[cy + 8*i][l];
            acc[0][i] = fmaf(qv, k0v, acc[0][i]);
            acc[1][i] = fmaf(qv, k1v, acc[1][i]);
        }
    }
    float* out = g_Sp + ((size_t)bh*NSPLIT + sp)*1024;
#pragma unroll
    for (int i = 0; i < 4; i++) {
        int c = cy + 8*i;
        out[c*32 + 2*d2]   = acc[0][i];
        out[c*32 + 2*d2+1] = acc[1][i];
    }
}

__global__ void attn_softmax_kernel()
{
    int bh = blockIdx.x, t = threadIdx.x;
    float s = 0.f;
    const float* sp = g_Sp + (size_t)bh*NSPLIT*1024 + t;
#pragma unroll
    for (int i = 0; i < NSPLIT; i++) s += sp[(size_t)i*1024];
    s *= 0.17677669529663687f;
    float mx = s;
#pragma unroll
    for (int o = 16; o > 0; o >>= 1) mx = fmaxf(mx, __shfl_xor_sync(0xffffffffu, mx, o));
    float e = expf(s - mx);
    float sum = e;
#pragma unroll
    for (int o = 16; o > 0; o >>= 1) sum += __shfl_xor_sync(0xffffffffu, sum, o);
    g_A[(size_t)bh*1024 + t] = e / sum;
}

__global__ __launch_bounds__(256)
void attn_av_kernel()
{
    __shared__ float As[1024];
    int bh = blockIdx.x;
    int b = bh >> 3, h = bh & 7;
    int tid = threadIdx.x;
#pragma unroll
    for (int i = 0; i < 4; i++) As[tid + 256*i] = g_A[(size_t)bh*1024 + tid + 256*i];
    __syncthreads();
    int c2 = blockIdx.y*256 + tid;
    const float* vp = g_kv + (size_t)b*2*CC*LL + (size_t)(CC + h*HCC)*LL + 2*c2;
    float acc0[32], acc1[32];
#pragma unroll
    for (int c = 0; c < 32; c++) { acc0[c]=0.f; acc1[c]=0.f; }
#pragma unroll 4
    for (int d = 0; d < 32; d++) {
        float2 v = *(const float2*)(vp + (size_t)d*LL);
#pragma unroll
        for (int c = 0; c < 32; c++) {
            float a = As[c*32+d];
            acc0[c] = fmaf(a, v.x, acc0[c]);
            acc1[c] = fmaf(a, v.y, acc1[c]);
        }
    }
#pragma unroll
    for (int c = 0; c < 32; c++) {
        g_a16[((size_t)b*CC + h*HCC + c)*(LL/2) + c2] = packf16(acc0[c], acc1[c]);
    }
}

// ---------------------------------------------------------------------------
// Launcher
// ---------------------------------------------------------------------------
extern "C" void kernel_launch(void* const* d_in, const int* in_sizes, int n_in,
                              void* d_out, int out_size)
{
    (void)in_sizes; (void)n_in; (void)out_size;
    const float* optical = (const float*)d_in[0];
    const float* sar     = (const float*)d_in[1];
    const float* gopt    = (const float*)d_in[2];
    const float* bopt    = (const float*)d_in[3];
    const float* gsar    = (const float*)d_in[4];
    const float* bsar    = (const float*)d_in[5];
    const float* Wq      = (const float*)d_in[6];
    const float* Wk      = (const float*)d_in[7];
    const float* Wv      = (const float*)d_in[8];
    const float* Wo      = (const float*)d_in[9];
    const float* gffn    = (const float*)d_in[10];
    const float* bffn    = (const float*)d_in[11];
    const float* W1      = (const float*)d_in[12];
    const float* b1      = (const float*)d_in[13];
    const float* W2      = (const float*)d_in[14];
    const float* b2      = (const float*)d_in[15];
    float* out = (float*)d_out;

    float *p_wsq,*p_wbq,*p_wskv,*p_wbkv,*p_ws1,*p_wb1;
    float *p_mu_o,*p_rs_o,*p_mu_s,*p_rs_s,*p_mu_x,*p_rs_x;
    float *p_q,*p_kv,*p_x;
    u32 *p_Aqh,*p_Aql,*p_Akvh,*p_Akvl,*p_A1h,*p_A1l,*p_Aoh,*p_Aol,*p_A2h,*p_A2l;
    u32 *p_o16,*p_s16,*p_a16,*p_x16,*p_hg;
    cudaGetSymbolAddress((void**)&p_wsq, g_wsq);     cudaGetSymbolAddress((void**)&p_wbq, g_wbq);
    cudaGetSymbolAddress((void**)&p_wskv, g_wskv);   cudaGetSymbolAddress((void**)&p_wbkv, g_wbkv);
    cudaGetSymbolAddress((void**)&p_ws1, g_ws1);     cudaGetSymbolAddress((void**)&p_wb1, g_wb1v);
    cudaGetSymbolAddress((void**)&p_mu_o, g_mu_o);   cudaGetSymbolAddress((void**)&p_rs_o, g_rs_o);
    cudaGetSymbolAddress((void**)&p_mu_s, g_mu_s);   cudaGetSymbolAddress((void**)&p_rs_s, g_rs_s);
    cudaGetSymbolAddress((void**)&p_mu_x, g_mu_x);   cudaGetSymbolAddress((void**)&p_rs_x, g_rs_x);
    cudaGetSymbolAddress((void**)&p_q, g_q);         cudaGetSymbolAddress((void**)&p_kv, g_kv);
    cudaGetSymbolAddress((void**)&p_x, g_x);
    cudaGetSymbolAddress((void**)&p_o16, g_o16);     cudaGetSymbolAddress((void**)&p_s16, g_s16);
    cudaGetSymbolAddress((void**)&p_a16, g_a16);     cudaGetSymbolAddress((void**)&p_x16, g_x16);
    cudaGetSymbolAddress((void**)&p_hg, g_hg);
    cudaGetSymbolAddress((void**)&p_Aqh, g_Aqh);     cudaGetSymbolAddress((void**)&p_Aql, g_Aql);
    cudaGetSymbolAddress((void**)&p_Akvh, g_Akvh);   cudaGetSymbolAddress((void**)&p_Akvl, g_Akvl);
    cudaGetSymbolAddress((void**)&p_A1h, g_A1h);     cudaGetSymbolAddress((void**)&p_A1l, g_A1l);
    cudaGetSymbolAddress((void**)&p_Aoh, g_Aoh);     cudaGetSymbolAddress((void**)&p_Aol, g_Aol);
    cudaGetSymbolAddress((void**)&p_A2h, g_A2h);     cudaGetSymbolAddress((void**)&p_A2l, g_A2l);

    cudaFuncSetAttribute(gemm_mma<0,256,256>, cudaFuncAttributeMaxDynamicSharedMemorySize, GSMEM);
    cudaFuncSetAttribute(gemm_mma<0,256,512>, cudaFuncAttributeMaxDynamicSharedMemorySize, GSMEM);
    cudaFuncSetAttribute(gemm_mma<1,256,256>, cudaFuncAttributeMaxDynamicSharedMemorySize, GSMEM);
    cudaFuncSetAttribute(gemm_mma<2,512,256>, cudaFuncAttributeMaxDynamicSharedMemorySize, GSMEM);
    cudaFuncSetAttribute(gemm_mma<3,256,FH>,  cudaFuncAttributeMaxDynamicSharedMemorySize, GSMEM);

    // 1) weight prep
    prep_fold<<<1792, 256>>>(Wq, Wk, Wv, W1, gopt, bopt, gsar, bsar, gffn, bffn, b1);
    prep_plain<<<256, 256>>>(Wo, p_Aoh, p_Aol, 256);
    prep_plain<<<256, 256>>>(W2, p_A2h, p_A2l, 512);

    // 2) LN stats + fp16 conversion
    ln_conv_kernel<<<(NPIX/2)/128, 512>>>(optical, p_mu_o, p_rs_o, p_o16);
    ln_conv_kernel<<<(NPIX/2)/128, 512>>>(sar,     p_mu_s, p_rs_s, p_s16);

    // 3) Q projection + fused K/V projection
    dim3 gp(LL/128, CC/128, BB);
    dim3 gkv(LL/128, 2*CC/128, BB);
    gemm_mma<0,256,256><<<gp, 256,GSMEM>>>(p_Aqh,  p_Aql,  p_o16, p_q,  p_mu_o, p_rs_o, p_wsq,  p_wbq,  0, 0);
    gemm_mma<0,256,512><<<gkv,256,GSMEM>>>(p_Akvh, p_Akvl, p_s16, p_kv, p_mu_s, p_rs_s, p_wskv, p_wbkv, 0, 0);

    // 4) channel attention -> fp16 attn
    attn_s_kernel<<<dim3(BB*NHH, NSPLIT), 128>>>();
    attn_softmax_kernel<<<BB*NHH, 1024>>>();
    attn_av_kernel<<<dim3(BB*NHH, (LL/2)/256), 256>>>();

    // 5) Wo + residual -> x (fp32)
    gemm_mma<1,256,256><<<gp,256,GSMEM>>>(p_Aoh, p_Aol, p_a16, p_x, 0, 0, 0, 0, optical, 0);

    // 6) LN stats + fp16 conversion on x
    ln_conv_kernel<<<(NPIX/2)/128, 512>>>(p_x, p_mu_x, p_rs_x, p_x16);

    // 7) W1 (LN+b1 folded, row-paired) + fused SimpleGate -> hg (fp16)
    dim3 gp1(LL/128, FH2/128, BB);
    gemm_mma<3,256,FH><<<gp1,256,GSMEM>>>(p_A1h, p_A1l, p_x16, (float*)0, p_mu_x, p_rs_x, p_ws1, p_wb1, 0, 0);

    // 8) W2 + b2 + residual -> out
    gemm_mma<2,512,256><<<gp,256,GSMEM>>>(p_A2h, p_A2l, p_hg, out, 0, 0, 0, 0, p_x, b2);
}

// round 7
// speedup vs baseline: 4.5725x; 1.3287x over previous
#include <cuda_runtime.h>
#include <cuda_fp16.h>

typedef unsigned int u32;
typedef unsigned long long u64;

#define BB   16
#define CC   256
#define LL   4096
#define NHH  8
#define HCC  32
#define FH   512
#define FH2  1024
#define NPIX (BB*LL)
#define NSPLIT 32

// ---------------------------------------------------------------------------
// Scratch
// ---------------------------------------------------------------------------
__device__ float g_wsq[CC],  g_wbq[CC];
__device__ float g_wskv[2*CC], g_wbkv[2*CC];
__device__ float g_ws1[FH2], g_wb1v[FH2];      // permuted order
__device__ float g_mu_o[NPIX], g_rs_o[NPIX];
__device__ float g_mu_s[NPIX], g_rs_s[NPIX];
__device__ float g_mu_x[NPIX], g_rs_x[NPIX];
// weights: packed fp16x2 (k even in low 16) == fp16[M][K] row-major
__device__ __align__(128) u32 g_Aq[CC*128];
__device__ __align__(128) u32 g_Akv[2*CC*128];   // Wk rows 0-255, Wv 256-511
__device__ __align__(128) u32 g_A1[FH2*128];     // permuted rows
__device__ __align__(128) u32 g_Ao[CC*128];
__device__ __align__(128) u32 g_A2[CC*256];
// fp32 activations (residual path)
__device__ __align__(128) float g_x[BB*CC*LL];
// fp16 activations, packed u32 [C][L/2] per batch
__device__ __align__(128) u32 g_o16[BB*CC*(LL/2)];
__device__ __align__(128) u32 g_s16[BB*CC*(LL/2)];
__device__ __align__(128) u32 g_q16[BB*CC*(LL/2)];
__device__ __align__(128) u32 g_kv16[BB*2*CC*(LL/2)];  // k rows 0-255, v 256-511
__device__ __align__(128) u32 g_a16[BB*CC*(LL/2)];
__device__ __align__(128) u32 g_x16[BB*CC*(LL/2)];
__device__ __align__(128) u32 g_hg[BB*FH*(LL/2)];
__device__ __align__(128) float g_Sp[BB*NHH*NSPLIT*HCC*HCC];
__device__ __align__(128) float g_A[BB*NHH*HCC*HCC];

// ---------------------------------------------------------------------------
// PTX helpers
// ---------------------------------------------------------------------------
__device__ __forceinline__ u32 smem_u32(const void* p) {
    u32 a;
    asm("{ .reg .u64 t; cvta.to.shared.u64 t, %1; cvt.u32.u64 %0, t; }" : "=r"(a) : "l"(p));
    return a;
}
#define LDSM_X4(r0,r1,r2,r3,addr) \
    asm volatile("ldmatrix.sync.aligned.m8n8.x4.shared.b16 {%0,%1,%2,%3}, [%4];" \
        : "=r"(r0),"=r"(r1),"=r"(r2),"=r"(r3) : "r"(addr))
#define LDSM_X4_T(r0,r1,r2,r3,addr) \
    asm volatile("ldmatrix.sync.aligned.m8n8.x4.trans.shared.b16 {%0,%1,%2,%3}, [%4];" \
        : "=r"(r0),"=r"(r1),"=r"(r2),"=r"(r3) : "r"(addr))
#define MMA_F16(d, a, b0, b1) \
    asm volatile("mma.sync.aligned.m16n8k16.row.col.f32.f16.f16.f32 " \
        "{%0,%1,%2,%3}, {%4,%5,%6,%7}, {%8,%9}, {%0,%1,%2,%3};" \
        : "+f"((d)[0]),"+f"((d)[1]),"+f"((d)[2]),"+f"((d)[3]) \
        : "r"((a)[0]),"r"((a)[1]),"r"((a)[2]),"r"((a)[3]), "r"(b0),"r"(b1))
#define CP16(dst, src) \
    asm volatile("cp.async.cg.shared.global [%0], [%1], 16;" \
        :: "r"(dst), "l"(src) : "memory")
#define CP_COMMIT() asm volatile("cp.async.commit_group;" ::: "memory")
#define CP_WAIT(n)  asm volatile("cp.async.wait_group %0;" :: "n"(n) : "memory")

__device__ __forceinline__ u32 packf16(float a, float b) {
    __half2 h = __floats2half2_rn(a, b);
    return *(u32*)&h;
}
__device__ __forceinline__ float2 unpackf16(u32 w) {
    __half2 h = *(__half2*)&w;
    return __half22float2(h);
}

// ---------------------------------------------------------------------------
// Prep: fold LN gain, rowsum(W*g), W@beta (+b1); single fp16 weights.
// W1 rows permuted for gate pairing. Wk/Wv stacked.
// ---------------------------------------------------------------------------
__global__ void prep_fold(const float* __restrict__ Wq, const float* __restrict__ Wk,
                          const float* __restrict__ Wv, const float* __restrict__ W1,
                          const float* __restrict__ gopt, const float* __restrict__ bopt,
                          const float* __restrict__ gsar, const float* __restrict__ bsar,
                          const float* __restrict__ gffn, const float* __restrict__ bffn,
                          const float* __restrict__ b1)
{
    int row = blockIdx.x;   // 0..1791
    int c   = threadIdx.x;
    const float* W; float* ws; float* wb; u32* Ah;
    const float* gg; const float* bb; int m, mdst; float extra = 0.f;
    if (row < 256)      { W=Wq; ws=g_wsq;  wb=g_wbq;  Ah=g_Aq;  gg=gopt; bb=bopt; m=row;     mdst=m; }
    else if (row < 512) { W=Wk; ws=g_wskv; wb=g_wbkv; Ah=g_Akv; gg=gsar; bb=bsar; m=row-256; mdst=m; }
    else if (row < 768) { W=Wv; ws=g_wskv; wb=g_wbkv; Ah=g_Akv; gg=gsar; bb=bsar; m=row-512; mdst=m+256; }
    else {
        W=W1; ws=g_ws1; wb=g_wb1v; Ah=g_A1; gg=gffn; bb=bffn; m=row-768;
        extra = b1[m];
        if (m < FH) mdst = ((m>>3)<<4) + (m&7);
        else        { int mm = m-FH; mdst = ((mm>>3)<<4) + (mm&7) + 8; }
    }
    float w  = W[m*CC + c];
    float wg = w * gg[c];
    u32 hu = (u32)__half_as_ushort(__float2half_rn(wg));
    u32 hp = __shfl_xor_sync(0xffffffffu, hu, 1);
    if (!(c & 1)) Ah[mdst*128 + (c>>1)] = hu | (hp << 16);
    __shared__ float s1[256], s2[256];
    s1[c] = wg; s2[c] = w * bb[c];
    __syncthreads();
    for (int off = 128; off > 0; off >>= 1) {
        if (c < off) { s1[c] += s1[c+off]; s2[c] += s2[c+off]; }
        __syncthreads();
    }
    if (c == 0) { ws[mdst] = s1[0]; wb[mdst] = s2[0] + extra; }
}

__global__ void prep_plain(const float* __restrict__ W, u32* __restrict__ Ah, int K)
{
    int m = blockIdx.x, c0 = threadIdx.x;
    for (int k0 = 0; k0 < K; k0 += 256) {
        int c = k0 + c0;
        float w = W[(size_t)m*K + c];
        u32 hu = (u32)__half_as_ushort(__float2half_rn(w));
        u32 hp = __shfl_xor_sync(0xffffffffu, hu, 1);
        if (!(c0 & 1)) Ah[(size_t)m*(K/2) + (c>>1)] = hu | (hp << 16);
    }
}

// ---------------------------------------------------------------------------
// LN stats + fp16 conversion (4 threads / pixel-pair)
// ---------------------------------------------------------------------------
__global__ __launch_bounds__(512)
void ln_conv_kernel(const float* __restrict__ x,
                    float* __restrict__ mu, float* __restrict__ rs,
                    u32* __restrict__ x16)
{
    __shared__ float ssx[512], ssx2[512], ssy[512], ssy2[512];
    int tid = threadIdx.x;
    int pr = tid & 127, qd = tid >> 7;
    int p2 = blockIdx.x*128 + pr;
    int b = p2 >> 11, l2 = p2 & 2047;
    const float* base = x + (size_t)b*CC*LL + 2*l2;
    u32* oh = x16 + (size_t)b*CC*(LL/2) + l2;
    float sx=0.f, sx2=0.f, sy=0.f, sy2=0.f;
    int c0 = qd*64;
#pragma unroll 8
    for (int i = 0; i < 64; i++) {
        int c = c0 + i;
        float2 v = *(const float2*)(base + (size_t)c*LL);
        sx += v.x; sx2 = fmaf(v.x, v.x, sx2);
        sy += v.y; sy2 = fmaf(v.y, v.y, sy2);
        oh[(size_t)c*(LL/2)] = packf16(v.x, v.y);
    }
    ssx[tid]=sx; ssx2[tid]=sx2; ssy[tid]=sy; ssy2[tid]=sy2;
    __syncthreads();
    if (qd == 0) {
        float tx  = ssx[pr]  + ssx[pr+128]  + ssx[pr+256]  + ssx[pr+384];
        float tx2 = ssx2[pr] + ssx2[pr+128] + ssx2[pr+256] + ssx2[pr+384];
        float ty  = ssy[pr]  + ssy[pr+128]  + ssy[pr+256]  + ssy[pr+384];
        float ty2 = ssy2[pr] + ssy2[pr+128] + ssy2[pr+256] + ssy2[pr+384];
        float mx = tx*(1.f/CC), my = ty*(1.f/CC);
        int p = b*LL + 2*l2;
        mu[p]   = mx; rs[p]   = rsqrtf(fmaf(-mx, mx, tx2*(1.f/CC)) + 1e-5f);
        mu[p+1] = my; rs[p+1] = rsqrtf(fmaf(-my, my, ty2*(1.f/CC)) + 1e-5f);
    }
}

// ---------------------------------------------------------------------------
// Single-term fp16 GEMM, cp.async 2-stage, 2 CTAs/SM. CTA 128x128, K chunk 32.
// MODE 0: LN epilogue -> packed fp16 Y16 [m][L/2]
// MODE 1: +res -> fp32 ; MODE 2: +bias +res -> fp32 ; MODE 3: gate -> g_hg fp16
// ---------------------------------------------------------------------------
#define A_STR 80
#define B_STR 272
#define AS_A  0
#define BS_B  10240
#define STAGE 18944
#define GSMEM (2*STAGE)

template<int MODE, int KD, int MD>
__global__ __launch_bounds__(256, 2)
void gemm_mma(const u32* __restrict__ Ah,
              const u32* __restrict__ Xp,
              void* __restrict__ Yv,
              const float* __restrict__ mu, const float* __restrict__ rs,
              const float* __restrict__ wsum, const float* __restrict__ wb,
              const float* __restrict__ res, const float* __restrict__ bias)
{
    extern __shared__ __align__(128) char smem[];
    const u32 sbase = smem_u32(smem);

    int tid = threadIdx.x, lane = tid & 31, wid = tid >> 5;
    int n0 = blockIdx.x * 128, m0 = blockIdx.y * 128, b = blockIdx.z;
    int wm = wid >> 2, wn = wid & 3;

    float acc[4][4][4];
#pragma unroll
    for (int i=0;i<4;i++)
#pragma unroll
        for (int j=0;j<4;j++)
#pragma unroll
            for (int r=0;r<4;r++) acc[i][j][r]=0.f;

    // cp.async mapping: A 512 x 16B -> 2/thread ; B 512 x 16B -> 2/thread
    int ia0 = tid, ia1 = tid + 256;
    int ar0 = ia0 >> 2, ap0 = (ia0 & 3) * 4;
    int ar1 = ia1 >> 2, ap1 = (ia1 & 3) * 4;
    int br0 = ia0 >> 4, bc0 = (ia0 & 15) * 4;
    int br1 = ia1 >> 4, bc1 = (ia1 & 15) * 4;
    const u32* srcA0 = Ah + (size_t)(m0+ar0)*(KD/2) + ap0;
    const u32* srcA1 = Ah + (size_t)(m0+ar1)*(KD/2) + ap1;
    const u32* Xb = Xp + (size_t)b*KD*(LL/2) + (n0>>1);
    const u32* srcB0 = Xb + (size_t)br0*(LL/2) + bc0;
    const u32* srcB1 = Xb + (size_t)br1*(LL/2) + bc1;
    u32 dA0 = sbase + AS_A + (u32)(ar0*A_STR + ap0*4);
    u32 dA1 = sbase + AS_A + (u32)(ar1*A_STR + ap1*4);
    u32 dB0 = sbase + BS_B + (u32)(br0*B_STR + bc0*4);
    u32 dB1 = sbase + BS_B + (u32)(br1*B_STR + bc1*4);

    u32 a_lm_base = sbase + (u32)((wm*64 + (lane & 15)) * A_STR) + ((lane & 16) ? 16u : 0u);
    u32 b_lm_base = sbase + BS_B + (u32)((lane & 15) * B_STR)
                  + (u32)((wn*32 + ((lane & 16) ? 8 : 0)) * 2);

#define ISSUE(st, kc) do { \
        u32 so = (u32)((st)*STAGE); \
        int ko2 = (kc) >> 1; size_t kb = (size_t)(kc)*(LL/2); \
        CP16(dA0+so, srcA0+ko2); CP16(dA1+so, srcA1+ko2); \
        CP16(dB0+so, srcB0+kb);  CP16(dB1+so, srcB1+kb); \
        CP_COMMIT(); \
    } while(0)

    ISSUE(0, 0);

#pragma unroll 1
    for (int kc = 0; kc < KD; kc += 32) {
        int cur = (kc >> 5) & 1;
        if (kc + 32 < KD) {
            ISSUE(cur ^ 1, kc + 32);
            CP_WAIT(1);
        } else {
            CP_WAIT(0);
        }
        __syncthreads();
        u32 so = (u32)(cur * STAGE);
#pragma unroll
        for (int ks = 0; ks < 32; ks += 16) {
            u32 af[4][4], bf[4][2];
            u32 ab = a_lm_base + so + (u32)(ks*2);
#pragma unroll
            for (int i = 0; i < 4; i++)
                LDSM_X4(af[i][0], af[i][1], af[i][2], af[i][3], ab + (u32)(i*16*A_STR));
            u32 bb0 = b_lm_base + so + (u32)(ks*B_STR);
#pragma unroll
            for (int j2 = 0; j2 < 2; j2++)
                LDSM_X4_T(bf[j2*2][0], bf[j2*2][1], bf[j2*2+1][0], bf[j2*2+1][1], bb0 + (u32)(j2*32));
#pragma unroll
            for (int i = 0; i < 4; i++)
#pragma unroll
                for (int j = 0; j < 4; j++)
                    MMA_F16(acc[i][j], af[i], bf[j][0], bf[j][1]);
        }
        __syncthreads();
    }
#undef ISSUE

    // ---- epilogue
    float* Y = (float*)Yv;
    u32* Y16 = (u32*)Yv;
#pragma unroll
    for (int i = 0; i < 4; i++) {
        int r0 = m0 + wm*64 + i*16 + (lane >> 2);
        int r1 = r0 + 8;
        if (MODE == 3) {
            int t = ((r0 >> 4) << 3) + (r0 & 7);
            float ws1 = wsum[r0], wb1 = wb[r0];
            float ws2 = wsum[r1], wb2 = wb[r1];
#pragma unroll
            for (int j = 0; j < 4; j++) {
                int c0 = n0 + wn*32 + j*8 + 2*(lane & 3);
                int p0 = b*LL + c0;
                float2 m2 = *(const float2*)(mu + p0);
                float2 s2 = *(const float2*)(rs + p0);
                float e1x = s2.x*(acc[i][j][0] - m2.x*ws1) + wb1;
                float e1y = s2.y*(acc[i][j][1] - m2.y*ws1) + wb1;
                float e2x = s2.x*(acc[i][j][2] - m2.x*ws2) + wb2;
                float e2y = s2.y*(acc[i][j][3] - m2.y*ws2) + wb2;
                g_hg[((size_t)b*FH + t)*(LL/2) + (c0 >> 1)] = packf16(e1x*e2x, e1y*e2y);
            }
            continue;
        }
        if (MODE == 0) {
            float ws0 = wsum[r0], wb0 = wb[r0];
            float ws1v = wsum[r1], wb1 = wb[r1];
#pragma unroll
            for (int j = 0; j < 4; j++) {
                int c0 = n0 + wn*32 + j*8 + 2*(lane & 3);
                int p0 = b*LL + c0;
                float2 m2 = *(const float2*)(mu + p0);
                float2 s2 = *(const float2*)(rs + p0);
                float o0x = s2.x*(acc[i][j][0] - m2.x*ws0) + wb0;
                float o0y = s2.y*(acc[i][j][1] - m2.y*ws0) + wb0;
                float o1x = s2.x*(acc[i][j][2] - m2.x*ws1v) + wb1;
                float o1y = s2.y*(acc[i][j][3] - m2.y*ws1v) + wb1;
                Y16[((size_t)b*MD + r0)*(LL/2) + (c0>>1)] = packf16(o0x, o0y);
                Y16[((size_t)b*MD + r1)*(LL/2) + (c0>>1)] = packf16(o1x, o1y);
            }
            continue;
        }
        float bv0 = 0.f, bv1 = 0.f;
        if (MODE == 2) { bv0 = bias[r0]; bv1 = bias[r1]; }
#pragma unroll
        for (int j = 0; j < 4; j++) {
            int c0 = n0 + wn*32 + j*8 + 2*(lane & 3);
            const float* q0 = res + (size_t)b*MD*LL + (size_t)r0*LL + c0;
            const float* q1 = res + (size_t)b*MD*LL + (size_t)r1*LL + c0;
            float2 a0 = *(const float2*)q0, a1 = *(const float2*)q1;
            float* y0 = Y + (size_t)b*MD*LL + (size_t)r0*LL + c0;
            float* y1 = Y + (size_t)b*MD*LL + (size_t)r1*LL + c0;
            *(float2*)y0 = make_float2(acc[i][j][0] + bv0 + a0.x, acc[i][j][1] + bv0 + a0.y);
            *(float2*)y1 = make_float2(acc[i][j][2] + bv1 + a1.x, acc[i][j][3] + bv1 + a1.y);
        }
    }
}

// ---------------------------------------------------------------------------
// Attention (fp16 q/k/v, fp32 accumulate)
// ---------------------------------------------------------------------------
__global__ __launch_bounds__(128)
void attn_s_kernel()
{
    __shared__ float qs[HCC][129];
    __shared__ float ks[HCC][129];
    int bh = blockIdx.x, sp = blockIdx.y;
    int b = bh >> 3, h = bh & 7;
    int l0 = sp * 128;
    int tid = threadIdx.x;
    const u32* qp = g_q16  + ((size_t)b*CC   + h*HCC)*(LL/2) + (l0>>1);
    const u32* kp = g_kv16 + ((size_t)b*2*CC + h*HCC)*(LL/2) + (l0>>1);
    for (int idx = tid; idx < HCC*64; idx += 128) {
        int r = idx >> 6, ci = idx & 63;
        float2 qv = unpackf16(qp[(size_t)r*(LL/2) + ci]);
        float2 kv = unpackf16(kp[(size_t)r*(LL/2) + ci]);
        qs[r][2*ci] = qv.x; qs[r][2*ci+1] = qv.y;
        ks[r][2*ci] = kv.x; ks[r][2*ci+1] = kv.y;
    }
    __syncthreads();
    int d2 = tid & 15, cy = tid >> 4;
    float acc[2][4] = {{0.f,0.f,0.f,0.f},{0.f,0.f,0.f,0.f}};
#pragma unroll 4
    for (int l = 0; l < 128; l++) {
        float k0v = ks[2*d2][l], k1v = ks[2*d2+1][l];
#pragma unroll
        for (int i = 0; i < 4; i++) {
            float qv = qs[cy + 8*i][l];
            acc[0][i] = fmaf(qv, k0v, acc[0][i]);
            acc[1][i] = fmaf(qv, k1v, acc[1][i]);
        }
    }
    float* out = g_Sp + ((size_t)bh*NSPLIT + sp)*1024;
#pragma unroll
    for (int i = 0; i < 4; i++) {
        int c = cy + 8*i;
        out[c*32 + 2*d2]   = acc[0][i];
        out[c*32 + 2*d2+1] = acc[1][i];
    }
}

__global__ void attn_softmax_kernel()
{
    int bh = blockIdx.x, t = threadIdx.x;
    float s = 0.f;
    const float* sp = g_Sp + (size_t)bh*NSPLIT*1024 + t;
#pragma unroll
    for (int i = 0; i < NSPLIT; i++) s += sp[(size_t)i*1024];
    s *= 0.17677669529663687f;
    float mx = s;
#pragma unroll
    for (int o = 16; o > 0; o >>= 1) mx = fmaxf(mx, __shfl_xor_sync(0xffffffffu, mx, o));
    float e = expf(s - mx);
    float sum = e;
#pragma unroll
    for (int o = 16; o > 0; o >>= 1) sum += __shfl_xor_sync(0xffffffffu, sum, o);
    g_A[(size_t)bh*1024 + t] = e / sum;
}

__global__ __launch_bounds__(256)
void attn_av_kernel()
{
    __shared__ float As[1024];
    int bh = blockIdx.x;
    int b = bh >> 3, h = bh & 7;
    int tid = threadIdx.x;
#pragma unroll
    for (int i = 0; i < 4; i++) As[tid + 256*i] = g_A[(size_t)bh*1024 + tid + 256*i];
    __syncthreads();
    int c2 = blockIdx.y*256 + tid;
    const u32* vp = g_kv16 + ((size_t)b*2*CC + CC + h*HCC)*(LL/2) + c2;
    float acc0[32], acc1[32];
#pragma unroll
    for (int c = 0; c < 32; c++) { acc0[c]=0.f; acc1[c]=0.f; }
#pragma unroll 4
    for (int d = 0; d < 32; d++) {
        float2 v = unpackf16(vp[(size_t)d*(LL/2)]);
#pragma unroll
        for (int c = 0; c < 32; c++) {
            float a = As[c*32+d];
            acc0[c] = fmaf(a, v.x, acc0[c]);
            acc1[c] = fmaf(a, v.y, acc1[c]);
        }
    }
#pragma unroll
    for (int c = 0; c < 32; c++) {
        g_a16[((size_t)b*CC + h*HCC + c)*(LL/2) + c2] = packf16(acc0[c], acc1[c]);
    }
}

// ---------------------------------------------------------------------------
// Launcher
// ---------------------------------------------------------------------------
extern "C" void kernel_launch(void* const* d_in, const int* in_sizes, int n_in,
                              void* d_out, int out_size)
{
    (void)in_sizes; (void)n_in; (void)out_size;
    const float* optical = (const float*)d_in[0];
    const float* sar     = (const float*)d_in[1];
    const float* gopt    = (const float*)d_in[2];
    const float* bopt    = (const float*)d_in[3];
    const float* gsar    = (const float*)d_in[4];
    const float* bsar    = (const float*)d_in[5];
    const float* Wq      = (const float*)d_in[6];
    const float* Wk      = (const float*)d_in[7];
    const float* Wv      = (const float*)d_in[8];
    const float* Wo      = (const float*)d_in[9];
    const float* gffn    = (const float*)d_in[10];
    const float* bffn    = (const float*)d_in[11];
    const float* W1      = (const float*)d_in[12];
    const float* b1      = (const float*)d_in[13];
    const float* W2      = (const float*)d_in[14];
    const float* b2      = (const float*)d_in[15];
    float* out = (float*)d_out;

    float *p_wsq,*p_wbq,*p_wskv,*p_wbkv,*p_ws1,*p_wb1;
    float *p_mu_o,*p_rs_o,*p_mu_s,*p_rs_s,*p_mu_x,*p_rs_x;
    float *p_x;
    u32 *p_Aq,*p_Akv,*p_A1,*p_Ao,*p_A2;
    u32 *p_o16,*p_s16,*p_q16,*p_kv16,*p_a16,*p_x16,*p_hg;
    cudaGetSymbolAddress((void**)&p_wsq, g_wsq);     cudaGetSymbolAddress((void**)&p_wbq, g_wbq);
    cudaGetSymbolAddress((void**)&p_wskv, g_wskv);   cudaGetSymbolAddress((void**)&p_wbkv, g_wbkv);
    cudaGetSymbolAddress((void**)&p_ws1, g_ws1);     cudaGetSymbolAddress((void**)&p_wb1, g_wb1v);
    cudaGetSymbolAddress((void**)&p_mu_o, g_mu_o);   cudaGetSymbolAddress((void**)&p_rs_o, g_rs_o);
    cudaGetSymbolAddress((void**)&p_mu_s, g_mu_s);   cudaGetSymbolAddress((void**)&p_rs_s, g_rs_s);
    cudaGetSymbolAddress((void**)&p_mu_x, g_mu_x);   cudaGetSymbolAddress((void**)&p_rs_x, g_rs_x);
    cudaGetSymbolAddress((void**)&p_x, g_x);
    cudaGetSymbolAddress((void**)&p_o16, g_o16);     cudaGetSymbolAddress((void**)&p_s16, g_s16);
    cudaGetSymbolAddress((void**)&p_q16, g_q16);     cudaGetSymbolAddress((void**)&p_kv16, g_kv16);
    cudaGetSymbolAddress((void**)&p_a16, g_a16);     cudaGetSymbolAddress((void**)&p_x16, g_x16);
    cudaGetSymbolAddress((void**)&p_hg, g_hg);
    cudaGetSymbolAddress((void**)&p_Aq, g_Aq);       cudaGetSymbolAddress((void**)&p_Akv, g_Akv);
    cudaGetSymbolAddress((void**)&p_A1, g_A1);       cudaGetSymbolAddress((void**)&p_Ao, g_Ao);
    cudaGetSymbolAddress((void**)&p_A2, g_A2);

    cudaFuncSetAttribute(gemm_mma<0,256,256>, cudaFuncAttributeMaxDynamicSharedMemorySize, GSMEM);
    cudaFuncSetAttribute(gemm_mma<0,256,512>, cudaFuncAttributeMaxDynamicSharedMemorySize, GSMEM);
    cudaFuncSetAttribute(gemm_mma<1,256,256>, cudaFuncAttributeMaxDynamicSharedMemorySize, GSMEM);
    cudaFuncSetAttribute(gemm_mma<2,512,256>, cudaFuncAttributeMaxDynamicSharedMemorySize, GSMEM);
    cudaFuncSetAttribute(gemm_mma<3,256,FH>,  cudaFuncAttributeMaxDynamicSharedMemorySize, GSMEM);

    // 1) weight prep
    prep_fold<<<1792, 256>>>(Wq, Wk, Wv, W1, gopt, bopt, gsar, bsar, gffn, bffn, b1);
    prep_plain<<<256, 256>>>(Wo, p_Ao, 256);
    prep_plain<<<256, 256>>>(W2, p_A2, 512);

    // 2) LN stats + fp16 conversion
    ln_conv_kernel<<<(NPIX/2)/128, 512>>>(optical, p_mu_o, p_rs_o, p_o16);
    ln_conv_kernel<<<(NPIX/2)/128, 512>>>(sar,     p_mu_s, p_rs_s, p_s16);

    // 3) Q projection + fused K/V projection -> fp16
    dim3 gp(LL/128, CC/128, BB);
    dim3 gkv(LL/128, 2*CC/128, BB);
    gemm_mma<0,256,256><<<gp, 256,GSMEM>>>(p_Aq,  p_o16, p_q16,  p_mu_o, p_rs_o, p_wsq,  p_wbq,  0, 0);
    gemm_mma<0,256,512><<<gkv,256,GSMEM>>>(p_Akv, p_s16, p_kv16, p_mu_s, p_rs_s, p_wskv, p_wbkv, 0, 0);

    // 4) channel attention -> fp16 attn
    attn_s_kernel<<<dim3(BB*NHH, NSPLIT), 128>>>();
    attn_softmax_kernel<<<BB*NHH, 1024>>>();
    attn_av_kernel<<<dim3(BB*NHH, (LL/2)/256), 256>>>();

    // 5) Wo + residual -> x (fp32)
    gemm_mma<1,256,256><<<gp,256,GSMEM>>>(p_Ao, p_a16, p_x, 0, 0, 0, 0, optical, 0);

    // 6) LN stats + fp16 conversion on x
    ln_conv_kernel<<<(NPIX/2)/128, 512>>>(p_x, p_mu_x, p_rs_x, p_x16);

    // 7) W1 (LN+b1 folded, row-paired) + fused SimpleGate -> hg (fp16)
    dim3 gp1(LL/128, FH2/128, BB);
    gemm_mma<3,256,FH><<<gp1,256,GSMEM>>>(p_A1, p_x16, (void*)0, p_mu_x, p_rs_x, p_ws1, p_wb1, 0, 0);

    // 8) W2 + b2 + residual -> out
    gemm_mma<2,512,256><<<gp,256,GSMEM>>>(p_A2, p_hg, out, 0, 0, 0, 0, p_x, b2);
}

// round 8
// speedup vs baseline: 4.7243x; 1.0332x over previous
#include <cuda_runtime.h>
#include <cuda_fp16.h>

typedef unsigned int u32;
typedef unsigned long long u64;

#define BB   16
#define CC   256
#define LL   4096
#define NHH  8
#define HCC  32
#define FH   512
#define FH2  1024
#define NPIX (BB*LL)

// ---------------------------------------------------------------------------
// Scratch
// ---------------------------------------------------------------------------
__device__ float g_wsq[CC],  g_wbq[CC];
__device__ float g_wskv[2*CC], g_wbkv[2*CC];
__device__ float g_ws1[FH2], g_wb1v[FH2];      // permuted order
__device__ float g_mu_o[NPIX], g_rs_o[NPIX];
__device__ float g_mu_s[NPIX], g_rs_s[NPIX];
__device__ float g_mu_x[NPIX], g_rs_x[NPIX];
// weights: packed fp16x2 (k even in low 16) == fp16[M][K] row-major
__device__ __align__(128) u32 g_Aq[CC*128];
__device__ __align__(128) u32 g_Akv[2*CC*128];   // Wk rows 0-255, Wv 256-511
__device__ __align__(128) u32 g_A1[FH2*128];     // permuted rows
__device__ __align__(128) u32 g_Ao[CC*128];
__device__ __align__(128) u32 g_A2[CC*256];
// fp32 activations (residual path)
__device__ __align__(128) float g_x[BB*CC*LL];
// fp16 activations, packed u32 [C][L/2] per batch
__device__ __align__(128) u32 g_o16[BB*CC*(LL/2)];
__device__ __align__(128) u32 g_s16[BB*CC*(LL/2)];
__device__ __align__(128) u32 g_q16[BB*CC*(LL/2)];
__device__ __align__(128) u32 g_kv16[BB*2*CC*(LL/2)];  // k rows 0-255, v 256-511
__device__ __align__(128) u32 g_a16[BB*CC*(LL/2)];
__device__ __align__(128) u32 g_x16[BB*CC*(LL/2)];
__device__ __align__(128) u32 g_hg[BB*FH*(LL/2)];
__device__ __align__(128) float g_A[BB*NHH*HCC*HCC];

// ---------------------------------------------------------------------------
// PTX helpers
// ---------------------------------------------------------------------------
__device__ __forceinline__ u32 smem_u32(const void* p) {
    u32 a;
    asm("{ .reg .u64 t; cvta.to.shared.u64 t, %1; cvt.u32.u64 %0, t; }" : "=r"(a) : "l"(p));
    return a;
}
#define LDSM_X4(r0,r1,r2,r3,addr) \
    asm volatile("ldmatrix.sync.aligned.m8n8.x4.shared.b16 {%0,%1,%2,%3}, [%4];" \
        : "=r"(r0),"=r"(r1),"=r"(r2),"=r"(r3) : "r"(addr))
#define LDSM_X4_T(r0,r1,r2,r3,addr) \
    asm volatile("ldmatrix.sync.aligned.m8n8.x4.trans.shared.b16 {%0,%1,%2,%3}, [%4];" \
        : "=r"(r0),"=r"(r1),"=r"(r2),"=r"(r3) : "r"(addr))
#define MMA_F16(d, a, b0, b1) \
    asm volatile("mma.sync.aligned.m16n8k16.row.col.f32.f16.f16.f32 " \
        "{%0,%1,%2,%3}, {%4,%5,%6,%7}, {%8,%9}, {%0,%1,%2,%3};" \
        : "+f"((d)[0]),"+f"((d)[1]),"+f"((d)[2]),"+f"((d)[3]) \
        : "r"((a)[0]),"r"((a)[1]),"r"((a)[2]),"r"((a)[3]), "r"(b0),"r"(b1))
#define CP16(dst, src) \
    asm volatile("cp.async.cg.shared.global [%0], [%1], 16;" \
        :: "r"(dst), "l"(src) : "memory")
#define CP_COMMIT() asm volatile("cp.async.commit_group;" ::: "memory")
#define CP_WAIT(n)  asm volatile("cp.async.wait_group %0;" :: "n"(n) : "memory")

__device__ __forceinline__ u32 packf16(float a, float b) {
    __half2 h = __floats2half2_rn(a, b);
    return *(u32*)&h;
}
__device__ __forceinline__ float2 unpackf16(u32 w) {
    __half2 h = *(__half2*)&w;
    return __half22float2(h);
}

// ---------------------------------------------------------------------------
// Prep
// ---------------------------------------------------------------------------
__global__ void prep_fold(const float* __restrict__ Wq, const float* __restrict__ Wk,
                          const float* __restrict__ Wv, const float* __restrict__ W1,
                          const float* __restrict__ gopt, const float* __restrict__ bopt,
                          const float* __restrict__ gsar, const float* __restrict__ bsar,
                          const float* __restrict__ gffn, const float* __restrict__ bffn,
                          const float* __restrict__ b1)
{
    int row = blockIdx.x;
    int c   = threadIdx.x;
    const float* W; float* ws; float* wb; u32* Ah;
    const float* gg; const float* bb; int m, mdst; float extra = 0.f;
    if (row < 256)      { W=Wq; ws=g_wsq;  wb=g_wbq;  Ah=g_Aq;  gg=gopt; bb=bopt; m=row;     mdst=m; }
    else if (row < 512) { W=Wk; ws=g_wskv; wb=g_wbkv; Ah=g_Akv; gg=gsar; bb=bsar; m=row-256; mdst=m; }
    else if (row < 768) { W=Wv; ws=g_wskv; wb=g_wbkv; Ah=g_Akv; gg=gsar; bb=bsar; m=row-512; mdst=m+256; }
    else {
        W=W1; ws=g_ws1; wb=g_wb1v; Ah=g_A1; gg=gffn; bb=bffn; m=row-768;
        extra = b1[m];
        if (m < FH) mdst = ((m>>3)<<4) + (m&7);
        else        { int mm = m-FH; mdst = ((mm>>3)<<4) + (mm&7) + 8; }
    }
    float w  = W[m*CC + c];
    float wg = w * gg[c];
    u32 hu = (u32)__half_as_ushort(__float2half_rn(wg));
    u32 hp = __shfl_xor_sync(0xffffffffu, hu, 1);
    if (!(c & 1)) Ah[mdst*128 + (c>>1)] = hu | (hp << 16);
    __shared__ float s1[256], s2[256];
    s1[c] = wg; s2[c] = w * bb[c];
    __syncthreads();
    for (int off = 128; off > 0; off >>= 1) {
        if (c < off) { s1[c] += s1[c+off]; s2[c] += s2[c+off]; }
        __syncthreads();
    }
    if (c == 0) { ws[mdst] = s1[0]; wb[mdst] = s2[0] + extra; }
}

__global__ void prep_plain(const float* __restrict__ W, u32* __restrict__ Ah, int K)
{
    int m = blockIdx.x, c0 = threadIdx.x;
    for (int k0 = 0; k0 < K; k0 += 256) {
        int c = k0 + c0;
        float w = W[(size_t)m*K + c];
        u32 hu = (u32)__half_as_ushort(__float2half_rn(w));
        u32 hp = __shfl_xor_sync(0xffffffffu, hu, 1);
        if (!(c0 & 1)) Ah[(size_t)m*(K/2) + (c>>1)] = hu | (hp << 16);
    }
}

// ---------------------------------------------------------------------------
// LN stats + fp16 conversion (inputs only; x handled in MODE4 GEMM epilogue)
// ---------------------------------------------------------------------------
__global__ __launch_bounds__(512)
void ln_conv_kernel(const float* __restrict__ x,
                    float* __restrict__ mu, float* __restrict__ rs,
                    u32* __restrict__ x16)
{
    __shared__ float ssx[512], ssx2[512], ssy[512], ssy2[512];
    int tid = threadIdx.x;
    int pr = tid & 127, qd = tid >> 7;
    int p2 = blockIdx.x*128 + pr;
    int b = p2 >> 11, l2 = p2 & 2047;
    const float* base = x + (size_t)b*CC*LL + 2*l2;
    u32* oh = x16 + (size_t)b*CC*(LL/2) + l2;
    float sx=0.f, sx2=0.f, sy=0.f, sy2=0.f;
    int c0 = qd*64;
#pragma unroll 8
    for (int i = 0; i < 64; i++) {
        int c = c0 + i;
        float2 v = *(const float2*)(base + (size_t)c*LL);
        sx += v.x; sx2 = fmaf(v.x, v.x, sx2);
        sy += v.y; sy2 = fmaf(v.y, v.y, sy2);
        oh[(size_t)c*(LL/2)] = packf16(v.x, v.y);
    }
    ssx[tid]=sx; ssx2[tid]=sx2; ssy[tid]=sy; ssy2[tid]=sy2;
    __syncthreads();
    if (qd == 0) {
        float tx  = ssx[pr]  + ssx[pr+128]  + ssx[pr+256]  + ssx[pr+384];
        float tx2 = ssx2[pr] + ssx2[pr+128] + ssx2[pr+256] + ssx2[pr+384];
        float ty  = ssy[pr]  + ssy[pr+128]  + ssy[pr+256]  + ssy[pr+384];
        float ty2 = ssy2[pr] + ssy2[pr+128] + ssy2[pr+256] + ssy2[pr+384];
        float mx = tx*(1.f/CC), my = ty*(1.f/CC);
        int p = b*LL + 2*l2;
        mu[p]   = mx; rs[p]   = rsqrtf(fmaf(-mx, mx, tx2*(1.f/CC)) + 1e-5f);
        mu[p+1] = my; rs[p+1] = rsqrtf(fmaf(-my, my, ty2*(1.f/CC)) + 1e-5f);
    }
}

// ---------------------------------------------------------------------------
// Single-fp16 GEMM, cp.async 2-stage, K chunk 64, 2 CTAs/SM.
// Template: MODE, KD, MD, MT(rows/CTA), NT(cols/CTA).
// MODE 0: LN epilogue -> fp16 Y16 ; 2: +bias +res -> fp32
// MODE 3: gate -> g_hg fp16 ; MODE 4: +res -> g_x fp32 + g_x16 + LN stats
// ---------------------------------------------------------------------------
#define A_STR 144

template<int MODE, int KD, int MD, int MT, int NT>
__global__ __launch_bounds__(256, 2)
void gemm_mma(const u32* __restrict__ Ah,
              const u32* __restrict__ Xp,
              void* __restrict__ Yv,
              const float* __restrict__ mu, const float* __restrict__ rs,
              const float* __restrict__ wsum, const float* __restrict__ wb,
              const float* __restrict__ res, const float* __restrict__ bias)
{
    constexpr int B_STRc = NT*2 + 16;
    constexpr int BS = MT*A_STR;
    constexpr int STAGE = MT*A_STR + 64*B_STRc;
    constexpr int WN = (MT == 128) ? 4 : 2;   // warps along N
    constexpr int BSEG = NT/8;                // 16B segs per B row

    extern __shared__ __align__(128) char smem[];
    const u32 sbase = smem_u32(smem);

    int tid = threadIdx.x, lane = tid & 31, wid = tid >> 5;
    int n0 = blockIdx.x * NT, m0 = blockIdx.y * MT, b = blockIdx.z;
    int wm = wid / WN, wn = wid % WN;

    float acc[4][4][4];
#pragma unroll
    for (int i=0;i<4;i++)
#pragma unroll
        for (int j=0;j<4;j++)
#pragma unroll
            for (int r=0;r<4;r++) acc[i][j][r]=0.f;

    const u32* Xb = Xp + (size_t)b*KD*(LL/2) + (n0>>1);

    u32 a_lm_base = sbase + (u32)((wm*64 + (lane & 15)) * A_STR) + ((lane & 16) ? 16u : 0u);
    u32 b_lm_base = sbase + BS + (u32)((lane & 15) * B_STRc)
                  + (u32)((wn*32 + ((lane & 16) ? 8 : 0)) * 2);

#define ISSUE(st, kc) do { \
        u32 so = sbase + (u32)((st)*STAGE); \
        _Pragma("unroll") \
        for (int ii = tid; ii < MT*8; ii += 256) { \
            int row = ii >> 3, seg = ii & 7; \
            CP16(so + (u32)(row*A_STR + seg*16), \
                 Ah + (size_t)(m0+row)*(KD/2) + ((kc)>>1) + seg*4); \
        } \
        _Pragma("unroll") \
        for (int ii = tid; ii < 64*BSEG; ii += 256) { \
            int row = ii / BSEG, seg = ii % BSEG; \
            CP16(so + (u32)(BS + row*B_STRc + seg*16), \
                 Xb + (size_t)((kc)+row)*(LL/2) + seg*4); \
        } \
        CP_COMMIT(); \
    } while(0)

    ISSUE(0, 0);

#pragma unroll 1
    for (int kc = 0; kc < KD; kc += 64) {
        int cur = (kc >> 6) & 1;
        if (kc + 64 < KD) {
            ISSUE(cur ^ 1, kc + 64);
            CP_WAIT(1);
        } else {
            CP_WAIT(0);
        }
        __syncthreads();
        u32 so = (u32)(cur * STAGE);
#pragma unroll
        for (int ks = 0; ks < 64; ks += 16) {
            u32 af[4][4], bf[4][2];
            u32 ab = a_lm_base + so + (u32)(ks*2);
#pragma unroll
            for (int i = 0; i < 4; i++)
                LDSM_X4(af[i][0], af[i][1], af[i][2], af[i][3], ab + (u32)(i*16*A_STR));
            u32 bb0 = b_lm_base + so + (u32)(ks*B_STRc);
#pragma unroll
            for (int j2 = 0; j2 < 2; j2++)
                LDSM_X4_T(bf[j2*2][0], bf[j2*2][1], bf[j2*2+1][0], bf[j2*2+1][1], bb0 + (u32)(j2*32));
#pragma unroll
            for (int i = 0; i < 4; i++)
#pragma unroll
                for (int j = 0; j < 4; j++)
                    MMA_F16(acc[i][j], af[i], bf[j][0], bf[j][1]);
        }
        __syncthreads();
    }
#undef ISSUE

    // ---- epilogue
    float* Y = (float*)Yv;
    u32* Y16 = (u32*)Yv;
    float cs[4][4];
    if (MODE == 4) {
#pragma unroll
        for (int j=0;j<4;j++)
#pragma unroll
            for (int k=0;k<4;k++) cs[j][k]=0.f;
    }
#pragma unroll
    for (int i = 0; i < 4; i++) {
        int r0 = m0 + wm*64 + i*16 + (lane >> 2);
        int r1 = r0 + 8;
        if (MODE == 3) {
            int t = ((r0 >> 4) << 3) + (r0 & 7);
            float ws1 = wsum[r0], wb1 = wb[r0];
            float ws2 = wsum[r1], wb2 = wb[r1];
#pragma unroll
            for (int j = 0; j < 4; j++) {
                int c0 = n0 + wn*32 + j*8 + 2*(lane & 3);
                int p0 = b*LL + c0;
                float2 m2 = *(const float2*)(mu + p0);
                float2 s2 = *(const float2*)(rs + p0);
                float e1x = s2.x*(acc[i][j][0] - m2.x*ws1) + wb1;
                float e1y = s2.y*(acc[i][j][1] - m2.y*ws1) + wb1;
                float e2x = s2.x*(acc[i][j][2] - m2.x*ws2) + wb2;
                float e2y = s2.y*(acc[i][j][3] - m2.y*ws2) + wb2;
                g_hg[((size_t)b*FH + t)*(LL/2) + (c0 >> 1)] = packf16(e1x*e2x, e1y*e2y);
            }
        } else if (MODE == 0) {
            float ws0 = wsum[r0], wb0 = wb[r0];
            float ws1v = wsum[r1], wb1 = wb[r1];
#pragma unroll
            for (int j = 0; j < 4; j++) {
                int c0 = n0 + wn*32 + j*8 + 2*(lane & 3);
                int p0 = b*LL + c0;
                float2 m2 = *(const float2*)(mu + p0);
                float2 s2 = *(const float2*)(rs + p0);
                float o0x = s2.x*(acc[i][j][0] - m2.x*ws0) + wb0;
                float o0y = s2.y*(acc[i][j][1] - m2.y*ws0) + wb0;
                float o1x = s2.x*(acc[i][j][2] - m2.x*ws1v) + wb1;
                float o1y = s2.y*(acc[i][j][3] - m2.y*ws1v) + wb1;
                Y16[((size_t)b*MD + r0)*(LL/2) + (c0>>1)] = packf16(o0x, o0y);
                Y16[((size_t)b*MD + r1)*(LL/2) + (c0>>1)] = packf16(o1x, o1y);
            }
        } else if (MODE == 4) {
#pragma unroll
            for (int j = 0; j < 4; j++) {
                int c0 = n0 + wn*32 + j*8 + 2*(lane & 3);
                const float* q0 = res + (size_t)b*MD*LL + (size_t)r0*LL + c0;
                const float* q1 = res + (size_t)b*MD*LL + (size_t)r1*LL + c0;
                float2 a0 = *(const float2*)q0, a1 = *(const float2*)q1;
                float y00 = acc[i][j][0] + a0.x, y01 = acc[i][j][1] + a0.y;
                float y10 = acc[i][j][2] + a1.x, y11 = acc[i][j][3] + a1.y;
                float* y0 = Y + (size_t)b*MD*LL + (size_t)r0*LL + c0;
                float* y1 = Y + (size_t)b*MD*LL + (size_t)r1*LL + c0;
                *(float2*)y0 = make_float2(y00, y01);
                *(float2*)y1 = make_float2(y10, y11);
                g_x16[((size_t)b*MD + r0)*(LL/2) + (c0>>1)] = packf16(y00, y01);
                g_x16[((size_t)b*MD + r1)*(LL/2) + (c0>>1)] = packf16(y10, y11);
                cs[j][0] += y00 + y10;
                cs[j][1] += y00*y00 + y10*y10;
                cs[j][2] += y01 + y11;
                cs[j][3] += y01*y01 + y11*y11;
            }
        } else { // MODE 2
            float bv0 = bias[r0], bv1 = bias[r1];
#pragma unroll
            for (int j = 0; j < 4; j++) {
                int c0 = n0 + wn*32 + j*8 + 2*(lane & 3);
                const float* q0 = res + (size_t)b*MD*LL + (size_t)r0*LL + c0;
                const float* q1 = res + (size_t)b*MD*LL + (size_t)r1*LL + c0;
                float2 a0 = *(const float2*)q0, a1 = *(const float2*)q1;
                float* y0 = Y + (size_t)b*MD*LL + (size_t)r0*LL + c0;
                float* y1 = Y + (size_t)b*MD*LL + (size_t)r1*LL + c0;
                *(float2*)y0 = make_float2(acc[i][j][0] + bv0 + a0.x, acc[i][j][1] + bv0 + a0.y);
                *(float2*)y1 = make_float2(acc[i][j][2] + bv1 + a1.x, acc[i][j][3] + bv1 + a1.y);
            }
        }
    }
    if (MODE == 4) {
        // reduce over 256 rows: shuffle within warp (lanes sharing lane&3), smem across wm
        float4 (*red)[32] = (float4(*)[32])smem;
#pragma unroll
        for (int j = 0; j < 4; j++)
#pragma unroll
            for (int o = 4; o < 32; o <<= 1) {
                cs[j][0] += __shfl_xor_sync(0xffffffffu, cs[j][0], o);
                cs[j][1] += __shfl_xor_sync(0xffffffffu, cs[j][1], o);
                cs[j][2] += __shfl_xor_sync(0xffffffffu, cs[j][2], o);
                cs[j][3] += __shfl_xor_sync(0xffffffffu, cs[j][3], o);
            }
        if (lane < 4) {
#pragma unroll
            for (int j = 0; j < 4; j++) {
                int cp = wn*16 + j*4 + lane;   // column pair index 0..31
                red[wm][cp] = make_float4(cs[j][0], cs[j][1], cs[j][2], cs[j][3]);
            }
        }
        __syncthreads();
        if (tid < 32) {
            float4 t0 = red[0][tid], t1 = red[1][tid], t2 = red[2][tid], t3 = red[3][tid];
            float sx  = t0.x+t1.x+t2.x+t3.x;
            float sx2 = t0.y+t1.y+t2.y+t3.y;
            float sy  = t0.z+t1.z+t2.z+t3.z;
            float sy2 = t0.w+t1.w+t2.w+t3.w;
            float mx = sx*(1.f/CC), my = sy*(1.f/CC);
            int p = b*LL + n0 + 2*tid;
            g_mu_x[p]   = mx; g_rs_x[p]   = rsqrtf(fmaf(-mx, mx, sx2*(1.f/CC)) + 1e-5f);
            g_mu_x[p+1] = my; g_rs_x[p+1] = rsqrtf(fmaf(-my, my, sy2*(1.f/CC)) + 1e-5f);
        }
    }
}

// ---------------------------------------------------------------------------
// Attention: fused S + softmax (one block per (b,h)), then A@V
// ---------------------------------------------------------------------------
__global__ __launch_bounds__(256)
void attn_s_kernel()
{
    __shared__ float qs[HCC][130];
    __shared__ float ks[HCC][130];
    __shared__ float s_sm[1024];
    int bh = blockIdx.x;
    int b = bh >> 3, h = bh & 7;
    int tid = threadIdx.x;
    const u32* qp = g_q16  + ((size_t)b*CC   + h*HCC)*(LL/2);
    const u32* kp = g_kv16 + ((size_t)b*2*CC + h*HCC)*(LL/2);
    int d = tid & 31, c0 = tid >> 5;
    float a0=0.f, a1=0.f, a2=0.f, a3=0.f;
    uint2 pq[4], pk[4];
    // prefetch chunk 0
#pragma unroll
    for (int it = 0; it < 4; it++) {
        int idx = it*256 + tid;
        int r = idx >> 5, ci2 = idx & 31;
        pq[it] = *(const uint2*)(qp + (size_t)r*(LL/2) + ci2*2);
        pk[it] = *(const uint2*)(kp + (size_t)r*(LL/2) + ci2*2);
    }
#pragma unroll 1
    for (int sp = 0; sp < 32; sp++) {
        // store prefetched chunk (convert to fp32)
#pragma unroll
        for (int it = 0; it < 4; it++) {
            int idx = it*256 + tid;
            int r = idx >> 5, ci2 = idx & 31;
            float2 v0 = unpackf16(pq[it].x), v1 = unpackf16(pq[it].y);
            qs[r][ci2*4] = v0.x; qs[r][ci2*4+1] = v0.y;
            qs[r][ci2*4+2] = v1.x; qs[r][ci2*4+3] = v1.y;
            float2 w0 = unpackf16(pk[it].x), w1 = unpackf16(pk[it].y);
            ks[r][ci2*4] = w0.x; ks[r][ci2*4+1] = w0.y;
            ks[r][ci2*4+2] = w1.x; ks[r][ci2*4+3] = w1.y;
        }
        __syncthreads();
        // prefetch next chunk
        if (sp + 1 < 32) {
#pragma unroll
            for (int it = 0; it < 4; it++) {
                int idx = it*256 + tid;
                int r = idx >> 5, ci2 = idx & 31;
                pq[it] = *(const uint2*)(qp + (size_t)r*(LL/2) + (sp+1)*64 + ci2*2);
                pk[it] = *(const uint2*)(kp + (size_t)r*(LL/2) + (sp+1)*64 + ci2*2);
            }
        }
        // compute: rows c0, c0+8, c0+16, c0+24 vs col d
#pragma unroll 4
        for (int l2 = 0; l2 < 64; l2++) {
            float2 kv = *(const float2*)&ks[d][l2*2];
            float2 q0 = *(const float2*)&qs[c0][l2*2];
            float2 q1 = *(const float2*)&qs[c0+8][l2*2];
            float2 q2 = *(const float2*)&qs[c0+16][l2*2];
            float2 q3 = *(const float2*)&qs[c0+24][l2*2];
            a0 = fmaf(q0.x, kv.x, a0); a0 = fmaf(q0.y, kv.y, a0);
            a1 = fmaf(q1.x, kv.x, a1); a1 = fmaf(q1.y, kv.y, a1);
            a2 = fmaf(q2.x, kv.x, a2); a2 = fmaf(q2.y, kv.y, a2);
            a3 = fmaf(q3.x, kv.x, a3); a3 = fmaf(q3.y, kv.y, a3);
        }
        __syncthreads();
    }
    const float sc = 0.17677669529663687f;
    s_sm[(c0   )*32 + d] = a0*sc;
    s_sm[(c0+8 )*32 + d] = a1*sc;
    s_sm[(c0+16)*32 + d] = a2*sc;
    s_sm[(c0+24)*32 + d] = a3*sc;
    __syncthreads();
    // softmax: warp w handles rows 4w..4w+3
    int wid = tid >> 5, lane = tid & 31;
#pragma unroll
    for (int rr = 0; rr < 4; rr++) {
        int c = wid*4 + rr;
        float v = s_sm[c*32 + lane];
        float mx = v;
#pragma unroll
        for (int o = 16; o > 0; o >>= 1) mx = fmaxf(mx, __shfl_xor_sync(0xffffffffu, mx, o));
        float e = expf(v - mx);
        float sum = e;
#pragma unroll
        for (int o = 16; o > 0; o >>= 1) sum += __shfl_xor_sync(0xffffffffu, sum, o);
        g_A[(size_t)bh*1024 + c*32 + lane] = e / sum;
    }
}

__global__ __launch_bounds__(256)
void attn_av_kernel()
{
    __shared__ float As[1024];
    int bh = blockIdx.x;
    int b = bh >> 3, h = bh & 7;
    int tid = threadIdx.x;
#pragma unroll
    for (int i = 0; i < 4; i++) As[tid + 256*i] = g_A[(size_t)bh*1024 + tid + 256*i];
    __syncthreads();
    int c2 = blockIdx.y*256 + tid;
    const u32* vp = g_kv16 + ((size_t)b*2*CC + CC + h*HCC)*(LL/2) + c2;
    float acc0[32], acc1[32];
#pragma unroll
    for (int c = 0; c < 32; c++) { acc0[c]=0.f; acc1[c]=0.f; }
#pragma unroll 4
    for (int d = 0; d < 32; d++) {
        float2 v = unpackf16(vp[(size_t)d*(LL/2)]);
#pragma unroll
        for (int c = 0; c < 32; c++) {
            float a = As[c*32+d];
            acc0[c] = fmaf(a, v.x, acc0[c]);
            acc1[c] = fmaf(a, v.y, acc1[c]);
        }
    }
#pragma unroll
    for (int c = 0; c < 32; c++) {
        g_a16[((size_t)b*CC + h*HCC + c)*(LL/2) + c2] = packf16(acc0[c], acc1[c]);
    }
}

// ---------------------------------------------------------------------------
// Launcher
// ---------------------------------------------------------------------------
#define GS_128 (2*(128*A_STR + 64*(128*2+16)))   // 71680
#define GS_256 (2*(256*A_STR + 64*(64*2+16)))    // 92160

extern "C" void kernel_launch(void* const* d_in, const int* in_sizes, int n_in,
                              void* d_out, int out_size)
{
    (void)in_sizes; (void)n_in; (void)out_size;
    const float* optical = (const float*)d_in[0];
    const float* sar     = (const float*)d_in[1];
    const float* gopt    = (const float*)d_in[2];
    const float* bopt    = (const float*)d_in[3];
    const float* gsar    = (const float*)d_in[4];
    const float* bsar    = (const float*)d_in[5];
    const float* Wq      = (const float*)d_in[6];
    const float* Wk      = (const float*)d_in[7];
    const float* Wv      = (const float*)d_in[8];
    const float* Wo      = (const float*)d_in[9];
    const float* gffn    = (const float*)d_in[10];
    const float* bffn    = (const float*)d_in[11];
    const float* W1      = (const float*)d_in[12];
    const float* b1      = (const float*)d_in[13];
    const float* W2      = (const float*)d_in[14];
    const float* b2      = (const float*)d_in[15];
    float* out = (float*)d_out;

    float *p_wsq,*p_wbq,*p_wskv,*p_wbkv,*p_ws1,*p_wb1;
    float *p_mu_o,*p_rs_o,*p_mu_s,*p_rs_s,*p_mu_x,*p_rs_x;
    float *p_x;
    u32 *p_Aq,*p_Akv,*p_A1,*p_Ao,*p_A2;
    u32 *p_o16,*p_s16,*p_q16,*p_kv16,*p_a16,*p_x16,*p_hg;
    cudaGetSymbolAddress((void**)&p_wsq, g_wsq);     cudaGetSymbolAddress((void**)&p_wbq, g_wbq);
    cudaGetSymbolAddress((void**)&p_wskv, g_wskv);   cudaGetSymbolAddress((void**)&p_wbkv, g_wbkv);
    cudaGetSymbolAddress((void**)&p_ws1, g_ws1);     cudaGetSymbolAddress((void**)&p_wb1, g_wb1v);
    cudaGetSymbolAddress((void**)&p_mu_o, g_mu_o);   cudaGetSymbolAddress((void**)&p_rs_o, g_rs_o);
    cudaGetSymbolAddress((void**)&p_mu_s, g_mu_s);   cudaGetSymbolAddress((void**)&p_rs_s, g_rs_s);
    cudaGetSymbolAddress((void**)&p_mu_x, g_mu_x);   cudaGetSymbolAddress((void**)&p_rs_x, g_rs_x);
    cudaGetSymbolAddress((void**)&p_x, g_x);
    cudaGetSymbolAddress((void**)&p_o16, g_o16);     cudaGetSymbolAddress((void**)&p_s16, g_s16);
    cudaGetSymbolAddress((void**)&p_q16, g_q16);     cudaGetSymbolAddress((void**)&p_kv16, g_kv16);
    cudaGetSymbolAddress((void**)&p_a16, g_a16);     cudaGetSymbolAddress((void**)&p_x16, g_x16);
    cudaGetSymbolAddress((void**)&p_hg, g_hg);
    cudaGetSymbolAddress((void**)&p_Aq, g_Aq);       cudaGetSymbolAddress((void**)&p_Akv, g_Akv);
    cudaGetSymbolAddress((void**)&p_A1, g_A1);       cudaGetSymbolAddress((void**)&p_Ao, g_Ao);
    cudaGetSymbolAddress((void**)&p_A2, g_A2);

    cudaFuncSetAttribute((void*)gemm_mma<0,256,256,128,128>, cudaFuncAttributeMaxDynamicSharedMemorySize, GS_128);
    cudaFuncSetAttribute((void*)gemm_mma<0,256,512,128,128>, cudaFuncAttributeMaxDynamicSharedMemorySize, GS_128);
    cudaFuncSetAttribute((void*)gemm_mma<4,256,256,256,64>,  cudaFuncAttributeMaxDynamicSharedMemorySize, GS_256);
    cudaFuncSetAttribute((void*)gemm_mma<3,256,FH2,128,128>, cudaFuncAttributeMaxDynamicSharedMemorySize, GS_128);
    cudaFuncSetAttribute((void*)gemm_mma<2,512,256,128,128>, cudaFuncAttributeMaxDynamicSharedMemorySize, GS_128);

    // 1) weight prep
    prep_fold<<<1792, 256>>>(Wq, Wk, Wv, W1, gopt, bopt, gsar, bsar, gffn, bffn, b1);
    prep_plain<<<256, 256>>>(Wo, p_Ao, 256);
    prep_plain<<<256, 256>>>(W2, p_A2, 512);

    // 2) LN stats + fp16 conversion (inputs)
    ln_conv_kernel<<<(NPIX/2)/128, 512>>>(optical, p_mu_o, p_rs_o, p_o16);
    ln_conv_kernel<<<(NPIX/2)/128, 512>>>(sar,     p_mu_s, p_rs_s, p_s16);

    // 3) Q projection + fused K/V projection -> fp16
    gemm_mma<0,256,256,128,128><<<dim3(32,2,BB),256,GS_128>>>(p_Aq,  p_o16, p_q16,  p_mu_o, p_rs_o, p_wsq,  p_wbq,  0, 0);
    gemm_mma<0,256,512,128,128><<<dim3(32,4,BB),256,GS_128>>>(p_Akv, p_s16, p_kv16, p_mu_s, p_rs_s, p_wskv, p_wbkv, 0, 0);

    // 4) channel attention (fused S+softmax) -> fp16 attn
    attn_s_kernel<<<BB*NHH, 256>>>();
    attn_av_kernel<<<dim3(BB*NHH, (LL/2)/256), 256>>>();

    // 5+6) Wo + residual + LN stats + fp16 conv (fused) -> g_x, g_x16, mu_x, rs_x
    gemm_mma<4,256,256,256,64><<<dim3(64,1,BB),256,GS_256>>>(p_Ao, p_a16, p_x, 0, 0, 0, 0, optical, 0);

    // 7) W1 (LN+b1 folded, row-paired) + fused SimpleGate -> hg (fp16)
    gemm_mma<3,256,FH2,128,128><<<dim3(32,8,BB),256,GS_128>>>(p_A1, p_x16, (void*)0, p_mu_x, p_rs_x, p_ws1, p_wb1, 0, 0);

    // 8) W2 + b2 + residual -> out
    gemm_mma<2,512,256,128,128><<<dim3(32,2,BB),256,GS_128>>>(p_A2, p_hg, out, 0, 0, 0, 0, p_x, b2);
}

// round 9
// speedup vs baseline: 4.8459x; 1.0257x over previous
#include <cuda_runtime.h>
#include <cuda_fp16.h>

typedef unsigned int u32;
typedef unsigned long long u64;

#define BB   16
#define CC   256
#define LL   4096
#define NHH  8
#define HCC  32
#define FH   512
#define FH2  1024
#define NPIX (BB*LL)

// ---------------------------------------------------------------------------
// Scratch
// ---------------------------------------------------------------------------
__device__ float g_wsq[CC],  g_wbq[CC];
__device__ float g_wskv[2*CC], g_wbkv[2*CC];
__device__ float g_ws1[FH2], g_wb1v[FH2];      // permuted order
__device__ float g_mu_o[NPIX], g_rs_o[NPIX];
__device__ float g_mu_s[NPIX], g_rs_s[NPIX];
__device__ float g_mu_x[NPIX], g_rs_x[NPIX];
// weights: packed fp16x2 (k even in low 16) == fp16[M][K] row-major
__device__ __align__(128) u32 g_Aq[CC*128];
__device__ __align__(128) u32 g_Akv[2*CC*128];   // Wk rows 0-255, Wv 256-511
__device__ __align__(128) u32 g_A1[FH2*128];     // permuted rows
__device__ __align__(128) u32 g_Ao[CC*128];
__device__ __align__(128) u32 g_A2[CC*256];
// fp16 activations, packed u32 [C][L/2] per batch
__device__ __align__(128) u32 g_o16[BB*CC*(LL/2)];
__device__ __align__(128) u32 g_s16[BB*CC*(LL/2)];
__device__ __align__(128) u32 g_q16[BB*CC*(LL/2)];
__device__ __align__(128) u32 g_kv16[BB*2*CC*(LL/2)];  // k rows 0-255, v 256-511
__device__ __align__(128) u32 g_a16[BB*CC*(LL/2)];
__device__ __align__(128) u32 g_x16[BB*CC*(LL/2)];     // x residual, fp16 only
__device__ __align__(128) u32 g_hg[BB*FH*(LL/2)];
__device__ __align__(128) float g_A[BB*NHH*HCC*HCC];

// ---------------------------------------------------------------------------
// PTX helpers
// ---------------------------------------------------------------------------
__device__ __forceinline__ u32 smem_u32(const void* p) {
    u32 a;
    asm("{ .reg .u64 t; cvta.to.shared.u64 t, %1; cvt.u32.u64 %0, t; }" : "=r"(a) : "l"(p));
    return a;
}
#define LDSM_X4(r0,r1,r2,r3,addr) \
    asm volatile("ldmatrix.sync.aligned.m8n8.x4.shared.b16 {%0,%1,%2,%3}, [%4];" \
        : "=r"(r0),"=r"(r1),"=r"(r2),"=r"(r3) : "r"(addr))
#define LDSM_X4_T(r0,r1,r2,r3,addr) \
    asm volatile("ldmatrix.sync.aligned.m8n8.x4.trans.shared.b16 {%0,%1,%2,%3}, [%4];" \
        : "=r"(r0),"=r"(r1),"=r"(r2),"=r"(r3) : "r"(addr))
#define MMA_F16(d, a, b0, b1) \
    asm volatile("mma.sync.aligned.m16n8k16.row.col.f32.f16.f16.f32 " \
        "{%0,%1,%2,%3}, {%4,%5,%6,%7}, {%8,%9}, {%0,%1,%2,%3};" \
        : "+f"((d)[0]),"+f"((d)[1]),"+f"((d)[2]),"+f"((d)[3]) \
        : "r"((a)[0]),"r"((a)[1]),"r"((a)[2]),"r"((a)[3]), "r"(b0),"r"(b1))
#define CP16(dst, src) \
    asm volatile("cp.async.cg.shared.global [%0], [%1], 16;" \
        :: "r"(dst), "l"(src) : "memory")
#define CP_COMMIT() asm volatile("cp.async.commit_group;" ::: "memory")
#define CP_WAIT(n)  asm volatile("cp.async.wait_group %0;" :: "n"(n) : "memory")

__device__ __forceinline__ u32 packf16(float a, float b) {
    __half2 h = __floats2half2_rn(a, b);
    return *(u32*)&h;
}
__device__ __forceinline__ float2 unpackf16(u32 w) {
    __half2 h = *(__half2*)&w;
    return __half22float2(h);
}

// ---------------------------------------------------------------------------
// Prep
// ---------------------------------------------------------------------------
__global__ void prep_fold(const float* __restrict__ Wq, const float* __restrict__ Wk,
                          const float* __restrict__ Wv, const float* __restrict__ W1,
                          const float* __restrict__ gopt, const float* __restrict__ bopt,
                          const float* __restrict__ gsar, const float* __restrict__ bsar,
                          const float* __restrict__ gffn, const float* __restrict__ bffn,
                          const float* __restrict__ b1)
{
    int row = blockIdx.x;
    int c   = threadIdx.x;
    const float* W; float* ws; float* wb; u32* Ah;
    const float* gg; const float* bb; int m, mdst; float extra = 0.f;
    if (row < 256)      { W=Wq; ws=g_wsq;  wb=g_wbq;  Ah=g_Aq;  gg=gopt; bb=bopt; m=row;     mdst=m; }
    else if (row < 512) { W=Wk; ws=g_wskv; wb=g_wbkv; Ah=g_Akv; gg=gsar; bb=bsar; m=row-256; mdst=m; }
    else if (row < 768) { W=Wv; ws=g_wskv; wb=g_wbkv; Ah=g_Akv; gg=gsar; bb=bsar; m=row-512; mdst=m+256; }
    else {
        W=W1; ws=g_ws1; wb=g_wb1v; Ah=g_A1; gg=gffn; bb=bffn; m=row-768;
        extra = b1[m];
        if (m < FH) mdst = ((m>>3)<<4) + (m&7);
        else        { int mm = m-FH; mdst = ((mm>>3)<<4) + (mm&7) + 8; }
    }
    float w  = W[m*CC + c];
    float wg = w * gg[c];
    u32 hu = (u32)__half_as_ushort(__float2half_rn(wg));
    u32 hp = __shfl_xor_sync(0xffffffffu, hu, 1);
    if (!(c & 1)) Ah[mdst*128 + (c>>1)] = hu | (hp << 16);
    __shared__ float s1[256], s2[256];
    s1[c] = wg; s2[c] = w * bb[c];
    __syncthreads();
    for (int off = 128; off > 0; off >>= 1) {
        if (c < off) { s1[c] += s1[c+off]; s2[c] += s2[c+off]; }
        __syncthreads();
    }
    if (c == 0) { ws[mdst] = s1[0]; wb[mdst] = s2[0] + extra; }
}

__global__ void prep_plain(const float* __restrict__ W, u32* __restrict__ Ah, int K)
{
    int m = blockIdx.x, c0 = threadIdx.x;
    for (int k0 = 0; k0 < K; k0 += 256) {
        int c = k0 + c0;
        float w = W[(size_t)m*K + c];
        u32 hu = (u32)__half_as_ushort(__float2half_rn(w));
        u32 hp = __shfl_xor_sync(0xffffffffu, hu, 1);
        if (!(c0 & 1)) Ah[(size_t)m*(K/2) + (c>>1)] = hu | (hp << 16);
    }
}

// ---------------------------------------------------------------------------
// LN stats + fp16 conversion for BOTH input tensors in one launch (grid.y: 0/1)
// ---------------------------------------------------------------------------
__global__ __launch_bounds__(512)
void ln_conv_kernel(const float* __restrict__ x0, const float* __restrict__ x1)
{
    const float* x  = blockIdx.y ? x1 : x0;
    float* mu = blockIdx.y ? g_mu_s : g_mu_o;
    float* rs = blockIdx.y ? g_rs_s : g_rs_o;
    u32* x16  = blockIdx.y ? g_s16 : g_o16;
    __shared__ float ssx[512], ssx2[512], ssy[512], ssy2[512];
    int tid = threadIdx.x;
    int pr = tid & 127, qd = tid >> 7;
    int p2 = blockIdx.x*128 + pr;
    int b = p2 >> 11, l2 = p2 & 2047;
    const float* base = x + (size_t)b*CC*LL + 2*l2;
    u32* oh = x16 + (size_t)b*CC*(LL/2) + l2;
    float sx=0.f, sx2=0.f, sy=0.f, sy2=0.f;
    int c0 = qd*64;
#pragma unroll 8
    for (int i = 0; i < 64; i++) {
        int c = c0 + i;
        float2 v = *(const float2*)(base + (size_t)c*LL);
        sx += v.x; sx2 = fmaf(v.x, v.x, sx2);
        sy += v.y; sy2 = fmaf(v.y, v.y, sy2);
        oh[(size_t)c*(LL/2)] = packf16(v.x, v.y);
    }
    ssx[tid]=sx; ssx2[tid]=sx2; ssy[tid]=sy; ssy2[tid]=sy2;
    __syncthreads();
    if (qd == 0) {
        float tx  = ssx[pr]  + ssx[pr+128]  + ssx[pr+256]  + ssx[pr+384];
        float tx2 = ssx2[pr] + ssx2[pr+128] + ssx2[pr+256] + ssx2[pr+384];
        float ty  = ssy[pr]  + ssy[pr+128]  + ssy[pr+256]  + ssy[pr+384];
        float ty2 = ssy2[pr] + ssy2[pr+128] + ssy2[pr+256] + ssy2[pr+384];
        float mx = tx*(1.f/CC), my = ty*(1.f/CC);
        int p = b*LL + 2*l2;
        mu[p]   = mx; rs[p]   = rsqrtf(fmaf(-mx, mx, tx2*(1.f/CC)) + 1e-5f);
        mu[p+1] = my; rs[p+1] = rsqrtf(fmaf(-my, my, ty2*(1.f/CC)) + 1e-5f);
    }
}

// ---------------------------------------------------------------------------
// Single-fp16 GEMM, cp.async 2-stage, K chunk 64, 2 CTAs/SM.
// MODE 0: LN epilogue -> fp16 Y16
// MODE 2: +bias +fp16-res -> fp32 out
// MODE 3: gate -> g_hg fp16
// MODE 4: +fp32-res -> g_x16 fp16 + LN stats (no fp32 x)
// ---------------------------------------------------------------------------
#define A_STR 144

template<int MODE, int KD, int MD, int MT, int NT>
__global__ __launch_bounds__(256, 2)
void gemm_mma(const u32* __restrict__ Ah,
              const u32* __restrict__ Xp,
              void* __restrict__ Yv,
              const float* __restrict__ mu, const float* __restrict__ rs,
              const float* __restrict__ wsum, const float* __restrict__ wb,
              const void* __restrict__ res, const float* __restrict__ bias)
{
    constexpr int B_STRc = NT*2 + 16;
    constexpr int BS = MT*A_STR;
    constexpr int STAGE = MT*A_STR + 64*B_STRc;
    constexpr int WN = (MT == 128) ? 4 : 2;
    constexpr int BSEG = NT/8;

    extern __shared__ __align__(128) char smem[];
    const u32 sbase = smem_u32(smem);

    int tid = threadIdx.x, lane = tid & 31, wid = tid >> 5;
    int n0 = blockIdx.x * NT, m0 = blockIdx.y * MT, b = blockIdx.z;
    int wm = wid / WN, wn = wid % WN;

    float acc[4][4][4];
#pragma unroll
    for (int i=0;i<4;i++)
#pragma unroll
        for (int j=0;j<4;j++)
#pragma unroll
            for (int r=0;r<4;r++) acc[i][j][r]=0.f;

    const u32* Xb = Xp + (size_t)b*KD*(LL/2) + (n0>>1);

    u32 a_lm_base = sbase + (u32)((wm*64 + (lane & 15)) * A_STR) + ((lane & 16) ? 16u : 0u);
    u32 b_lm_base = sbase + BS + (u32)((lane & 15) * B_STRc)
                  + (u32)((wn*32 + ((lane & 16) ? 8 : 0)) * 2);

#define ISSUE(st, kc) do { \
        u32 so = sbase + (u32)((st)*STAGE); \
        _Pragma("unroll") \
        for (int ii = tid; ii < MT*8; ii += 256) { \
            int row = ii >> 3, seg = ii & 7; \
            CP16(so + (u32)(row*A_STR + seg*16), \
                 Ah + (size_t)(m0+row)*(KD/2) + ((kc)>>1) + seg*4); \
        } \
        _Pragma("unroll") \
        for (int ii = tid; ii < 64*BSEG; ii += 256) { \
            int row = ii / BSEG, seg = ii % BSEG; \
            CP16(so + (u32)(BS + row*B_STRc + seg*16), \
                 Xb + (size_t)((kc)+row)*(LL/2) + seg*4); \
        } \
        CP_COMMIT(); \
    } while(0)

    ISSUE(0, 0);

#pragma unroll 1
    for (int kc = 0; kc < KD; kc += 64) {
        int cur = (kc >> 6) & 1;
        if (kc + 64 < KD) {
            ISSUE(cur ^ 1, kc + 64);
            CP_WAIT(1);
        } else {
            CP_WAIT(0);
        }
        __syncthreads();
        u32 so = (u32)(cur * STAGE);
#pragma unroll
        for (int ks = 0; ks < 64; ks += 16) {
            u32 af[4][4], bf[4][2];
            u32 ab = a_lm_base + so + (u32)(ks*2);
#pragma unroll
            for (int i = 0; i < 4; i++)
                LDSM_X4(af[i][0], af[i][1], af[i][2], af[i][3], ab + (u32)(i*16*A_STR));
            u32 bb0 = b_lm_base + so + (u32)(ks*B_STRc);
#pragma unroll
            for (int j2 = 0; j2 < 2; j2++)
                LDSM_X4_T(bf[j2*2][0], bf[j2*2][1], bf[j2*2+1][0], bf[j2*2+1][1], bb0 + (u32)(j2*32));
#pragma unroll
            for (int i = 0; i < 4; i++)
#pragma unroll
                for (int j = 0; j < 4; j++)
                    MMA_F16(acc[i][j], af[i], bf[j][0], bf[j][1]);
        }
        __syncthreads();
    }
#undef ISSUE

    // ---- epilogue
    float* Y = (float*)Yv;
    u32* Y16 = (u32*)Yv;
    float cs[4][4];
    if (MODE == 4) {
#pragma unroll
        for (int j=0;j<4;j++)
#pragma unroll
            for (int k=0;k<4;k++) cs[j][k]=0.f;
    }
#pragma unroll
    for (int i = 0; i < 4; i++) {
        int r0 = m0 + wm*64 + i*16 + (lane >> 2);
        int r1 = r0 + 8;
        if (MODE == 3) {
            int t = ((r0 >> 4) << 3) + (r0 & 7);
            float ws1 = wsum[r0], wb1 = wb[r0];
            float ws2 = wsum[r1], wb2 = wb[r1];
#pragma unroll
            for (int j = 0; j < 4; j++) {
                int c0 = n0 + wn*32 + j*8 + 2*(lane & 3);
                int p0 = b*LL + c0;
                float2 m2 = *(const float2*)(mu + p0);
                float2 s2 = *(const float2*)(rs + p0);
                float e1x = s2.x*(acc[i][j][0] - m2.x*ws1) + wb1;
                float e1y = s2.y*(acc[i][j][1] - m2.y*ws1) + wb1;
                float e2x = s2.x*(acc[i][j][2] - m2.x*ws2) + wb2;
                float e2y = s2.y*(acc[i][j][3] - m2.y*ws2) + wb2;
                g_hg[((size_t)b*FH + t)*(LL/2) + (c0 >> 1)] = packf16(e1x*e2x, e1y*e2y);
            }
        } else if (MODE == 0) {
            float ws0 = wsum[r0], wb0 = wb[r0];
            float ws1v = wsum[r1], wb1 = wb[r1];
#pragma unroll
            for (int j = 0; j < 4; j++) {
                int c0 = n0 + wn*32 + j*8 + 2*(lane & 3);
                int p0 = b*LL + c0;
                float2 m2 = *(const float2*)(mu + p0);
                float2 s2 = *(const float2*)(rs + p0);
                float o0x = s2.x*(acc[i][j][0] - m2.x*ws0) + wb0;
                float o0y = s2.y*(acc[i][j][1] - m2.y*ws0) + wb0;
                float o1x = s2.x*(acc[i][j][2] - m2.x*ws1v) + wb1;
                float o1y = s2.y*(acc[i][j][3] - m2.y*ws1v) + wb1;
                Y16[((size_t)b*MD + r0)*(LL/2) + (c0>>1)] = packf16(o0x, o0y);
                Y16[((size_t)b*MD + r1)*(LL/2) + (c0>>1)] = packf16(o1x, o1y);
            }
        } else if (MODE == 4) {
            const float* rf = (const float*)res;
#pragma unroll
            for (int j = 0; j < 4; j++) {
                int c0 = n0 + wn*32 + j*8 + 2*(lane & 3);
                const float* q0 = rf + (size_t)b*MD*LL + (size_t)r0*LL + c0;
                const float* q1 = rf + (size_t)b*MD*LL + (size_t)r1*LL + c0;
                float2 a0 = *(const float2*)q0, a1 = *(const float2*)q1;
                float y00 = acc[i][j][0] + a0.x, y01 = acc[i][j][1] + a0.y;
                float y10 = acc[i][j][2] + a1.x, y11 = acc[i][j][3] + a1.y;
                g_x16[((size_t)b*MD + r0)*(LL/2) + (c0>>1)] = packf16(y00, y01);
                g_x16[((size_t)b*MD + r1)*(LL/2) + (c0>>1)] = packf16(y10, y11);
                cs[j][0] += y00 + y10;
                cs[j][1] += y00*y00 + y10*y10;
                cs[j][2] += y01 + y11;
                cs[j][3] += y01*y01 + y11*y11;
            }
        } else { // MODE 2: fp16 residual, fp32 out
            const u32* r16 = (const u32*)res;
            float bv0 = bias[r0], bv1 = bias[r1];
#pragma unroll
            for (int j = 0; j < 4; j++) {
                int c0 = n0 + wn*32 + j*8 + 2*(lane & 3);
                float2 a0 = unpackf16(r16[((size_t)b*MD + r0)*(LL/2) + (c0>>1)]);
                float2 a1 = unpackf16(r16[((size_t)b*MD + r1)*(LL/2) + (c0>>1)]);
                float* y0 = Y + (size_t)b*MD*LL + (size_t)r0*LL + c0;
                float* y1 = Y + (size_t)b*MD*LL + (size_t)r1*LL + c0;
                *(float2*)y0 = make_float2(acc[i][j][0] + bv0 + a0.x, acc[i][j][1] + bv0 + a0.y);
                *(float2*)y1 = make_float2(acc[i][j][2] + bv1 + a1.x, acc[i][j][3] + bv1 + a1.y);
            }
        }
    }
    if (MODE == 4) {
        float4 (*red)[32] = (float4(*)[32])smem;
#pragma unroll
        for (int j = 0; j < 4; j++)
#pragma unroll
            for (int o = 4; o < 32; o <<= 1) {
                cs[j][0] += __shfl_xor_sync(0xffffffffu, cs[j][0], o);
                cs[j][1] += __shfl_xor_sync(0xffffffffu, cs[j][1], o);
                cs[j][2] += __shfl_xor_sync(0xffffffffu, cs[j][2], o);
                cs[j][3] += __shfl_xor_sync(0xffffffffu, cs[j][3], o);
            }
        if (lane < 4) {
#pragma unroll
            for (int j = 0; j < 4; j++) {
                int cp = wn*16 + j*4 + lane;
                red[wm][cp] = make_float4(cs[j][0], cs[j][1], cs[j][2], cs[j][3]);
            }
        }
        __syncthreads();
        if (tid < 32) {
            float4 t0 = red[0][tid], t1 = red[1][tid], t2 = red[2][tid], t3 = red[3][tid];
            float sx  = t0.x+t1.x+t2.x+t3.x;
            float sx2 = t0.y+t1.y+t2.y+t3.y;
            float sy  = t0.z+t1.z+t2.z+t3.z;
            float sy2 = t0.w+t1.w+t2.w+t3.w;
            float mx = sx*(1.f/CC), my = sy*(1.f/CC);
            int p = b*LL + n0 + 2*tid;
            g_mu_x[p]   = mx; g_rs_x[p]   = rsqrtf(fmaf(-mx, mx, sx2*(1.f/CC)) + 1e-5f);
            g_mu_x[p+1] = my; g_rs_x[p+1] = rsqrtf(fmaf(-my, my, sy2*(1.f/CC)) + 1e-5f);
        }
    }
}

// ---------------------------------------------------------------------------
// Attention: fused S + softmax, then A@V
// ---------------------------------------------------------------------------
__global__ __launch_bounds__(256)
void attn_s_kernel()
{
    __shared__ float qs[HCC][130];
    __shared__ float ks[HCC][130];
    __shared__ float s_sm[1024];
    int bh = blockIdx.x;
    int b = bh >> 3, h = bh & 7;
    int tid = threadIdx.x;
    const u32* qp = g_q16  + ((size_t)b*CC   + h*HCC)*(LL/2);
    const u32* kp = g_kv16 + ((size_t)b*2*CC + h*HCC)*(LL/2);
    int d = tid & 31, c0 = tid >> 5;
    float a0=0.f, a1=0.f, a2=0.f, a3=0.f;
    uint2 pq[4], pk[4];
#pragma unroll
    for (int it = 0; it < 4; it++) {
        int idx = it*256 + tid;
        int r = idx >> 5, ci2 = idx & 31;
        pq[it] = *(const uint2*)(qp + (size_t)r*(LL/2) + ci2*2);
        pk[it] = *(const uint2*)(kp + (size_t)r*(LL/2) + ci2*2);
    }
#pragma unroll 1
    for (int sp = 0; sp < 32; sp++) {
#pragma unroll
        for (int it = 0; it < 4; it++) {
            int idx = it*256 + tid;
            int r = idx >> 5, ci2 = idx & 31;
            float2 v0 = unpackf16(pq[it].x), v1 = unpackf16(pq[it].y);
            qs[r][ci2*4] = v0.x; qs[r][ci2*4+1] = v0.y;
            qs[r][ci2*4+2] = v1.x; qs[r][ci2*4+3] = v1.y;
            float2 w0 = unpackf16(pk[it].x), w1 = unpackf16(pk[it].y);
            ks[r][ci2*4] = w0.x; ks[r][ci2*4+1] = w0.y;
            ks[r][ci2*4+2] = w1.x; ks[r][ci2*4+3] = w1.y;
        }
        __syncthreads();
        if (sp + 1 < 32) {
#pragma unroll
            for (int it = 0; it < 4; it++) {
                int idx = it*256 + tid;
                int r = idx >> 5, ci2 = idx & 31;
                pq[it] = *(const uint2*)(qp + (size_t)r*(LL/2) + (sp+1)*64 + ci2*2);
                pk[it] = *(const uint2*)(kp + (size_t)r*(LL/2) + (sp+1)*64 + ci2*2);
            }
        }
#pragma unroll 4
        for (int l2 = 0; l2 < 64; l2++) {
            float2 kv = *(const float2*)&ks[d][l2*2];
            float2 q0 = *(const float2*)&qs[c0][l2*2];
            float2 q1 = *(const float2*)&qs[c0+8][l2*2];
            float2 q2 = *(const float2*)&qs[c0+16][l2*2];
            float2 q3 = *(const float2*)&qs[c0+24][l2*2];
            a0 = fmaf(q0.x, kv.x, a0); a0 = fmaf(q0.y, kv.y, a0);
            a1 = fmaf(q1.x, kv.x, a1); a1 = fmaf(q1.y, kv.y, a1);
            a2 = fmaf(q2.x, kv.x, a2); a2 = fmaf(q2.y, kv.y, a2);
            a3 = fmaf(q3.x, kv.x, a3); a3 = fmaf(q3.y, kv.y, a3);
        }
        __syncthreads();
    }
    const float sc = 0.17677669529663687f;
    s_sm[(c0   )*32 + d] = a0*sc;
    s_sm[(c0+8 )*32 + d] = a1*sc;
    s_sm[(c0+16)*32 + d] = a2*sc;
    s_sm[(c0+24)*32 + d] = a3*sc;
    __syncthreads();
    int wid = tid >> 5, lane = tid & 31;
#pragma unroll
    for (int rr = 0; rr < 4; rr++) {
        int c = wid*4 + rr;
        float v = s_sm[c*32 + lane];
        float mx = v;
#pragma unroll
        for (int o = 16; o > 0; o >>= 1) mx = fmaxf(mx, __shfl_xor_sync(0xffffffffu, mx, o));
        float e = expf(v - mx);
        float sum = e;
#pragma unroll
        for (int o = 16; o > 0; o >>= 1) sum += __shfl_xor_sync(0xffffffffu, sum, o);
        g_A[(size_t)bh*1024 + c*32 + lane] = e / sum;
    }
}

__global__ __launch_bounds__(256)
void attn_av_kernel()
{
    __shared__ float As[1024];
    int bh = blockIdx.x;
    int b = bh >> 3, h = bh & 7;
    int tid = threadIdx.x;
#pragma unroll
    for (int i = 0; i < 4; i++) As[tid + 256*i] = g_A[(size_t)bh*1024 + tid + 256*i];
    __syncthreads();
    int c2 = blockIdx.y*256 + tid;
    const u32* vp = g_kv16 + ((size_t)b*2*CC + CC + h*HCC)*(LL/2) + c2;
    float acc0[32], acc1[32];
#pragma unroll
    for (int c = 0; c < 32; c++) { acc0[c]=0.f; acc1[c]=0.f; }
#pragma unroll 4
    for (int d = 0; d < 32; d++) {
        float2 v = unpackf16(vp[(size_t)d*(LL/2)]);
#pragma unroll
        for (int c = 0; c < 32; c++) {
            float a = As[c*32+d];
            acc0[c] = fmaf(a, v.x, acc0[c]);
            acc1[c] = fmaf(a, v.y, acc1[c]);
        }
    }
#pragma unroll
    for (int c = 0; c < 32; c++) {
        g_a16[((size_t)b*CC + h*HCC + c)*(LL/2) + c2] = packf16(acc0[c], acc1[c]);
    }
}

// ---------------------------------------------------------------------------
// Launcher
// ---------------------------------------------------------------------------
#define GS_128 (2*(128*A_STR + 64*(128*2+16)))   // 71680
#define GS_256 (2*(256*A_STR + 64*(64*2+16)))    // 92160

extern "C" void kernel_launch(void* const* d_in, const int* in_sizes, int n_in,
                              void* d_out, int out_size)
{
    (void)in_sizes; (void)n_in; (void)out_size;
    const float* optical = (const float*)d_in[0];
    const float* sar     = (const float*)d_in[1];
    const float* gopt    = (const float*)d_in[2];
    const float* bopt    = (const float*)d_in[3];
    const float* gsar    = (const float*)d_in[4];
    const float* bsar    = (const float*)d_in[5];
    const float* Wq      = (const float*)d_in[6];
    const float* Wk      = (const float*)d_in[7];
    const float* Wv      = (const float*)d_in[8];
    const float* Wo      = (const float*)d_in[9];
    const float* gffn    = (const float*)d_in[10];
    const float* bffn    = (const float*)d_in[11];
    const float* W1      = (const float*)d_in[12];
    const float* b1      = (const float*)d_in[13];
    const float* W2      = (const float*)d_in[14];
    const float* b2      = (const float*)d_in[15];
    float* out = (float*)d_out;

    float *p_wsq,*p_wbq,*p_wskv,*p_wbkv,*p_ws1,*p_wb1;
    float *p_mu_o,*p_rs_o,*p_mu_s,*p_rs_s,*p_mu_x,*p_rs_x;
    u32 *p_Aq,*p_Akv,*p_A1,*p_Ao,*p_A2;
    u32 *p_o16,*p_s16,*p_q16,*p_kv16,*p_a16,*p_x16,*p_hg;
    cudaGetSymbolAddress((void**)&p_wsq, g_wsq);     cudaGetSymbolAddress((void**)&p_wbq, g_wbq);
    cudaGetSymbolAddress((void**)&p_wskv, g_wskv);   cudaGetSymbolAddress((void**)&p_wbkv, g_wbkv);
    cudaGetSymbolAddress((void**)&p_ws1, g_ws1);     cudaGetSymbolAddress((void**)&p_wb1, g_wb1v);
    cudaGetSymbolAddress((void**)&p_mu_o, g_mu_o);   cudaGetSymbolAddress((void**)&p_rs_o, g_rs_o);
    cudaGetSymbolAddress((void**)&p_mu_s, g_mu_s);   cudaGetSymbolAddress((void**)&p_rs_s, g_rs_s);
    cudaGetSymbolAddress((void**)&p_mu_x, g_mu_x);   cudaGetSymbolAddress((void**)&p_rs_x, g_rs_x);
    cudaGetSymbolAddress((void**)&p_o16, g_o16);     cudaGetSymbolAddress((void**)&p_s16, g_s16);
    cudaGetSymbolAddress((void**)&p_q16, g_q16);     cudaGetSymbolAddress((void**)&p_kv16, g_kv16);
    cudaGetSymbolAddress((void**)&p_a16, g_a16);     cudaGetSymbolAddress((void**)&p_x16, g_x16);
    cudaGetSymbolAddress((void**)&p_hg, g_hg);
    cudaGetSymbolAddress((void**)&p_Aq, g_Aq);       cudaGetSymbolAddress((void**)&p_Akv, g_Akv);
    cudaGetSymbolAddress((void**)&p_A1, g_A1);       cudaGetSymbolAddress((void**)&p_Ao, g_Ao);
    cudaGetSymbolAddress((void**)&p_A2, g_A2);

    cudaFuncSetAttribute((void*)gemm_mma<0,256,256,128,128>, cudaFuncAttributeMaxDynamicSharedMemorySize, GS_128);
    cudaFuncSetAttribute((void*)gemm_mma<0,256,512,128,128>, cudaFuncAttributeMaxDynamicSharedMemorySize, GS_128);
    cudaFuncSetAttribute((void*)gemm_mma<4,256,256,256,64>,  cudaFuncAttributeMaxDynamicSharedMemorySize, GS_256);
    cudaFuncSetAttribute((void*)gemm_mma<3,256,FH2,128,128>, cudaFuncAttributeMaxDynamicSharedMemorySize, GS_128);
    cudaFuncSetAttribute((void*)gemm_mma<2,512,256,128,128>, cudaFuncAttributeMaxDynamicSharedMemorySize, GS_128);

    // 1) weight prep
    prep_fold<<<1792, 256>>>(Wq, Wk, Wv, W1, gopt, bopt, gsar, bsar, gffn, bffn, b1);
    prep_plain<<<256, 256>>>(Wo, p_Ao, 256);
    prep_plain<<<256, 256>>>(W2, p_A2, 512);

    // 2) LN stats + fp16 conversion (both inputs, one launch)
    ln_conv_kernel<<<dim3((NPIX/2)/128, 2), 512>>>(optical, sar);

    // 3) Q projection + fused K/V projection -> fp16
    gemm_mma<0,256,256,128,128><<<dim3(32,2,BB),256,GS_128>>>(p_Aq,  p_o16, p_q16,  p_mu_o, p_rs_o, p_wsq,  p_wbq,  0, 0);
    gemm_mma<0,256,512,128,128><<<dim3(32,4,BB),256,GS_128>>>(p_Akv, p_s16, p_kv16, p_mu_s, p_rs_s, p_wskv, p_wbkv, 0, 0);

    // 4) channel attention (fused S+softmax) -> fp16 attn
    attn_s_kernel<<<BB*NHH, 256>>>();
    attn_av_kernel<<<dim3(BB*NHH, (LL/2)/256), 256>>>();

    // 5+6) Wo + residual(optical fp32) + LN stats -> g_x16 (fp16 only)
    gemm_mma<4,256,256,256,64><<<dim3(64,1,BB),256,GS_256>>>(p_Ao, p_a16, (void*)0, 0, 0, 0, 0, optical, 0);

    // 7) W1 (LN+b1 folded, row-paired) + fused SimpleGate -> hg (fp16)
    gemm_mma<3,256,FH2,128,128><<<dim3(32,8,BB),256,GS_128>>>(p_A1, p_x16, (void*)0, p_mu_x, p_rs_x, p_ws1, p_wb1, 0, 0);

    // 8) W2 + b2 + residual(x16 fp16) -> out fp32
    gemm_mma<2,512,256,128,128><<<dim3(32,2,BB),256,GS_128>>>(p_A2, p_hg, out, 0, 0, 0, 0, p_x16, b2);
}

// round 10
// speedup vs baseline: 5.0905x; 1.0505x over previous
#include <cuda_runtime.h>
#include <cuda_fp16.h>

typedef unsigned int u32;
typedef unsigned long long u64;

#define BB   16
#define CC   256
#define LL   4096
#define NHH  8
#define HCC  32
#define FH   512
#define FH2  1024
#define NPIX (BB*LL)
#define NSP  4

// ---------------------------------------------------------------------------
// Scratch
// ---------------------------------------------------------------------------
__device__ float g_wsq[CC],  g_wbq[CC];
__device__ float g_wskv[2*CC], g_wbkv[2*CC];
__device__ float g_ws1[FH2], g_wb1v[FH2];      // permuted order
__device__ float g_mu_o[NPIX], g_rs_o[NPIX];
__device__ float g_mu_s[NPIX], g_rs_s[NPIX];
__device__ float g_mu_x[NPIX], g_rs_x[NPIX];
// weights: packed fp16x2 (k even in low 16) == fp16[M][K] row-major
__device__ __align__(128) u32 g_Aq[CC*128];
__device__ __align__(128) u32 g_Akv[2*CC*128];   // Wk rows 0-255, Wv 256-511
__device__ __align__(128) u32 g_A1[FH2*128];     // permuted rows
__device__ __align__(128) u32 g_Ao[CC*128];
__device__ __align__(128) u32 g_A2[CC*256];
// fp16 activations, packed u32 [C][L/2] per batch
__device__ __align__(128) u32 g_o16[BB*CC*(LL/2)];
__device__ __align__(128) u32 g_s16[BB*CC*(LL/2)];
__device__ __align__(128) u32 g_q16[BB*CC*(LL/2)];
__device__ __align__(128) u32 g_kv16[BB*2*CC*(LL/2)];  // k rows 0-255, v 256-511
__device__ __align__(128) u32 g_a16[BB*CC*(LL/2)];
__device__ __align__(128) u32 g_x16[BB*CC*(LL/2)];     // x residual, fp16 only
__device__ __align__(128) u32 g_hg[BB*FH*(LL/2)];
__device__ __align__(128) float g_Sp[BB*NHH*NSP*HCC*HCC];
__device__ __align__(128) float g_A[BB*NHH*HCC*HCC];

// ---------------------------------------------------------------------------
// PTX helpers
// ---------------------------------------------------------------------------
__device__ __forceinline__ u32 smem_u32(const void* p) {
    u32 a;
    asm("{ .reg .u64 t; cvta.to.shared.u64 t, %1; cvt.u32.u64 %0, t; }" : "=r"(a) : "l"(p));
    return a;
}
#define LDSM_X4(r0,r1,r2,r3,addr) \
    asm volatile("ldmatrix.sync.aligned.m8n8.x4.shared.b16 {%0,%1,%2,%3}, [%4];" \
        : "=r"(r0),"=r"(r1),"=r"(r2),"=r"(r3) : "r"(addr))
#define LDSM_X4_T(r0,r1,r2,r3,addr) \
    asm volatile("ldmatrix.sync.aligned.m8n8.x4.trans.shared.b16 {%0,%1,%2,%3}, [%4];" \
        : "=r"(r0),"=r"(r1),"=r"(r2),"=r"(r3) : "r"(addr))
#define MMA_F16(d, a, b0, b1) \
    asm volatile("mma.sync.aligned.m16n8k16.row.col.f32.f16.f16.f32 " \
        "{%0,%1,%2,%3}, {%4,%5,%6,%7}, {%8,%9}, {%0,%1,%2,%3};" \
        : "+f"((d)[0]),"+f"((d)[1]),"+f"((d)[2]),"+f"((d)[3]) \
        : "r"((a)[0]),"r"((a)[1]),"r"((a)[2]),"r"((a)[3]), "r"(b0),"r"(b1))
#define CP16(dst, src) \
    asm volatile("cp.async.cg.shared.global [%0], [%1], 16;" \
        :: "r"(dst), "l"(src) : "memory")
#define CP_COMMIT() asm volatile("cp.async.commit_group;" ::: "memory")
#define CP_WAIT(n)  asm volatile("cp.async.wait_group %0;" :: "n"(n) : "memory")

__device__ __forceinline__ u32 packf16(float a, float b) {
    __half2 h = __floats2half2_rn(a, b);
    return *(u32*)&h;
}
__device__ __forceinline__ float2 unpackf16(u32 w) {
    __half2 h = *(__half2*)&w;
    return __half22float2(h);
}

// ---------------------------------------------------------------------------
// Prep: all five weight matrices in one launch.
// rows 0..255 Wq | 256..511 Wk | 512..767 Wv | 768..1791 W1 (fold+perm)
// rows 1792..2047 Wo (plain) | 2048..2559 W2 (plain, K=512: 2 rows per m)
// ---------------------------------------------------------------------------
__global__ void prep_fold(const float* __restrict__ Wq, const float* __restrict__ Wk,
                          const float* __restrict__ Wv, const float* __restrict__ W1,
                          const float* __restrict__ Wo, const float* __restrict__ W2,
                          const float* __restrict__ gopt, const float* __restrict__ bopt,
                          const float* __restrict__ gsar, const float* __restrict__ bsar,
                          const float* __restrict__ gffn, const float* __restrict__ bffn,
                          const float* __restrict__ b1)
{
    int row = blockIdx.x;
    int c   = threadIdx.x;
    if (row >= 1792) {
        // plain fp16 pack, no LN fold, no reduction
        float w; u32* dst; int di;
        if (row < 2048) {
            int m = row - 1792;
            w = Wo[m*CC + c];
            dst = g_Ao; di = m*128 + (c>>1);
        } else {
            int r2 = row - 2048;          // 0..511
            int m = r2 >> 1, half = r2 & 1;
            int cg = half*256 + c;
            w = W2[m*512 + cg];
            dst = g_A2; di = m*256 + (cg>>1);
        }
        u32 hu = (u32)__half_as_ushort(__float2half_rn(w));
        u32 hp = __shfl_xor_sync(0xffffffffu, hu, 1);
        if (!(c & 1)) dst[di] = hu | (hp << 16);
        return;
    }
    const float* W; float* ws; float* wb; u32* Ah;
    const float* gg; const float* bb; int m, mdst; float extra = 0.f;
    if (row < 256)      { W=Wq; ws=g_wsq;  wb=g_wbq;  Ah=g_Aq;  gg=gopt; bb=bopt; m=row;     mdst=m; }
    else if (row < 512) { W=Wk; ws=g_wskv; wb=g_wbkv; Ah=g_Akv; gg=gsar; bb=bsar; m=row-256; mdst=m; }
    else if (row < 768) { W=Wv; ws=g_wskv; wb=g_wbkv; Ah=g_Akv; gg=gsar; bb=bsar; m=row-512; mdst=m+256; }
    else {
        W=W1; ws=g_ws1; wb=g_wb1v; Ah=g_A1; gg=gffn; bb=bffn; m=row-768;
        extra = b1[m];
        if (m < FH) mdst = ((m>>3)<<4) + (m&7);
        else        { int mm = m-FH; mdst = ((mm>>3)<<4) + (mm&7) + 8; }
    }
    float w  = W[m*CC + c];
    float wg = w * gg[c];
    u32 hu = (u32)__half_as_ushort(__float2half_rn(wg));
    u32 hp = __shfl_xor_sync(0xffffffffu, hu, 1);
    if (!(c & 1)) Ah[mdst*128 + (c>>1)] = hu | (hp << 16);
    __shared__ float s1[256], s2[256];
    s1[c] = wg; s2[c] = w * bb[c];
    __syncthreads();
    for (int off = 128; off > 0; off >>= 1) {
        if (c < off) { s1[c] += s1[c+off]; s2[c] += s2[c+off]; }
        __syncthreads();
    }
    if (c == 0) { ws[mdst] = s1[0]; wb[mdst] = s2[0] + extra; }
}

// ---------------------------------------------------------------------------
// LN stats + fp16 conversion for BOTH input tensors in one launch (grid.y: 0/1)
// ---------------------------------------------------------------------------
__global__ __launch_bounds__(512)
void ln_conv_kernel(const float* __restrict__ x0, const float* __restrict__ x1)
{
    const float* x  = blockIdx.y ? x1 : x0;
    float* mu = blockIdx.y ? g_mu_s : g_mu_o;
    float* rs = blockIdx.y ? g_rs_s : g_rs_o;
    u32* x16  = blockIdx.y ? g_s16 : g_o16;
    __shared__ float ssx[512], ssx2[512], ssy[512], ssy2[512];
    int tid = threadIdx.x;
    int pr = tid & 127, qd = tid >> 7;
    int p2 = blockIdx.x*128 + pr;
    int b = p2 >> 11, l2 = p2 & 2047;
    const float* base = x + (size_t)b*CC*LL + 2*l2;
    u32* oh = x16 + (size_t)b*CC*(LL/2) + l2;
    float sx=0.f, sx2=0.f, sy=0.f, sy2=0.f;
    int c0 = qd*64;
#pragma unroll 8
    for (int i = 0; i < 64; i++) {
        int c = c0 + i;
        float2 v = *(const float2*)(base + (size_t)c*LL);
        sx += v.x; sx2 = fmaf(v.x, v.x, sx2);
        sy += v.y; sy2 = fmaf(v.y, v.y, sy2);
        oh[(size_t)c*(LL/2)] = packf16(v.x, v.y);
    }
    ssx[tid]=sx; ssx2[tid]=sx2; ssy[tid]=sy; ssy2[tid]=sy2;
    __syncthreads();
    if (qd == 0) {
        float tx  = ssx[pr]  + ssx[pr+128]  + ssx[pr+256]  + ssx[pr+384];
        float tx2 = ssx2[pr] + ssx2[pr+128] + ssx2[pr+256] + ssx2[pr+384];
        float ty  = ssy[pr]  + ssy[pr+128]  + ssy[pr+256]  + ssy[pr+384];
        float ty2 = ssy2[pr] + ssy2[pr+128] + ssy2[pr+256] + ssy2[pr+384];
        float mx = tx*(1.f/CC), my = ty*(1.f/CC);
        int p = b*LL + 2*l2;
        mu[p]   = mx; rs[p]   = rsqrtf(fmaf(-mx, mx, tx2*(1.f/CC)) + 1e-5f);
        mu[p+1] = my; rs[p+1] = rsqrtf(fmaf(-my, my, ty2*(1.f/CC)) + 1e-5f);
    }
}

// ---------------------------------------------------------------------------
// Shared GEMM body (mainloop) as macro-free inline pieces used by both kernels
// ---------------------------------------------------------------------------
#define A_STR 144

// ---------------------------------------------------------------------------
// Fused Q+KV projection GEMM. grid (32, 6, BB): y<2 -> Q, y>=2 -> KV.
// MODE0 epilogue (LN fold) -> fp16 output.
// ---------------------------------------------------------------------------
__global__ __launch_bounds__(256, 2)
void gemm_qkv()
{
    constexpr int KD = 256, MT = 128, NT = 128;
    constexpr int B_STRc = NT*2 + 16;
    constexpr int BS = MT*A_STR;
    constexpr int STAGE = BS + 64*B_STRc;

    extern __shared__ __align__(128) char smem[];
    const u32 sbase = smem_u32(smem);

    int y = blockIdx.y;
    bool isq = (y < 2);
    const u32* Ah   = isq ? g_Aq  : g_Akv;
    const u32* Xp   = isq ? g_o16 : g_s16;
    u32* Y16        = isq ? g_q16 : g_kv16;
    const float* mu = isq ? g_mu_o : g_mu_s;
    const float* rs = isq ? g_rs_o : g_rs_s;
    const float* wsum = isq ? g_wsq : g_wskv;
    const float* wb   = isq ? g_wbq : g_wbkv;
    int md = isq ? 256 : 512;
    int m0 = (isq ? y : y - 2) * MT;

    int tid = threadIdx.x, lane = tid & 31, wid = tid >> 5;
    int n0 = blockIdx.x * NT, b = blockIdx.z;
    int wm = wid >> 2, wn = wid & 3;

    float acc[4][4][4];
#pragma unroll
    for (int i=0;i<4;i++)
#pragma unroll
        for (int j=0;j<4;j++)
#pragma unroll
            for (int r=0;r<4;r++) acc[i][j][r]=0.f;

    const u32* Xb = Xp + (size_t)b*KD*(LL/2) + (n0>>1);
    u32 a_lm_base = sbase + (u32)((wm*64 + (lane & 15)) * A_STR) + ((lane & 16) ? 16u : 0u);
    u32 b_lm_base = sbase + BS + (u32)((lane & 15) * B_STRc)
                  + (u32)((wn*32 + ((lane & 16) ? 8 : 0)) * 2);

#define ISSUEQ(st, kc) do { \
        u32 so = sbase + (u32)((st)*STAGE); \
        _Pragma("unroll") \
        for (int ii = tid; ii < MT*8; ii += 256) { \
            int row = ii >> 3, seg = ii & 7; \
            CP16(so + (u32)(row*A_STR + seg*16), \
                 Ah + (size_t)(m0+row)*(KD/2) + ((kc)>>1) + seg*4); \
        } \
        _Pragma("unroll") \
        for (int ii = tid; ii < 64*16; ii += 256) { \
            int row = ii >> 4, seg = ii & 15; \
            CP16(so + (u32)(BS + row*B_STRc + seg*16), \
                 Xb + (size_t)((kc)+row)*(LL/2) + seg*4); \
        } \
        CP_COMMIT(); \
    } while(0)

    ISSUEQ(0, 0);
#pragma unroll 1
    for (int kc = 0; kc < KD; kc += 64) {
        int cur = (kc >> 6) & 1;
        if (kc + 64 < KD) { ISSUEQ(cur ^ 1, kc + 64); CP_WAIT(1); }
        else              { CP_WAIT(0); }
        __syncthreads();
        u32 so = (u32)(cur * STAGE);
#pragma unroll
        for (int ks = 0; ks < 64; ks += 16) {
            u32 af[4][4], bf[4][2];
            u32 ab = a_lm_base + so + (u32)(ks*2);
#pragma unroll
            for (int i = 0; i < 4; i++)
                LDSM_X4(af[i][0], af[i][1], af[i][2], af[i][3], ab + (u32)(i*16*A_STR));
            u32 bb0 = b_lm_base + so + (u32)(ks*B_STRc);
#pragma unroll
            for (int j2 = 0; j2 < 2; j2++)
                LDSM_X4_T(bf[j2*2][0], bf[j2*2][1], bf[j2*2+1][0], bf[j2*2+1][1], bb0 + (u32)(j2*32));
#pragma unroll
            for (int i = 0; i < 4; i++)
#pragma unroll
                for (int j = 0; j < 4; j++)
                    MMA_F16(acc[i][j], af[i], bf[j][0], bf[j][1]);
        }
        __syncthreads();
    }
#undef ISSUEQ

#pragma unroll
    for (int i = 0; i < 4; i++) {
        int r0 = m0 + wm*64 + i*16 + (lane >> 2);
        int r1 = r0 + 8;
        float ws0 = wsum[r0], wb0 = wb[r0];
        float ws1v = wsum[r1], wb1 = wb[r1];
#pragma unroll
        for (int j = 0; j < 4; j++) {
            int c0 = n0 + wn*32 + j*8 + 2*(lane & 3);
            int p0 = b*LL + c0;
            float2 m2 = *(const float2*)(mu + p0);
            float2 s2 = *(const float2*)(rs + p0);
            float o0x = s2.x*(acc[i][j][0] - m2.x*ws0) + wb0;
            float o0y = s2.y*(acc[i][j][1] - m2.y*ws0) + wb0;
            float o1x = s2.x*(acc[i][j][2] - m2.x*ws1v) + wb1;
            float o1y = s2.y*(acc[i][j][3] - m2.y*ws1v) + wb1;
            Y16[((size_t)b*md + r0)*(LL/2) + (c0>>1)] = packf16(o0x, o0y);
            Y16[((size_t)b*md + r1)*(LL/2) + (c0>>1)] = packf16(o1x, o1y);
        }
    }
}

// ---------------------------------------------------------------------------
// General GEMM (modes 2/3/4), cp.async 2-stage, K chunk 64, 2 CTAs/SM.
// MODE 2: +bias +fp16-res -> fp32 out
// MODE 3: gate -> g_hg fp16
// MODE 4: +fp32-res -> g_x16 fp16 + LN stats
// ---------------------------------------------------------------------------
template<int MODE, int KD, int MD, int MT, int NT>
__global__ __launch_bounds__(256, 2)
void gemm_mma(const u32* __restrict__ Ah,
              const u32* __restrict__ Xp,
              void* __restrict__ Yv,
              const float* __restrict__ mu, const float* __restrict__ rs,
              const float* __restrict__ wsum, const float* __restrict__ wb,
              const void* __restrict__ res, const float* __restrict__ bias)
{
    constexpr int B_STRc = NT*2 + 16;
    constexpr int BS = MT*A_STR;
    constexpr int STAGE = MT*A_STR + 64*B_STRc;
    constexpr int WN = (MT == 128) ? 4 : 2;
    constexpr int BSEG = NT/8;

    extern __shared__ __align__(128) char smem[];
    const u32 sbase = smem_u32(smem);

    int tid = threadIdx.x, lane = tid & 31, wid = tid >> 5;
    int n0 = blockIdx.x * NT, m0 = blockIdx.y * MT, b = blockIdx.z;
    int wm = wid / WN, wn = wid % WN;

    float acc[4][4][4];
#pragma unroll
    for (int i=0;i<4;i++)
#pragma unroll
        for (int j=0;j<4;j++)
#pragma unroll
            for (int r=0;r<4;r++) acc[i][j][r]=0.f;

    const u32* Xb = Xp + (size_t)b*KD*(LL/2) + (n0>>1);

    u32 a_lm_base = sbase + (u32)((wm*64 + (lane & 15)) * A_STR) + ((lane & 16) ? 16u : 0u);
    u32 b_lm_base = sbase + BS + (u32)((lane & 15) * B_STRc)
                  + (u32)((wn*32 + ((lane & 16) ? 8 : 0)) * 2);

#define ISSUE(st, kc) do { \
        u32 so = sbase + (u32)((st)*STAGE); \
        _Pragma("unroll") \
        for (int ii = tid; ii < MT*8; ii += 256) { \
            int row = ii >> 3, seg = ii & 7; \
            CP16(so + (u32)(row*A_STR + seg*16), \
                 Ah + (size_t)(m0+row)*(KD/2) + ((kc)>>1) + seg*4); \
        } \
        _Pragma("unroll") \
        for (int ii = tid; ii < 64*BSEG; ii += 256) { \
            int row = ii / BSEG, seg = ii % BSEG; \
            CP16(so + (u32)(BS + row*B_STRc + seg*16), \
                 Xb + (size_t)((kc)+row)*(LL/2) + seg*4); \
        } \
        CP_COMMIT(); \
    } while(0)

    ISSUE(0, 0);

#pragma unroll 1
    for (int kc = 0; kc < KD; kc += 64) {
        int cur = (kc >> 6) & 1;
        if (kc + 64 < KD) { ISSUE(cur ^ 1, kc + 64); CP_WAIT(1); }
        else              { CP_WAIT(0); }
        __syncthreads();
        u32 so = (u32)(cur * STAGE);
#pragma unroll
        for (int ks = 0; ks < 64; ks += 16) {
            u32 af[4][4], bf[4][2];
            u32 ab = a_lm_base + so + (u32)(ks*2);
#pragma unroll
            for (int i = 0; i < 4; i++)
                LDSM_X4(af[i][0], af[i][1], af[i][2], af[i][3], ab + (u32)(i*16*A_STR));
            u32 bb0 = b_lm_base + so + (u32)(ks*B_STRc);
#pragma unroll
            for (int j2 = 0; j2 < 2; j2++)
                LDSM_X4_T(bf[j2*2][0], bf[j2*2][1], bf[j2*2+1][0], bf[j2*2+1][1], bb0 + (u32)(j2*32));
#pragma unroll
            for (int i = 0; i < 4; i++)
#pragma unroll
                for (int j = 0; j < 4; j++)
                    MMA_F16(acc[i][j], af[i], bf[j][0], bf[j][1]);
        }
        __syncthreads();
    }
#undef ISSUE

    float* Y = (float*)Yv;
    float cs[4][4];
    if (MODE == 4) {
#pragma unroll
        for (int j=0;j<4;j++)
#pragma unroll
            for (int k=0;k<4;k++) cs[j][k]=0.f;
    }
#pragma unroll
    for (int i = 0; i < 4; i++) {
        int r0 = m0 + wm*64 + i*16 + (lane >> 2);
        int r1 = r0 + 8;
        if (MODE == 3) {
            int t = ((r0 >> 4) << 3) + (r0 & 7);
            float ws1 = wsum[r0], wb1 = wb[r0];
            float ws2 = wsum[r1], wb2 = wb[r1];
#pragma unroll
            for (int j = 0; j < 4; j++) {
                int c0 = n0 + wn*32 + j*8 + 2*(lane & 3);
                int p0 = b*LL + c0;
                float2 m2 = *(const float2*)(mu + p0);
                float2 s2 = *(const float2*)(rs + p0);
                float e1x = s2.x*(acc[i][j][0] - m2.x*ws1) + wb1;
                float e1y = s2.y*(acc[i][j][1] - m2.y*ws1) + wb1;
                float e2x = s2.x*(acc[i][j][2] - m2.x*ws2) + wb2;
                float e2y = s2.y*(acc[i][j][3] - m2.y*ws2) + wb2;
                g_hg[((size_t)b*FH + t)*(LL/2) + (c0 >> 1)] = packf16(e1x*e2x, e1y*e2y);
            }
        } else if (MODE == 4) {
            const float* rf = (const float*)res;
#pragma unroll
            for (int j = 0; j < 4; j++) {
                int c0 = n0 + wn*32 + j*8 + 2*(lane & 3);
                const float* q0 = rf + (size_t)b*MD*LL + (size_t)r0*LL + c0;
                const float* q1 = rf + (size_t)b*MD*LL + (size_t)r1*LL + c0;
                float2 a0 = *(const float2*)q0, a1 = *(const float2*)q1;
                float y00 = acc[i][j][0] + a0.x, y01 = acc[i][j][1] + a0.y;
                float y10 = acc[i][j][2] + a1.x, y11 = acc[i][j][3] + a1.y;
                g_x16[((size_t)b*MD + r0)*(LL/2) + (c0>>1)] = packf16(y00, y01);
                g_x16[((size_t)b*MD + r1)*(LL/2) + (c0>>1)] = packf16(y10, y11);
                cs[j][0] += y00 + y10;
                cs[j][1] += y00*y00 + y10*y10;
                cs[j][2] += y01 + y11;
                cs[j][3] += y01*y01 + y11*y11;
            }
        } else { // MODE 2
            const u32* r16 = (const u32*)res;
            float bv0 = bias[r0], bv1 = bias[r1];
#pragma unroll
            for (int j = 0; j < 4; j++) {
                int c0 = n0 + wn*32 + j*8 + 2*(lane & 3);
                float2 a0 = unpackf16(r16[((size_t)b*MD + r0)*(LL/2) + (c0>>1)]);
                float2 a1 = unpackf16(r16[((size_t)b*MD + r1)*(LL/2) + (c0>>1)]);
                float* y0 = Y + (size_t)b*MD*LL + (size_t)r0*LL + c0;
                float* y1 = Y + (size_t)b*MD*LL + (size_t)r1*LL + c0;
                *(float2*)y0 = make_float2(acc[i][j][0] + bv0 + a0.x, acc[i][j][1] + bv0 + a0.y);
                *(float2*)y1 = make_float2(acc[i][j][2] + bv1 + a1.x, acc[i][j][3] + bv1 + a1.y);
            }
        }
    }
    if (MODE == 4) {
        float4 (*red)[32] = (float4(*)[32])smem;
#pragma unroll
        for (int j = 0; j < 4; j++)
#pragma unroll
            for (int o = 4; o < 32; o <<= 1) {
                cs[j][0] += __shfl_xor_sync(0xffffffffu, cs[j][0], o);
                cs[j][1] += __shfl_xor_sync(0xffffffffu, cs[j][1], o);
                cs[j][2] += __shfl_xor_sync(0xffffffffu, cs[j][2], o);
                cs[j][3] += __shfl_xor_sync(0xffffffffu, cs[j][3], o);
            }
        if (lane < 4) {
#pragma unroll
            for (int j = 0; j < 4; j++) {
                int cp = wn*16 + j*4 + lane;
                red[wm][cp] = make_float4(cs[j][0], cs[j][1], cs[j][2], cs[j][3]);
            }
        }
        __syncthreads();
        if (tid < 32) {
            float4 t0 = red[0][tid], t1 = red[1][tid], t2 = red[2][tid], t3 = red[3][tid];
            float sx  = t0.x+t1.x+t2.x+t3.x;
            float sx2 = t0.y+t1.y+t2.y+t3.y;
            float sy  = t0.z+t1.z+t2.z+t3.z;
            float sy2 = t0.w+t1.w+t2.w+t3.w;
            float mx = sx*(1.f/CC), my = sy*(1.f/CC);
            int p = b*LL + n0 + 2*tid;
            g_mu_x[p]   = mx; g_rs_x[p]   = rsqrtf(fmaf(-mx, mx, sx2*(1.f/CC)) + 1e-5f);
            g_mu_x[p+1] = my; g_rs_x[p+1] = rsqrtf(fmaf(-my, my, sy2*(1.f/CC)) + 1e-5f);
        }
    }
}

// ---------------------------------------------------------------------------
// Attention: partial S over 4 L-splits (512 CTAs), softmax reduce, A@V
// ---------------------------------------------------------------------------
__global__ __launch_bounds__(256)
void attn_s_kernel()   // grid (BB*NHH, NSP)
{
    __shared__ float qs[HCC][130];
    __shared__ float ks[HCC][130];
    int bh = blockIdx.x, sp = blockIdx.y;
    int b = bh >> 3, h = bh & 7;
    int tid = threadIdx.x;
    const u32* qp = g_q16  + ((size_t)b*CC   + h*HCC)*(LL/2) + sp*512;
    const u32* kp = g_kv16 + ((size_t)b*2*CC + h*HCC)*(LL/2) + sp*512;
    int d = tid & 31, c0 = tid >> 5;
    float a0=0.f, a1=0.f, a2=0.f, a3=0.f;
    uint2 pq[4], pk[4];
#pragma unroll
    for (int it = 0; it < 4; it++) {
        int idx = it*256 + tid;
        int r = idx >> 5, ci2 = idx & 31;
        pq[it] = *(const uint2*)(qp + (size_t)r*(LL/2) + ci2*2);
        pk[it] = *(const uint2*)(kp + (size_t)r*(LL/2) + ci2*2);
    }
#pragma unroll 1
    for (int ch = 0; ch < 8; ch++) {
#pragma unroll
        for (int it = 0; it < 4; it++) {
            int idx = it*256 + tid;
            int r = idx >> 5, ci2 = idx & 31;
            float2 v0 = unpackf16(pq[it].x), v1 = unpackf16(pq[it].y);
            qs[r][ci2*4] = v0.x; qs[r][ci2*4+1] = v0.y;
            qs[r][ci2*4+2] = v1.x; qs[r][ci2*4+3] = v1.y;
            float2 w0 = unpackf16(pk[it].x), w1 = unpackf16(pk[it].y);
            ks[r][ci2*4] = w0.x; ks[r][ci2*4+1] = w0.y;
            ks[r][ci2*4+2] = w1.x; ks[r][ci2*4+3] = w1.y;
        }
        __syncthreads();
        if (ch + 1 < 8) {
#pragma unroll
            for (int it = 0; it < 4; it++) {
                int idx = it*256 + tid;
                int r = idx >> 5, ci2 = idx & 31;
                pq[it] = *(const uint2*)(qp + (size_t)r*(LL/2) + (ch+1)*64 + ci2*2);
                pk[it] = *(const uint2*)(kp + (size_t)r*(LL/2) + (ch+1)*64 + ci2*2);
            }
        }
#pragma unroll 4
        for (int l2 = 0; l2 < 64; l2++) {
            float2 kv = *(const float2*)&ks[d][l2*2];
            float2 q0 = *(const float2*)&qs[c0][l2*2];
            float2 q1 = *(const float2*)&qs[c0+8][l2*2];
            float2 q2 = *(const float2*)&qs[c0+16][l2*2];
            float2 q3 = *(const float2*)&qs[c0+24][l2*2];
            a0 = fmaf(q0.x, kv.x, a0); a0 = fmaf(q0.y, kv.y, a0);
            a1 = fmaf(q1.x, kv.x, a1); a1 = fmaf(q1.y, kv.y, a1);
            a2 = fmaf(q2.x, kv.x, a2); a2 = fmaf(q2.y, kv.y, a2);
            a3 = fmaf(q3.x, kv.x, a3); a3 = fmaf(q3.y, kv.y, a3);
        }
        __syncthreads();
    }
    float* out = g_Sp + ((size_t)bh*NSP + sp)*1024;
    out[(c0   )*32 + d] = a0;
    out[(c0+8 )*32 + d] = a1;
    out[(c0+16)*32 + d] = a2;
    out[(c0+24)*32 + d] = a3;
}

__global__ void attn_softmax_kernel()   // grid BB*NHH, 1024 threads
{
    int bh = blockIdx.x, t = threadIdx.x;
    const float* sp = g_Sp + (size_t)bh*NSP*1024 + t;
    float s = sp[0] + sp[1024] + sp[2048] + sp[3072];
    s *= 0.17677669529663687f;
    float mx = s;
#pragma unroll
    for (int o = 16; o > 0; o >>= 1) mx = fmaxf(mx, __shfl_xor_sync(0xffffffffu, mx, o));
    float e = expf(s - mx);
    float sum = e;
#pragma unroll
    for (int o = 16; o > 0; o >>= 1) sum += __shfl_xor_sync(0xffffffffu, sum, o);
    g_A[(size_t)bh*1024 + t] = e / sum;
}

__global__ __launch_bounds__(256)
void attn_av_kernel()
{
    __shared__ float As[1024];
    int bh = blockIdx.x;
    int b = bh >> 3, h = bh & 7;
    int tid = threadIdx.x;
#pragma unroll
    for (int i = 0; i < 4; i++) As[tid + 256*i] = g_A[(size_t)bh*1024 + tid + 256*i];
    __syncthreads();
    int c2 = blockIdx.y*256 + tid;
    const u32* vp = g_kv16 + ((size_t)b*2*CC + CC + h*HCC)*(LL/2) + c2;
    float acc0[32], acc1[32];
#pragma unroll
    for (int c = 0; c < 32; c++) { acc0[c]=0.f; acc1[c]=0.f; }
#pragma unroll 4
    for (int d = 0; d < 32; d++) {
        float2 v = unpackf16(vp[(size_t)d*(LL/2)]);
#pragma unroll
        for (int c = 0; c < 32; c++) {
            float a = As[c*32+d];
            acc0[c] = fmaf(a, v.x, acc0[c]);
            acc1[c] = fmaf(a, v.y, acc1[c]);
        }
    }
#pragma unroll
    for (int c = 0; c < 32; c++) {
        g_a16[((size_t)b*CC + h*HCC + c)*(LL/2) + c2] = packf16(acc0[c], acc1[c]);
    }
}

// ---------------------------------------------------------------------------
// Launcher
// ---------------------------------------------------------------------------
#define GS_128 (2*(128*A_STR + 64*(128*2+16)))   // 71680
#define GS_256 (2*(256*A_STR + 64*(64*2+16)))    // 92160

extern "C" void kernel_launch(void* const* d_in, const int* in_sizes, int n_in,
                              void* d_out, int out_size)
{
    (void)in_sizes; (void)n_in; (void)out_size;
    const float* optical = (const float*)d_in[0];
    const float* sar     = (const float*)d_in[1];
    const float* gopt    = (const float*)d_in[2];
    const float* bopt    = (const float*)d_in[3];
    const float* gsar    = (const float*)d_in[4];
    const float* bsar    = (const float*)d_in[5];
    const float* Wq      = (const float*)d_in[6];
    const float* Wk      = (const float*)d_in[7];
    const float* Wv      = (const float*)d_in[8];
    const float* Wo      = (const float*)d_in[9];
    const float* gffn    = (const float*)d_in[10];
    const float* bffn    = (const float*)d_in[11];
    const float* W1      = (const float*)d_in[12];
    const float* b1      = (const float*)d_in[13];
    const float* W2      = (const float*)d_in[14];
    const float* b2      = (const float*)d_in[15];
    float* out = (float*)d_out;

    float *p_ws1,*p_wb1,*p_mu_x,*p_rs_x;
    u32 *p_A1,*p_Ao,*p_A2,*p_a16,*p_x16,*p_hg;
    cudaGetSymbolAddress((void**)&p_ws1, g_ws1);     cudaGetSymbolAddress((void**)&p_wb1, g_wb1v);
    cudaGetSymbolAddress((void**)&p_mu_x, g_mu_x);   cudaGetSymbolAddress((void**)&p_rs_x, g_rs_x);
    cudaGetSymbolAddress((void**)&p_A1, g_A1);       cudaGetSymbolAddress((void**)&p_Ao, g_Ao);
    cudaGetSymbolAddress((void**)&p_A2, g_A2);
    cudaGetSymbolAddress((void**)&p_a16, g_a16);     cudaGetSymbolAddress((void**)&p_x16, g_x16);
    cudaGetSymbolAddress((void**)&p_hg, g_hg);

    cudaFuncSetAttribute((void*)gemm_qkv,                    cudaFuncAttributeMaxDynamicSharedMemorySize, GS_128);
    cudaFuncSetAttribute((void*)gemm_mma<4,256,256,256,64>,  cudaFuncAttributeMaxDynamicSharedMemorySize, GS_256);
    cudaFuncSetAttribute((void*)gemm_mma<3,256,FH2,128,128>, cudaFuncAttributeMaxDynamicSharedMemorySize, GS_128);
    cudaFuncSetAttribute((void*)gemm_mma<2,512,256,128,128>, cudaFuncAttributeMaxDynamicSharedMemorySize, GS_128);

    // 1) weight prep (all matrices, one launch)
    prep_fold<<<2560, 256>>>(Wq, Wk, Wv, W1, Wo, W2,
                             gopt, bopt, gsar, bsar, gffn, bffn, b1);

    // 2) LN stats + fp16 conversion (both inputs, one launch)
    ln_conv_kernel<<<dim3((NPIX/2)/128, 2), 512>>>(optical, sar);

    // 3) fused Q + K/V projections -> fp16
    gemm_qkv<<<dim3(32, 6, BB), 256, GS_128>>>();

    // 4) channel attention: 4-way partial S, softmax reduce, A@V
    attn_s_kernel<<<dim3(BB*NHH, NSP), 256>>>();
    attn_softmax_kernel<<<BB*NHH, 1024>>>();
    attn_av_kernel<<<dim3(BB*NHH, (LL/2)/256), 256>>>();

    // 5+6) Wo + residual(optical fp32) + LN stats -> g_x16 (fp16)
    gemm_mma<4,256,256,256,64><<<dim3(64,1,BB),256,GS_256>>>(p_Ao, p_a16, (void*)0, 0, 0, 0, 0, optical, 0);

    // 7) W1 (LN+b1 folded, row-paired) + fused SimpleGate -> hg (fp16)
    gemm_mma<3,256,FH2,128,128><<<dim3(32,8,BB),256,GS_128>>>(p_A1, p_x16, (void*)0, p_mu_x, p_rs_x, p_ws1, p_wb1, 0, 0);

    // 8) W2 + b2 + residual(x16 fp16) -> out fp32
    gemm_mma<2,512,256,128,128><<<dim3(32,2,BB),256,GS_128>>>(p_A2, p_hg, out, 0, 0, 0, 0, p_x16, b2);
}

// round 11
// speedup vs baseline: 5.6507x; 1.1101x over previous
#include <cuda_runtime.h>
#include <cuda_fp16.h>

typedef unsigned int u32;
typedef unsigned long long u64;

#define BB   16
#define CC   256
#define LL   4096
#define NHH  8
#define HCC  32
#define FH   512
#define FH2  1024
#define NPIX (BB*LL)
#define NSP  2

// ---------------------------------------------------------------------------
// Scratch
// ---------------------------------------------------------------------------
__device__ float g_wsq[CC],  g_wbq[CC];
__device__ float g_wskv[2*CC], g_wbkv[2*CC];
__device__ float g_ws1[FH2], g_wb1v[FH2];      // permuted order
__device__ float g_mu_o[NPIX], g_rs_o[NPIX];
__device__ float g_mu_s[NPIX], g_rs_s[NPIX];
__device__ float g_mu_x[NPIX], g_rs_x[NPIX];
__device__ __align__(128) u32 g_Aq[CC*128];
__device__ __align__(128) u32 g_Akv[2*CC*128];
__device__ __align__(128) u32 g_A1[FH2*128];
__device__ __align__(128) u32 g_Ao[CC*128];
__device__ __align__(128) u32 g_A2[CC*256];
__device__ __align__(128) u32 g_o16[BB*CC*(LL/2)];
__device__ __align__(128) u32 g_s16[BB*CC*(LL/2)];
__device__ __align__(128) u32 g_q16[BB*CC*(LL/2)];
__device__ __align__(128) u32 g_kv16[BB*2*CC*(LL/2)];
__device__ __align__(128) u32 g_a16[BB*CC*(LL/2)];
__device__ __align__(128) u32 g_x16[BB*CC*(LL/2)];
__device__ __align__(128) u32 g_hg[BB*FH*(LL/2)];
__device__ __align__(128) float g_Sp[BB*NHH*NSP*HCC*HCC];
__device__ __align__(128) float g_A[BB*NHH*HCC*HCC];

// ---------------------------------------------------------------------------
// PTX helpers
// ---------------------------------------------------------------------------
__device__ __forceinline__ u32 smem_u32(const void* p) {
    u32 a;
    asm("{ .reg .u64 t; cvta.to.shared.u64 t, %1; cvt.u32.u64 %0, t; }" : "=r"(a) : "l"(p));
    return a;
}
#define LDSM_X4(r0,r1,r2,r3,addr) \
    asm volatile("ldmatrix.sync.aligned.m8n8.x4.shared.b16 {%0,%1,%2,%3}, [%4];" \
        : "=r"(r0),"=r"(r1),"=r"(r2),"=r"(r3) : "r"(addr))
#define LDSM_X4_T(r0,r1,r2,r3,addr) \
    asm volatile("ldmatrix.sync.aligned.m8n8.x4.trans.shared.b16 {%0,%1,%2,%3}, [%4];" \
        : "=r"(r0),"=r"(r1),"=r"(r2),"=r"(r3) : "r"(addr))
#define MMA_F16(d, a, b0, b1) \
    asm volatile("mma.sync.aligned.m16n8k16.row.col.f32.f16.f16.f32 " \
        "{%0,%1,%2,%3}, {%4,%5,%6,%7}, {%8,%9}, {%0,%1,%2,%3};" \
        : "+f"((d)[0]),"+f"((d)[1]),"+f"((d)[2]),"+f"((d)[3]) \
        : "r"((a)[0]),"r"((a)[1]),"r"((a)[2]),"r"((a)[3]), "r"(b0),"r"(b1))
#define CP16(dst, src) \
    asm volatile("cp.async.cg.shared.global [%0], [%1], 16;" \
        :: "r"(dst), "l"(src) : "memory")
#define CP_COMMIT() asm volatile("cp.async.commit_group;" ::: "memory")
#define CP_WAIT(n)  asm volatile("cp.async.wait_group %0;" :: "n"(n) : "memory")

__device__ __forceinline__ u32 packf16(float a, float b) {
    __half2 h = __floats2half2_rn(a, b);
    return *(u32*)&h;
}
__device__ __forceinline__ float2 unpackf16(u32 w) {
    __half2 h = *(__half2*)&w;
    return __half22float2(h);
}

// ---------------------------------------------------------------------------
// Prep (all five weight matrices, one launch)
// ---------------------------------------------------------------------------
__global__ void prep_fold(const float* __restrict__ Wq, const float* __restrict__ Wk,
                          const float* __restrict__ Wv, const float* __restrict__ W1,
                          const float* __restrict__ Wo, const float* __restrict__ W2,
                          const float* __restrict__ gopt, const float* __restrict__ bopt,
                          const float* __restrict__ gsar, const float* __restrict__ bsar,
                          const float* __restrict__ gffn, const float* __restrict__ bffn,
                          const float* __restrict__ b1)
{
    int row = blockIdx.x;
    int c   = threadIdx.x;
    if (row >= 1792) {
        float w; u32* dst; int di;
        if (row < 2048) {
            int m = row - 1792;
            w = Wo[m*CC + c];
            dst = g_Ao; di = m*128 + (c>>1);
        } else {
            int r2 = row - 2048;
            int m = r2 >> 1, half = r2 & 1;
            int cg = half*256 + c;
            w = W2[m*512 + cg];
            dst = g_A2; di = m*256 + (cg>>1);
        }
        u32 hu = (u32)__half_as_ushort(__float2half_rn(w));
        u32 hp = __shfl_xor_sync(0xffffffffu, hu, 1);
        if (!(c & 1)) dst[di] = hu | (hp << 16);
        return;
    }
    const float* W; float* ws; float* wb; u32* Ah;
    const float* gg; const float* bb; int m, mdst; float extra = 0.f;
    if (row < 256)      { W=Wq; ws=g_wsq;  wb=g_wbq;  Ah=g_Aq;  gg=gopt; bb=bopt; m=row;     mdst=m; }
    else if (row < 512) { W=Wk; ws=g_wskv; wb=g_wbkv; Ah=g_Akv; gg=gsar; bb=bsar; m=row-256; mdst=m; }
    else if (row < 768) { W=Wv; ws=g_wskv; wb=g_wbkv; Ah=g_Akv; gg=gsar; bb=bsar; m=row-512; mdst=m+256; }
    else {
        W=W1; ws=g_ws1; wb=g_wb1v; Ah=g_A1; gg=gffn; bb=bffn; m=row-768;
        extra = b1[m];
        if (m < FH) mdst = ((m>>3)<<4) + (m&7);
        else        { int mm = m-FH; mdst = ((mm>>3)<<4) + (mm&7) + 8; }
    }
    float w  = W[m*CC + c];
    float wg = w * gg[c];
    u32 hu = (u32)__half_as_ushort(__float2half_rn(wg));
    u32 hp = __shfl_xor_sync(0xffffffffu, hu, 1);
    if (!(c & 1)) Ah[mdst*128 + (c>>1)] = hu | (hp << 16);
    __shared__ float s1[256], s2[256];
    s1[c] = wg; s2[c] = w * bb[c];
    __syncthreads();
    for (int off = 128; off > 0; off >>= 1) {
        if (c < off) { s1[c] += s1[c+off]; s2[c] += s2[c+off]; }
        __syncthreads();
    }
    if (c == 0) { ws[mdst] = s1[0]; wb[mdst] = s2[0] + extra; }
}

// ---------------------------------------------------------------------------
// LN stats + fp16 conversion (both input tensors, one launch)
// ---------------------------------------------------------------------------
__global__ __launch_bounds__(512)
void ln_conv_kernel(const float* __restrict__ x0, const float* __restrict__ x1)
{
    const float* x  = blockIdx.y ? x1 : x0;
    float* mu = blockIdx.y ? g_mu_s : g_mu_o;
    float* rs = blockIdx.y ? g_rs_s : g_rs_o;
    u32* x16  = blockIdx.y ? g_s16 : g_o16;
    __shared__ float ssx[512], ssx2[512], ssy[512], ssy2[512];
    int tid = threadIdx.x;
    int pr = tid & 127, qd = tid >> 7;
    int p2 = blockIdx.x*128 + pr;
    int b = p2 >> 11, l2 = p2 & 2047;
    const float* base = x + (size_t)b*CC*LL + 2*l2;
    u32* oh = x16 + (size_t)b*CC*(LL/2) + l2;
    float sx=0.f, sx2=0.f, sy=0.f, sy2=0.f;
    int c0 = qd*64;
#pragma unroll 8
    for (int i = 0; i < 64; i++) {
        int c = c0 + i;
        float2 v = *(const float2*)(base + (size_t)c*LL);
        sx += v.x; sx2 = fmaf(v.x, v.x, sx2);
        sy += v.y; sy2 = fmaf(v.y, v.y, sy2);
        oh[(size_t)c*(LL/2)] = packf16(v.x, v.y);
    }
    ssx[tid]=sx; ssx2[tid]=sx2; ssy[tid]=sy; ssy2[tid]=sy2;
    __syncthreads();
    if (qd == 0) {
        float tx  = ssx[pr]  + ssx[pr+128]  + ssx[pr+256]  + ssx[pr+384];
        float tx2 = ssx2[pr] + ssx2[pr+128] + ssx2[pr+256] + ssx2[pr+384];
        float ty  = ssy[pr]  + ssy[pr+128]  + ssy[pr+256]  + ssy[pr+384];
        float ty2 = ssy2[pr] + ssy2[pr+128] + ssy2[pr+256] + ssy2[pr+384];
        float mx = tx*(1.f/CC), my = ty*(1.f/CC);
        int p = b*LL + 2*l2;
        mu[p]   = mx; rs[p]   = rsqrtf(fmaf(-mx, mx, tx2*(1.f/CC)) + 1e-5f);
        mu[p+1] = my; rs[p+1] = rsqrtf(fmaf(-my, my, ty2*(1.f/CC)) + 1e-5f);
    }
}

#define A_STR 144

// ---------------------------------------------------------------------------
// Fused Q+KV projection GEMM. grid (32, 6, BB): y<2 -> Q, y>=2 -> KV.
// ---------------------------------------------------------------------------
__global__ __launch_bounds__(256, 2)
void gemm_qkv()
{
    constexpr int KD = 256, MT = 128, NT = 128;
    constexpr int B_STRc = NT*2 + 16;
    constexpr int BS = MT*A_STR;
    constexpr int STAGE = BS + 64*B_STRc;

    extern __shared__ __align__(128) char smem[];
    const u32 sbase = smem_u32(smem);

    int y = blockIdx.y;
    bool isq = (y < 2);
    const u32* Ah   = isq ? g_Aq  : g_Akv;
    const u32* Xp   = isq ? g_o16 : g_s16;
    u32* Y16        = isq ? g_q16 : g_kv16;
    const float* mu = isq ? g_mu_o : g_mu_s;
    const float* rs = isq ? g_rs_o : g_rs_s;
    const float* wsum = isq ? g_wsq : g_wskv;
    const float* wb   = isq ? g_wbq : g_wbkv;
    int md = isq ? 256 : 512;
    int m0 = (isq ? y : y - 2) * MT;

    int tid = threadIdx.x, lane = tid & 31, wid = tid >> 5;
    int n0 = blockIdx.x * NT, b = blockIdx.z;
    int wm = wid >> 2, wn = wid & 3;

    float acc[4][4][4];
#pragma unroll
    for (int i=0;i<4;i++)
#pragma unroll
        for (int j=0;j<4;j++)
#pragma unroll
            for (int r=0;r<4;r++) acc[i][j][r]=0.f;

    const u32* Xb = Xp + (size_t)b*KD*(LL/2) + (n0>>1);
    u32 a_lm_base = sbase + (u32)((wm*64 + (lane & 15)) * A_STR) + ((lane & 16) ? 16u : 0u);
    u32 b_lm_base = sbase + BS + (u32)((lane & 15) * B_STRc)
                  + (u32)((wn*32 + ((lane & 16) ? 8 : 0)) * 2);

#define ISSUEQ(st, kc) do { \
        u32 so = sbase + (u32)((st)*STAGE); \
        _Pragma("unroll") \
        for (int ii = tid; ii < MT*8; ii += 256) { \
            int row = ii >> 3, seg = ii & 7; \
            CP16(so + (u32)(row*A_STR + seg*16), \
                 Ah + (size_t)(m0+row)*(KD/2) + ((kc)>>1) + seg*4); \
        } \
        _Pragma("unroll") \
        for (int ii = tid; ii < 64*16; ii += 256) { \
            int row = ii >> 4, seg = ii & 15; \
            CP16(so + (u32)(BS + row*B_STRc + seg*16), \
                 Xb + (size_t)((kc)+row)*(LL/2) + seg*4); \
        } \
        CP_COMMIT(); \
    } while(0)

    ISSUEQ(0, 0);
#pragma unroll 1
    for (int kc = 0; kc < KD; kc += 64) {
        int cur = (kc >> 6) & 1;
        if (kc + 64 < KD) { ISSUEQ(cur ^ 1, kc + 64); CP_WAIT(1); }
        else              { CP_WAIT(0); }
        __syncthreads();
        u32 so = (u32)(cur * STAGE);
#pragma unroll
        for (int ks = 0; ks < 64; ks += 16) {
            u32 af[4][4], bf[4][2];
            u32 ab = a_lm_base + so + (u32)(ks*2);
#pragma unroll
            for (int i = 0; i < 4; i++)
                LDSM_X4(af[i][0], af[i][1], af[i][2], af[i][3], ab + (u32)(i*16*A_STR));
            u32 bb0 = b_lm_base + so + (u32)(ks*B_STRc);
#pragma unroll
            for (int j2 = 0; j2 < 2; j2++)
                LDSM_X4_T(bf[j2*2][0], bf[j2*2][1], bf[j2*2+1][0], bf[j2*2+1][1], bb0 + (u32)(j2*32));
#pragma unroll
            for (int i = 0; i < 4; i++)
#pragma unroll
                for (int j = 0; j < 4; j++)
                    MMA_F16(acc[i][j], af[i], bf[j][0], bf[j][1]);
        }
        __syncthreads();
    }
#undef ISSUEQ

#pragma unroll
    for (int i = 0; i < 4; i++) {
        int r0 = m0 + wm*64 + i*16 + (lane >> 2);
        int r1 = r0 + 8;
        float ws0 = wsum[r0], wb0 = wb[r0];
        float ws1v = wsum[r1], wb1 = wb[r1];
#pragma unroll
        for (int j = 0; j < 4; j++) {
            int c0 = n0 + wn*32 + j*8 + 2*(lane & 3);
            int p0 = b*LL + c0;
            float2 m2 = *(const float2*)(mu + p0);
            float2 s2 = *(const float2*)(rs + p0);
            float o0x = s2.x*(acc[i][j][0] - m2.x*ws0) + wb0;
            float o0y = s2.y*(acc[i][j][1] - m2.y*ws0) + wb0;
            float o1x = s2.x*(acc[i][j][2] - m2.x*ws1v) + wb1;
            float o1y = s2.y*(acc[i][j][3] - m2.y*ws1v) + wb1;
            Y16[((size_t)b*md + r0)*(LL/2) + (c0>>1)] = packf16(o0x, o0y);
            Y16[((size_t)b*md + r1)*(LL/2) + (c0>>1)] = packf16(o1x, o1y);
        }
    }
}

// ---------------------------------------------------------------------------
// General GEMM (modes 2/3/4)
// ---------------------------------------------------------------------------
template<int MODE, int KD, int MD, int MT, int NT>
__global__ __launch_bounds__(256, 2)
void gemm_mma(const u32* __restrict__ Ah,
              const u32* __restrict__ Xp,
              void* __restrict__ Yv,
              const float* __restrict__ mu, const float* __restrict__ rs,
              const float* __restrict__ wsum, const float* __restrict__ wb,
              const void* __restrict__ res, const float* __restrict__ bias)
{
    constexpr int B_STRc = NT*2 + 16;
    constexpr int BS = MT*A_STR;
    constexpr int STAGE = MT*A_STR + 64*B_STRc;
    constexpr int WN = (MT == 128) ? 4 : 2;
    constexpr int BSEG = NT/8;

    extern __shared__ __align__(128) char smem[];
    const u32 sbase = smem_u32(smem);

    int tid = threadIdx.x, lane = tid & 31, wid = tid >> 5;
    int n0 = blockIdx.x * NT, m0 = blockIdx.y * MT, b = blockIdx.z;
    int wm = wid / WN, wn = wid % WN;

    float acc[4][4][4];
#pragma unroll
    for (int i=0;i<4;i++)
#pragma unroll
        for (int j=0;j<4;j++)
#pragma unroll
            for (int r=0;r<4;r++) acc[i][j][r]=0.f;

    const u32* Xb = Xp + (size_t)b*KD*(LL/2) + (n0>>1);

    u32 a_lm_base = sbase + (u32)((wm*64 + (lane & 15)) * A_STR) + ((lane & 16) ? 16u : 0u);
    u32 b_lm_base = sbase + BS + (u32)((lane & 15) * B_STRc)
                  + (u32)((wn*32 + ((lane & 16) ? 8 : 0)) * 2);

#define ISSUE(st, kc) do { \
        u32 so = sbase + (u32)((st)*STAGE); \
        _Pragma("unroll") \
        for (int ii = tid; ii < MT*8; ii += 256) { \
            int row = ii >> 3, seg = ii & 7; \
            CP16(so + (u32)(row*A_STR + seg*16), \
                 Ah + (size_t)(m0+row)*(KD/2) + ((kc)>>1) + seg*4); \
        } \
        _Pragma("unroll") \
        for (int ii = tid; ii < 64*BSEG; ii += 256) { \
            int row = ii / BSEG, seg = ii % BSEG; \
            CP16(so + (u32)(BS + row*B_STRc + seg*16), \
                 Xb + (size_t)((kc)+row)*(LL/2) + seg*4); \
        } \
        CP_COMMIT(); \
    } while(0)

    ISSUE(0, 0);

#pragma unroll 1
    for (int kc = 0; kc < KD; kc += 64) {
        int cur = (kc >> 6) & 1;
        if (kc + 64 < KD) { ISSUE(cur ^ 1, kc + 64); CP_WAIT(1); }
        else              { CP_WAIT(0); }
        __syncthreads();
        u32 so = (u32)(cur * STAGE);
#pragma unroll
        for (int ks = 0; ks < 64; ks += 16) {
            u32 af[4][4], bf[4][2];
            u32 ab = a_lm_base + so + (u32)(ks*2);
#pragma unroll
            for (int i = 0; i < 4; i++)
                LDSM_X4(af[i][0], af[i][1], af[i][2], af[i][3], ab + (u32)(i*16*A_STR));
            u32 bb0 = b_lm_base + so + (u32)(ks*B_STRc);
#pragma unroll
            for (int j2 = 0; j2 < 2; j2++)
                LDSM_X4_T(bf[j2*2][0], bf[j2*2][1], bf[j2*2+1][0], bf[j2*2+1][1], bb0 + (u32)(j2*32));
#pragma unroll
            for (int i = 0; i < 4; i++)
#pragma unroll
                for (int j = 0; j < 4; j++)
                    MMA_F16(acc[i][j], af[i], bf[j][0], bf[j][1]);
        }
        __syncthreads();
    }
#undef ISSUE

    float* Y = (float*)Yv;
    float cs[4][4];
    if (MODE == 4) {
#pragma unroll
        for (int j=0;j<4;j++)
#pragma unroll
            for (int k=0;k<4;k++) cs[j][k]=0.f;
    }
#pragma unroll
    for (int i = 0; i < 4; i++) {
        int r0 = m0 + wm*64 + i*16 + (lane >> 2);
        int r1 = r0 + 8;
        if (MODE == 3) {
            int t = ((r0 >> 4) << 3) + (r0 & 7);
            float ws1 = wsum[r0], wb1 = wb[r0];
            float ws2 = wsum[r1], wb2 = wb[r1];
#pragma unroll
            for (int j = 0; j < 4; j++) {
                int c0 = n0 + wn*32 + j*8 + 2*(lane & 3);
                int p0 = b*LL + c0;
                float2 m2 = *(const float2*)(mu + p0);
                float2 s2 = *(const float2*)(rs + p0);
                float e1x = s2.x*(acc[i][j][0] - m2.x*ws1) + wb1;
                float e1y = s2.y*(acc[i][j][1] - m2.y*ws1) + wb1;
                float e2x = s2.x*(acc[i][j][2] - m2.x*ws2) + wb2;
                float e2y = s2.y*(acc[i][j][3] - m2.y*ws2) + wb2;
                g_hg[((size_t)b*FH + t)*(LL/2) + (c0 >> 1)] = packf16(e1x*e2x, e1y*e2y);
            }
        } else if (MODE == 4) {
            const float* rf = (const float*)res;
#pragma unroll
            for (int j = 0; j < 4; j++) {
                int c0 = n0 + wn*32 + j*8 + 2*(lane & 3);
                const float* q0 = rf + (size_t)b*MD*LL + (size_t)r0*LL + c0;
                const float* q1 = rf + (size_t)b*MD*LL + (size_t)r1*LL + c0;
                float2 a0 = *(const float2*)q0, a1 = *(const float2*)q1;
                float y00 = acc[i][j][0] + a0.x, y01 = acc[i][j][1] + a0.y;
                float y10 = acc[i][j][2] + a1.x, y11 = acc[i][j][3] + a1.y;
                g_x16[((size_t)b*MD + r0)*(LL/2) + (c0>>1)] = packf16(y00, y01);
                g_x16[((size_t)b*MD + r1)*(LL/2) + (c0>>1)] = packf16(y10, y11);
                cs[j][0] += y00 + y10;
                cs[j][1] += y00*y00 + y10*y10;
                cs[j][2] += y01 + y11;
                cs[j][3] += y01*y01 + y11*y11;
            }
        } else { // MODE 2
            const u32* r16 = (const u32*)res;
            float bv0 = bias[r0], bv1 = bias[r1];
#pragma unroll
            for (int j = 0; j < 4; j++) {
                int c0 = n0 + wn*32 + j*8 + 2*(lane & 3);
                float2 a0 = unpackf16(r16[((size_t)b*MD + r0)*(LL/2) + (c0>>1)]);
                float2 a1 = unpackf16(r16[((size_t)b*MD + r1)*(LL/2) + (c0>>1)]);
                float* y0 = Y + (size_t)b*MD*LL + (size_t)r0*LL + c0;
                float* y1 = Y + (size_t)b*MD*LL + (size_t)r1*LL + c0;
                *(float2*)y0 = make_float2(acc[i][j][0] + bv0 + a0.x, acc[i][j][1] + bv0 + a0.y);
                *(float2*)y1 = make_float2(acc[i][j][2] + bv1 + a1.x, acc[i][j][3] + bv1 + a1.y);
            }
        }
    }
    if (MODE == 4) {
        float4 (*red)[32] = (float4(*)[32])smem;
#pragma unroll
        for (int j = 0; j < 4; j++)
#pragma unroll
            for (int o = 4; o < 32; o <<= 1) {
                cs[j][0] += __shfl_xor_sync(0xffffffffu, cs[j][0], o);
                cs[j][1] += __shfl_xor_sync(0xffffffffu, cs[j][1], o);
                cs[j][2] += __shfl_xor_sync(0xffffffffu, cs[j][2], o);
                cs[j][3] += __shfl_xor_sync(0xffffffffu, cs[j][3], o);
            }
        if (lane < 4) {
#pragma unroll
            for (int j = 0; j < 4; j++) {
                int cp = wn*16 + j*4 + lane;
                red[wm][cp] = make_float4(cs[j][0], cs[j][1], cs[j][2], cs[j][3]);
            }
        }
        __syncthreads();
        if (tid < 32) {
            float4 t0 = red[0][tid], t1 = red[1][tid], t2 = red[2][tid], t3 = red[3][tid];
            float sx  = t0.x+t1.x+t2.x+t3.x;
            float sx2 = t0.y+t1.y+t2.y+t3.y;
            float sy  = t0.z+t1.z+t2.z+t3.z;
            float sy2 = t0.w+t1.w+t2.w+t3.w;
            float mx = sx*(1.f/CC), my = sy*(1.f/CC);
            int p = b*LL + n0 + 2*tid;
            g_mu_x[p]   = mx; g_rs_x[p]   = rsqrtf(fmaf(-mx, mx, sx2*(1.f/CC)) + 1e-5f);
            g_mu_x[p+1] = my; g_rs_x[p+1] = rsqrtf(fmaf(-my, my, sy2*(1.f/CC)) + 1e-5f);
        }
    }
}

// ---------------------------------------------------------------------------
// Attention S via mma.sync. grid (BB*NHH, NSP=2), 256 threads (8 warps).
// Each warp handles a 32-l slice of 256-l double-buffered chunks; partials
// reduced across warps in smem at the end.
// Q tile [32 c][256 l] fp16 row-major; K tile [32 d][256 l] — B fragments
// loaded with NON-transposed ldmatrix (see address pattern below).
// ---------------------------------------------------------------------------
#define QSTR 528
#define ATILE (32*QSTR)            // 16896
#define ASTAGE (2*ATILE)           // 33792  (Q + K per stage)
#define AS_SMEM (2*ASTAGE)         // 67584

__global__ __launch_bounds__(256, 2)
void attn_s_kernel()
{
    extern __shared__ __align__(128) char smem[];
    const u32 sbase = smem_u32(smem);
    int bh = blockIdx.x, sp = blockIdx.y;
    int b = bh >> 3, h = bh & 7;
    int tid = threadIdx.x, lane = tid & 31, wid = tid >> 5;
    const u32* qp = g_q16  + ((size_t)b*CC   + h*HCC)*(LL/2) + sp*1024;
    const u32* kp = g_kv16 + ((size_t)b*2*CC + h*HCC)*(LL/2) + sp*1024;

    float acc[2][4][4];
#pragma unroll
    for (int i=0;i<2;i++)
#pragma unroll
        for (int j=0;j<4;j++)
#pragma unroll
            for (int r=0;r<4;r++) acc[i][j][r]=0.f;

#define ISSUEA(st, ch) do { \
        u32 so = sbase + (u32)((st)*ASTAGE); \
        _Pragma("unroll") \
        for (int ii = tid; ii < 1024; ii += 256) { \
            int row = ii >> 5, seg = ii & 31; \
            CP16(so + (u32)(row*QSTR + seg*16), \
                 qp + (size_t)row*(LL/2) + (ch)*128 + seg*4); \
            CP16(so + (u32)(ATILE + row*QSTR + seg*16), \
                 kp + (size_t)row*(LL/2) + (ch)*128 + seg*4); \
        } \
        CP_COMMIT(); \
    } while(0)

    ISSUEA(0, 0);
    // warp's l-slice within chunk: bytes wid*64 (32 l = 64B)
    u32 woff = (u32)(wid * 64);
#pragma unroll 1
    for (int ch = 0; ch < 8; ch++) {
        int cur = ch & 1;
        if (ch + 1 < 8) { ISSUEA(cur ^ 1, ch + 1); CP_WAIT(1); }
        else            { CP_WAIT(0); }
        __syncthreads();
        u32 qb = sbase + (u32)(cur*ASTAGE);
        u32 kb = qb + ATILE;
#pragma unroll
        for (int s = 0; s < 2; s++) {
            u32 koff = woff + (u32)(s*32);
            u32 af[2][4], bf[4][2];
            u32 aaddr = qb + (u32)((lane & 15)*QSTR) + ((lane & 16) ? 16u : 0u) + koff;
            LDSM_X4(af[0][0], af[0][1], af[0][2], af[0][3], aaddr);
            LDSM_X4(af[1][0], af[1][1], af[1][2], af[1][3], aaddr + (u32)(16*QSTR));
            // B (non-trans): lanes 0-7 -> n0-7@k0 | 8-15 -> n0-7@k8 | 16-23 -> n8-15@k0 | 24-31 -> n8-15@k8
            u32 baddr = kb + (u32)(((lane & 7) + ((lane & 16) ? 8 : 0))*QSTR)
                      + ((lane & 8) ? 16u : 0u) + koff;
            LDSM_X4(bf[0][0], bf[0][1], bf[1][0], bf[1][1], baddr);
            LDSM_X4(bf[2][0], bf[2][1], bf[3][0], bf[3][1], baddr + (u32)(16*QSTR));
#pragma unroll
            for (int i = 0; i < 2; i++)
#pragma unroll
                for (int j = 0; j < 4; j++)
                    MMA_F16(acc[i][j], af[i], bf[j][0], bf[j][1]);
        }
        __syncthreads();
    }
#undef ISSUEA

    // write warp partials (reuse smem) and reduce
    float* part = (float*)smem;
#pragma unroll
    for (int i = 0; i < 2; i++)
#pragma unroll
        for (int j = 0; j < 4; j++)
#pragma unroll
            for (int r = 0; r < 4; r++) {
                int row = i*16 + (lane >> 2) + ((r & 2) ? 8 : 0);
                int col = j*8 + (lane & 3)*2 + (r & 1);
                part[wid*1024 + row*32 + col] = acc[i][j][r];
            }
    __syncthreads();
    float* out = g_Sp + ((size_t)bh*NSP + sp)*1024;
#pragma unroll
    for (int e = tid; e < 1024; e += 256) {
        float s = 0.f;
#pragma unroll
        for (int w = 0; w < 8; w++) s += part[w*1024 + e];
        out[e] = s;
    }
}

__global__ void attn_softmax_kernel()   // grid BB*NHH, 1024 threads
{
    int bh = blockIdx.x, t = threadIdx.x;
    const float* sp = g_Sp + (size_t)bh*NSP*1024 + t;
    float s = sp[0] + sp[1024];
    s *= 0.17677669529663687f;
    float mx = s;
#pragma unroll
    for (int o = 16; o > 0; o >>= 1) mx = fmaxf(mx, __shfl_xor_sync(0xffffffffu, mx, o));
    float e = expf(s - mx);
    float sum = e;
#pragma unroll
    for (int o = 16; o > 0; o >>= 1) sum += __shfl_xor_sync(0xffffffffu, sum, o);
    g_A[(size_t)bh*1024 + t] = e / sum;
}

__global__ __launch_bounds__(256)
void attn_av_kernel()
{
    __shared__ float As[1024];
    int bh = blockIdx.x;
    int b = bh >> 3, h = bh & 7;
    int tid = threadIdx.x;
#pragma unroll
    for (int i = 0; i < 4; i++) As[tid + 256*i] = g_A[(size_t)bh*1024 + tid + 256*i];
    __syncthreads();
    int c2 = blockIdx.y*256 + tid;
    const u32* vp = g_kv16 + ((size_t)b*2*CC + CC + h*HCC)*(LL/2) + c2;
    float acc0[32], acc1[32];
#pragma unroll
    for (int c = 0; c < 32; c++) { acc0[c]=0.f; acc1[c]=0.f; }
#pragma unroll 4
    for (int d = 0; d < 32; d++) {
        float2 v = unpackf16(vp[(size_t)d*(LL/2)]);
#pragma unroll
        for (int c = 0; c < 32; c++) {
            float a = As[c*32+d];
            acc0[c] = fmaf(a, v.x, acc0[c]);
            acc1[c] = fmaf(a, v.y, acc1[c]);
        }
    }
#pragma unroll
    for (int c = 0; c < 32; c++) {
        g_a16[((size_t)b*CC + h*HCC + c)*(LL/2) + c2] = packf16(acc0[c], acc1[c]);
    }
}

// ---------------------------------------------------------------------------
// Launcher
// ---------------------------------------------------------------------------
#define GS_128 (2*(128*A_STR + 64*(128*2+16)))   // 71680
#define GS_256 (2*(256*A_STR + 64*(64*2+16)))    // 92160

extern "C" void kernel_launch(void* const* d_in, const int* in_sizes, int n_in,
                              void* d_out, int out_size)
{
    (void)in_sizes; (void)n_in; (void)out_size;
    const float* optical = (const float*)d_in[0];
    const float* sar     = (const float*)d_in[1];
    const float* gopt    = (const float*)d_in[2];
    const float* bopt    = (const float*)d_in[3];
    const float* gsar    = (const float*)d_in[4];
    const float* bsar    = (const float*)d_in[5];
    const float* Wq      = (const float*)d_in[6];
    const float* Wk      = (const float*)d_in[7];
    const float* Wv      = (const float*)d_in[8];
    const float* Wo      = (const float*)d_in[9];
    const float* gffn    = (const float*)d_in[10];
    const float* bffn    = (const float*)d_in[11];
    const float* W1      = (const float*)d_in[12];
    const float* b1      = (const float*)d_in[13];
    const float* W2      = (const float*)d_in[14];
    const float* b2      = (const float*)d_in[15];
    float* out = (float*)d_out;

    float *p_ws1,*p_wb1,*p_mu_x,*p_rs_x;
    u32 *p_A1,*p_Ao,*p_A2,*p_a16,*p_x16,*p_hg;
    cudaGetSymbolAddress((void**)&p_ws1, g_ws1);     cudaGetSymbolAddress((void**)&p_wb1, g_wb1v);
    cudaGetSymbolAddress((void**)&p_mu_x, g_mu_x);   cudaGetSymbolAddress((void**)&p_rs_x, g_rs_x);
    cudaGetSymbolAddress((void**)&p_A1, g_A1);       cudaGetSymbolAddress((void**)&p_Ao, g_Ao);
    cudaGetSymbolAddress((void**)&p_A2, g_A2);
    cudaGetSymbolAddress((void**)&p_a16, g_a16);     cudaGetSymbolAddress((void**)&p_x16, g_x16);
    cudaGetSymbolAddress((void**)&p_hg, g_hg);

    cudaFuncSetAttribute((void*)gemm_qkv,                    cudaFuncAttributeMaxDynamicSharedMemorySize, GS_128);
    cudaFuncSetAttribute((void*)gemm_mma<4,256,256,256,64>,  cudaFuncAttributeMaxDynamicSharedMemorySize, GS_256);
    cudaFuncSetAttribute((void*)gemm_mma<3,256,FH2,128,128>, cudaFuncAttributeMaxDynamicSharedMemorySize, GS_128);
    cudaFuncSetAttribute((void*)gemm_mma<2,512,256,128,128>, cudaFuncAttributeMaxDynamicSharedMemorySize, GS_128);
    cudaFuncSetAttribute((void*)attn_s_kernel,               cudaFuncAttributeMaxDynamicSharedMemorySize, AS_SMEM);

    // 1) weight prep (one launch)
    prep_fold<<<2560, 256>>>(Wq, Wk, Wv, W1, Wo, W2,
                             gopt, bopt, gsar, bsar, gffn, bffn, b1);

    // 2) LN stats + fp16 conversion (both inputs, one launch)
    ln_conv_kernel<<<dim3((NPIX/2)/128, 2), 512>>>(optical, sar);

    // 3) fused Q + K/V projections -> fp16
    gemm_qkv<<<dim3(32, 6, BB), 256, GS_128>>>();

    // 4) channel attention: MMA partial S (2 L-splits), softmax reduce, A@V
    attn_s_kernel<<<dim3(BB*NHH, NSP), 256, AS_SMEM>>>();
    attn_softmax_kernel<<<BB*NHH, 1024>>>();
    attn_av_kernel<<<dim3(BB*NHH, (LL/2)/256), 256>>>();

    // 5+6) Wo + residual(optical fp32) + LN stats -> g_x16 (fp16)
    gemm_mma<4,256,256,256,64><<<dim3(64,1,BB),256,GS_256>>>(p_Ao, p_a16, (void*)0, 0, 0, 0, 0, optical, 0);

    // 7) W1 (LN+b1 folded, row-paired) + fused SimpleGate -> hg (fp16)
    gemm_mma<3,256,FH2,128,128><<<dim3(32,8,BB),256,GS_128>>>(p_A1, p_x16, (void*)0, p_mu_x, p_rs_x, p_ws1, p_wb1, 0, 0);

    // 8) W2 + b2 + residual(x16 fp16) -> out fp32
    gemm_mma<2,512,256,128,128><<<dim3(32,2,BB),256,GS_128>>>(p_A2, p_hg, out, 0, 0, 0, 0, p_x16, b2);
}

// round 12
// speedup vs baseline: 6.3828x; 1.1296x over previous
#include <cuda_runtime.h>
#include <cuda_fp16.h>

typedef unsigned int u32;
typedef unsigned long long u64;

#define BB   16
#define CC   256
#define LL   4096
#define NHH  8
#define HCC  32
#define FH   512
#define FH2  1024
#define NPIX (BB*LL)
#define NSP  2

// ---------------------------------------------------------------------------
// Scratch
// ---------------------------------------------------------------------------
__device__ float g_wsq[CC],  g_wbq[CC];
__device__ float g_wskv[2*CC], g_wbkv[2*CC];
__device__ float g_ws1[FH2], g_wb1v[FH2];
__device__ float g_mu_o[NPIX], g_rs_o[NPIX];
__device__ float g_mu_s[NPIX], g_rs_s[NPIX];
__device__ float g_mu_x[NPIX], g_rs_x[NPIX];
__device__ __align__(128) u32 g_Aq[CC*128];
__device__ __align__(128) u32 g_Akv[2*CC*128];
__device__ __align__(128) u32 g_A1[FH2*128];
__device__ __align__(128) u32 g_Ao[CC*128];
__device__ __align__(128) u32 g_A2[CC*256];
__device__ __align__(128) u32 g_o16[BB*CC*(LL/2)];
__device__ __align__(128) u32 g_s16[BB*CC*(LL/2)];
__device__ __align__(128) u32 g_q16[BB*CC*(LL/2)];
__device__ __align__(128) u32 g_kv16[BB*2*CC*(LL/2)];
__device__ __align__(128) u32 g_x16[BB*CC*(LL/2)];
__device__ __align__(128) u32 g_hg[BB*FH*(LL/2)];
__device__ __align__(128) float g_Sp[BB*NHH*NSP*HCC*HCC];
__device__ __align__(128) u32 g_A16[BB*NHH*HCC*(HCC/2)];   // softmaxed A, fp16 packed [c][d/2]

// ---------------------------------------------------------------------------
// PTX helpers
// ---------------------------------------------------------------------------
__device__ __forceinline__ u32 smem_u32(const void* p) {
    u32 a;
    asm("{ .reg .u64 t; cvta.to.shared.u64 t, %1; cvt.u32.u64 %0, t; }" : "=r"(a) : "l"(p));
    return a;
}
#define LDSM_X4(r0,r1,r2,r3,addr) \
    asm volatile("ldmatrix.sync.aligned.m8n8.x4.shared.b16 {%0,%1,%2,%3}, [%4];" \
        : "=r"(r0),"=r"(r1),"=r"(r2),"=r"(r3) : "r"(addr))
#define LDSM_X4_T(r0,r1,r2,r3,addr) \
    asm volatile("ldmatrix.sync.aligned.m8n8.x4.trans.shared.b16 {%0,%1,%2,%3}, [%4];" \
        : "=r"(r0),"=r"(r1),"=r"(r2),"=r"(r3) : "r"(addr))
#define MMA_F16(d, a, b0, b1) \
    asm volatile("mma.sync.aligned.m16n8k16.row.col.f32.f16.f16.f32 " \
        "{%0,%1,%2,%3}, {%4,%5,%6,%7}, {%8,%9}, {%0,%1,%2,%3};" \
        : "+f"((d)[0]),"+f"((d)[1]),"+f"((d)[2]),"+f"((d)[3]) \
        : "r"((a)[0]),"r"((a)[1]),"r"((a)[2]),"r"((a)[3]), "r"(b0),"r"(b1))
#define CP16(dst, src) \
    asm volatile("cp.async.cg.shared.global [%0], [%1], 16;" \
        :: "r"(dst), "l"(src) : "memory")
#define CP_COMMIT() asm volatile("cp.async.commit_group;" ::: "memory")
#define CP_WAIT(n)  asm volatile("cp.async.wait_group %0;" :: "n"(n) : "memory")

__device__ __forceinline__ u32 packf16(float a, float b) {
    __half2 h = __floats2half2_rn(a, b);
    return *(u32*)&h;
}
__device__ __forceinline__ float2 unpackf16(u32 w) {
    __half2 h = *(__half2*)&w;
    return __half22float2(h);
}

// ---------------------------------------------------------------------------
// Prep (all five weight matrices, one launch)
// ---------------------------------------------------------------------------
__global__ void prep_fold(const float* __restrict__ Wq, const float* __restrict__ Wk,
                          const float* __restrict__ Wv, const float* __restrict__ W1,
                          const float* __restrict__ Wo, const float* __restrict__ W2,
                          const float* __restrict__ gopt, const float* __restrict__ bopt,
                          const float* __restrict__ gsar, const float* __restrict__ bsar,
                          const float* __restrict__ gffn, const float* __restrict__ bffn,
                          const float* __restrict__ b1)
{
    int row = blockIdx.x;
    int c   = threadIdx.x;
    if (row >= 1792) {
        float w; u32* dst; int di;
        if (row < 2048) {
            int m = row - 1792;
            w = Wo[m*CC + c];
            dst = g_Ao; di = m*128 + (c>>1);
        } else {
            int r2 = row - 2048;
            int m = r2 >> 1, half = r2 & 1;
            int cg = half*256 + c;
            w = W2[m*512 + cg];
            dst = g_A2; di = m*256 + (cg>>1);
        }
        u32 hu = (u32)__half_as_ushort(__float2half_rn(w));
        u32 hp = __shfl_xor_sync(0xffffffffu, hu, 1);
        if (!(c & 1)) dst[di] = hu | (hp << 16);
        return;
    }
    const float* W; float* ws; float* wb; u32* Ah;
    const float* gg; const float* bb; int m, mdst; float extra = 0.f;
    if (row < 256)      { W=Wq; ws=g_wsq;  wb=g_wbq;  Ah=g_Aq;  gg=gopt; bb=bopt; m=row;     mdst=m; }
    else if (row < 512) { W=Wk; ws=g_wskv; wb=g_wbkv; Ah=g_Akv; gg=gsar; bb=bsar; m=row-256; mdst=m; }
    else if (row < 768) { W=Wv; ws=g_wskv; wb=g_wbkv; Ah=g_Akv; gg=gsar; bb=bsar; m=row-512; mdst=m+256; }
    else {
        W=W1; ws=g_ws1; wb=g_wb1v; Ah=g_A1; gg=gffn; bb=bffn; m=row-768;
        extra = b1[m];
        if (m < FH) mdst = ((m>>3)<<4) + (m&7);
        else        { int mm = m-FH; mdst = ((mm>>3)<<4) + (mm&7) + 8; }
    }
    float w  = W[m*CC + c];
    float wg = w * gg[c];
    u32 hu = (u32)__half_as_ushort(__float2half_rn(wg));
    u32 hp = __shfl_xor_sync(0xffffffffu, hu, 1);
    if (!(c & 1)) Ah[mdst*128 + (c>>1)] = hu | (hp << 16);
    __shared__ float s1[256], s2[256];
    s1[c] = wg; s2[c] = w * bb[c];
    __syncthreads();
    for (int off = 128; off > 0; off >>= 1) {
        if (c < off) { s1[c] += s1[c+off]; s2[c] += s2[c+off]; }
        __syncthreads();
    }
    if (c == 0) { ws[mdst] = s1[0]; wb[mdst] = s2[0] + extra; }
}

// ---------------------------------------------------------------------------
// LN stats + fp16 conversion (both input tensors, one launch)
// ---------------------------------------------------------------------------
__global__ __launch_bounds__(512)
void ln_conv_kernel(const float* __restrict__ x0, const float* __restrict__ x1)
{
    const float* x  = blockIdx.y ? x1 : x0;
    float* mu = blockIdx.y ? g_mu_s : g_mu_o;
    float* rs = blockIdx.y ? g_rs_s : g_rs_o;
    u32* x16  = blockIdx.y ? g_s16 : g_o16;
    __shared__ float ssx[512], ssx2[512], ssy[512], ssy2[512];
    int tid = threadIdx.x;
    int pr = tid & 127, qd = tid >> 7;
    int p2 = blockIdx.x*128 + pr;
    int b = p2 >> 11, l2 = p2 & 2047;
    const float* base = x + (size_t)b*CC*LL + 2*l2;
    u32* oh = x16 + (size_t)b*CC*(LL/2) + l2;
    float sx=0.f, sx2=0.f, sy=0.f, sy2=0.f;
    int c0 = qd*64;
#pragma unroll 8
    for (int i = 0; i < 64; i++) {
        int c = c0 + i;
        float2 v = *(const float2*)(base + (size_t)c*LL);
        sx += v.x; sx2 = fmaf(v.x, v.x, sx2);
        sy += v.y; sy2 = fmaf(v.y, v.y, sy2);
        oh[(size_t)c*(LL/2)] = packf16(v.x, v.y);
    }
    ssx[tid]=sx; ssx2[tid]=sx2; ssy[tid]=sy; ssy2[tid]=sy2;
    __syncthreads();
    if (qd == 0) {
        float tx  = ssx[pr]  + ssx[pr+128]  + ssx[pr+256]  + ssx[pr+384];
        float tx2 = ssx2[pr] + ssx2[pr+128] + ssx2[pr+256] + ssx2[pr+384];
        float ty  = ssy[pr]  + ssy[pr+128]  + ssy[pr+256]  + ssy[pr+384];
        float ty2 = ssy2[pr] + ssy2[pr+128] + ssy2[pr+256] + ssy2[pr+384];
        float mx = tx*(1.f/CC), my = ty*(1.f/CC);
        int p = b*LL + 2*l2;
        mu[p]   = mx; rs[p]   = rsqrtf(fmaf(-mx, mx, tx2*(1.f/CC)) + 1e-5f);
        mu[p+1] = my; rs[p+1] = rsqrtf(fmaf(-my, my, ty2*(1.f/CC)) + 1e-5f);
    }
}

#define A_STR 144

// ---------------------------------------------------------------------------
// Fused Q+KV projection GEMM. grid (32, 6, BB): y<2 -> Q, y>=2 -> KV.
// ---------------------------------------------------------------------------
__global__ __launch_bounds__(256, 2)
void gemm_qkv()
{
    constexpr int KD = 256, MT = 128, NT = 128;
    constexpr int B_STRc = NT*2 + 16;
    constexpr int BS = MT*A_STR;
    constexpr int STAGE = BS + 64*B_STRc;

    extern __shared__ __align__(128) char smem[];
    const u32 sbase = smem_u32(smem);

    int y = blockIdx.y;
    bool isq = (y < 2);
    const u32* Ah   = isq ? g_Aq  : g_Akv;
    const u32* Xp   = isq ? g_o16 : g_s16;
    u32* Y16        = isq ? g_q16 : g_kv16;
    const float* mu = isq ? g_mu_o : g_mu_s;
    const float* rs = isq ? g_rs_o : g_rs_s;
    const float* wsum = isq ? g_wsq : g_wskv;
    const float* wb   = isq ? g_wbq : g_wbkv;
    int md = isq ? 256 : 512;
    int m0 = (isq ? y : y - 2) * MT;

    int tid = threadIdx.x, lane = tid & 31, wid = tid >> 5;
    int n0 = blockIdx.x * NT, b = blockIdx.z;
    int wm = wid >> 2, wn = wid & 3;

    float acc[4][4][4];
#pragma unroll
    for (int i=0;i<4;i++)
#pragma unroll
        for (int j=0;j<4;j++)
#pragma unroll
            for (int r=0;r<4;r++) acc[i][j][r]=0.f;

    const u32* Xb = Xp + (size_t)b*KD*(LL/2) + (n0>>1);
    u32 a_lm_base = sbase + (u32)((wm*64 + (lane & 15)) * A_STR) + ((lane & 16) ? 16u : 0u);
    u32 b_lm_base = sbase + BS + (u32)((lane & 15) * B_STRc)
                  + (u32)((wn*32 + ((lane & 16) ? 8 : 0)) * 2);

#define ISSUEQ(st, kc) do { \
        u32 so = sbase + (u32)((st)*STAGE); \
        _Pragma("unroll") \
        for (int ii = tid; ii < MT*8; ii += 256) { \
            int row = ii >> 3, seg = ii & 7; \
            CP16(so + (u32)(row*A_STR + seg*16), \
                 Ah + (size_t)(m0+row)*(KD/2) + ((kc)>>1) + seg*4); \
        } \
        _Pragma("unroll") \
        for (int ii = tid; ii < 64*16; ii += 256) { \
            int row = ii >> 4, seg = ii & 15; \
            CP16(so + (u32)(BS + row*B_STRc + seg*16), \
                 Xb + (size_t)((kc)+row)*(LL/2) + seg*4); \
        } \
        CP_COMMIT(); \
    } while(0)

    ISSUEQ(0, 0);
#pragma unroll 1
    for (int kc = 0; kc < KD; kc += 64) {
        int cur = (kc >> 6) & 1;
        if (kc + 64 < KD) { ISSUEQ(cur ^ 1, kc + 64); CP_WAIT(1); }
        else              { CP_WAIT(0); }
        __syncthreads();
        u32 so = (u32)(cur * STAGE);
#pragma unroll
        for (int ks = 0; ks < 64; ks += 16) {
            u32 af[4][4], bf[4][2];
            u32 ab = a_lm_base + so + (u32)(ks*2);
#pragma unroll
            for (int i = 0; i < 4; i++)
                LDSM_X4(af[i][0], af[i][1], af[i][2], af[i][3], ab + (u32)(i*16*A_STR));
            u32 bb0 = b_lm_base + so + (u32)(ks*B_STRc);
#pragma unroll
            for (int j2 = 0; j2 < 2; j2++)
                LDSM_X4_T(bf[j2*2][0], bf[j2*2][1], bf[j2*2+1][0], bf[j2*2+1][1], bb0 + (u32)(j2*32));
#pragma unroll
            for (int i = 0; i < 4; i++)
#pragma unroll
                for (int j = 0; j < 4; j++)
                    MMA_F16(acc[i][j], af[i], bf[j][0], bf[j][1]);
        }
        __syncthreads();
    }
#undef ISSUEQ

#pragma unroll
    for (int i = 0; i < 4; i++) {
        int r0 = m0 + wm*64 + i*16 + (lane >> 2);
        int r1 = r0 + 8;
        float ws0 = wsum[r0], wb0 = wb[r0];
        float ws1v = wsum[r1], wb1 = wb[r1];
#pragma unroll
        for (int j = 0; j < 4; j++) {
            int c0 = n0 + wn*32 + j*8 + 2*(lane & 3);
            int p0 = b*LL + c0;
            float2 m2 = *(const float2*)(mu + p0);
            float2 s2 = *(const float2*)(rs + p0);
            float o0x = s2.x*(acc[i][j][0] - m2.x*ws0) + wb0;
            float o0y = s2.y*(acc[i][j][1] - m2.y*ws0) + wb0;
            float o1x = s2.x*(acc[i][j][2] - m2.x*ws1v) + wb1;
            float o1y = s2.y*(acc[i][j][3] - m2.y*ws1v) + wb1;
            Y16[((size_t)b*md + r0)*(LL/2) + (c0>>1)] = packf16(o0x, o0y);
            Y16[((size_t)b*md + r1)*(LL/2) + (c0>>1)] = packf16(o1x, o1y);
        }
    }
}

// ---------------------------------------------------------------------------
// General GEMM (modes 2/3): W1 gated, W2 final
// ---------------------------------------------------------------------------
template<int MODE, int KD, int MD, int MT, int NT>
__global__ __launch_bounds__(256, 2)
void gemm_mma(const u32* __restrict__ Ah,
              const u32* __restrict__ Xp,
              void* __restrict__ Yv,
              const float* __restrict__ mu, const float* __restrict__ rs,
              const float* __restrict__ wsum, const float* __restrict__ wb,
              const void* __restrict__ res, const float* __restrict__ bias)
{
    constexpr int B_STRc = NT*2 + 16;
    constexpr int BS = MT*A_STR;
    constexpr int STAGE = MT*A_STR + 64*B_STRc;
    constexpr int WN = (MT == 128) ? 4 : 2;
    constexpr int BSEG = NT/8;

    extern __shared__ __align__(128) char smem[];
    const u32 sbase = smem_u32(smem);

    int tid = threadIdx.x, lane = tid & 31, wid = tid >> 5;
    int n0 = blockIdx.x * NT, m0 = blockIdx.y * MT, b = blockIdx.z;
    int wm = wid / WN, wn = wid % WN;

    float acc[4][4][4];
#pragma unroll
    for (int i=0;i<4;i++)
#pragma unroll
        for (int j=0;j<4;j++)
#pragma unroll
            for (int r=0;r<4;r++) acc[i][j][r]=0.f;

    const u32* Xb = Xp + (size_t)b*KD*(LL/2) + (n0>>1);

    u32 a_lm_base = sbase + (u32)((wm*64 + (lane & 15)) * A_STR) + ((lane & 16) ? 16u : 0u);
    u32 b_lm_base = sbase + BS + (u32)((lane & 15) * B_STRc)
                  + (u32)((wn*32 + ((lane & 16) ? 8 : 0)) * 2);

#define ISSUE(st, kc) do { \
        u32 so = sbase + (u32)((st)*STAGE); \
        _Pragma("unroll") \
        for (int ii = tid; ii < MT*8; ii += 256) { \
            int row = ii >> 3, seg = ii & 7; \
            CP16(so + (u32)(row*A_STR + seg*16), \
                 Ah + (size_t)(m0+row)*(KD/2) + ((kc)>>1) + seg*4); \
        } \
        _Pragma("unroll") \
        for (int ii = tid; ii < 64*BSEG; ii += 256) { \
            int row = ii / BSEG, seg = ii % BSEG; \
            CP16(so + (u32)(BS + row*B_STRc + seg*16), \
                 Xb + (size_t)((kc)+row)*(LL/2) + seg*4); \
        } \
        CP_COMMIT(); \
    } while(0)

    ISSUE(0, 0);

#pragma unroll 1
    for (int kc = 0; kc < KD; kc += 64) {
        int cur = (kc >> 6) & 1;
        if (kc + 64 < KD) { ISSUE(cur ^ 1, kc + 64); CP_WAIT(1); }
        else              { CP_WAIT(0); }
        __syncthreads();
        u32 so = (u32)(cur * STAGE);
#pragma unroll
        for (int ks = 0; ks < 64; ks += 16) {
            u32 af[4][4], bf[4][2];
            u32 ab = a_lm_base + so + (u32)(ks*2);
#pragma unroll
            for (int i = 0; i < 4; i++)
                LDSM_X4(af[i][0], af[i][1], af[i][2], af[i][3], ab + (u32)(i*16*A_STR));
            u32 bb0 = b_lm_base + so + (u32)(ks*B_STRc);
#pragma unroll
            for (int j2 = 0; j2 < 2; j2++)
                LDSM_X4_T(bf[j2*2][0], bf[j2*2][1], bf[j2*2+1][0], bf[j2*2+1][1], bb0 + (u32)(j2*32));
#pragma unroll
            for (int i = 0; i < 4; i++)
#pragma unroll
                for (int j = 0; j < 4; j++)
                    MMA_F16(acc[i][j], af[i], bf[j][0], bf[j][1]);
        }
        __syncthreads();
    }
#undef ISSUE

    float* Y = (float*)Yv;
#pragma unroll
    for (int i = 0; i < 4; i++) {
        int r0 = m0 + wm*64 + i*16 + (lane >> 2);
        int r1 = r0 + 8;
        if (MODE == 3) {
            int t = ((r0 >> 4) << 3) + (r0 & 7);
            float ws1 = wsum[r0], wb1 = wb[r0];
            float ws2 = wsum[r1], wb2 = wb[r1];
#pragma unroll
            for (int j = 0; j < 4; j++) {
                int c0 = n0 + wn*32 + j*8 + 2*(lane & 3);
                int p0 = b*LL + c0;
                float2 m2 = *(const float2*)(mu + p0);
                float2 s2 = *(const float2*)(rs + p0);
                float e1x = s2.x*(acc[i][j][0] - m2.x*ws1) + wb1;
                float e1y = s2.y*(acc[i][j][1] - m2.y*ws1) + wb1;
                float e2x = s2.x*(acc[i][j][2] - m2.x*ws2) + wb2;
                float e2y = s2.y*(acc[i][j][3] - m2.y*ws2) + wb2;
                g_hg[((size_t)b*FH + t)*(LL/2) + (c0 >> 1)] = packf16(e1x*e2x, e1y*e2y);
            }
        } else { // MODE 2
            const u32* r16 = (const u32*)res;
            float bv0 = bias[r0], bv1 = bias[r1];
#pragma unroll
            for (int j = 0; j < 4; j++) {
                int c0 = n0 + wn*32 + j*8 + 2*(lane & 3);
                float2 a0 = unpackf16(r16[((size_t)b*MD + r0)*(LL/2) + (c0>>1)]);
                float2 a1 = unpackf16(r16[((size_t)b*MD + r1)*(LL/2) + (c0>>1)]);
                float* y0 = Y + (size_t)b*MD*LL + (size_t)r0*LL + c0;
                float* y1 = Y + (size_t)b*MD*LL + (size_t)r1*LL + c0;
                *(float2*)y0 = make_float2(acc[i][j][0] + bv0 + a0.x, acc[i][j][1] + bv0 + a0.y);
                *(float2*)y1 = make_float2(acc[i][j][2] + bv1 + a1.x, acc[i][j][3] + bv1 + a1.y);
            }
        }
    }
}

// ---------------------------------------------------------------------------
// Fused Wo GEMM with inline A@V B-tile construction + residual + LN stats.
// grid (64, 1, BB), 256 threads. MT=256, NT=64.
// smem: [B region 256*144][A weights 2 stages x 256*144]
// ---------------------------------------------------------------------------
#define WO_BSTR 144
#define WO_A    (256*WO_BSTR)          // 36864
#define WO_STAGE (256*A_STR)           // 36864
#define WO_SMEM (WO_A + 2*WO_STAGE)    // 110592

__global__ __launch_bounds__(256, 2)
void gemm_wo_av(const float* __restrict__ res)
{
    extern __shared__ __align__(128) char smem[];
    const u32 sbase = smem_u32(smem);
    int tid = threadIdx.x, lane = tid & 31, wid = tid >> 5;
    int n0 = blockIdx.x * 64, b = blockIdx.z;

    // ---- issue V tile (256 rows x 64 cols fp16) into B region + A chunk 0
    const u32* Vb = g_kv16 + ((size_t)b*2*CC + CC)*(LL/2) + (n0>>1);
#pragma unroll
    for (int ii = tid; ii < 256*8; ii += 256) {
        int row = ii >> 3, seg = ii & 7;
        CP16(sbase + (u32)(row*WO_BSTR + seg*16), Vb + (size_t)row*(LL/2) + seg*4);
    }
    CP_COMMIT();
#pragma unroll
    for (int ii = tid; ii < 256*8; ii += 256) {
        int row = ii >> 3, seg = ii & 7;
        CP16(sbase + (u32)(WO_A + row*A_STR + seg*16), g_Ao + (size_t)row*128 + seg*4);
    }
    CP_COMMIT();
    CP_WAIT(1);   // V done (A0 may still be in flight)
    __syncthreads();

    // ---- per-warp A@V: head w.  A_w from g_A16 (fp16), V via LDSM_T from smem.
    {
        float av[2][8][4];
#pragma unroll
        for (int i=0;i<2;i++)
#pragma unroll
            for (int j=0;j<8;j++)
#pragma unroll
                for (int r=0;r<4;r++) av[i][j][r]=0.f;
        const u32* Ab = g_A16 + (size_t)(b*NHH + wid)*512;
        int r0 = lane >> 2, cq = lane & 3;
#pragma unroll
        for (int s = 0; s < 2; s++) {
            u32 af[2][4];
#pragma unroll
            for (int i = 0; i < 2; i++) {
                af[i][0] = Ab[(i*16 + r0     )*16 + s*8 + cq];
                af[i][1] = Ab[(i*16 + r0 + 8 )*16 + s*8 + cq];
                af[i][2] = Ab[(i*16 + r0     )*16 + s*8 + cq + 4];
                af[i][3] = Ab[(i*16 + r0 + 8 )*16 + s*8 + cq + 4];
            }
            u32 vrow = sbase + (u32)((wid*32 + s*16 + (lane & 15))*WO_BSTR)
                     + ((lane & 16) ? 16u : 0u);
            u32 bf[8][2];
#pragma unroll
            for (int j2 = 0; j2 < 4; j2++)
                LDSM_X4_T(bf[j2*2][0], bf[j2*2][1], bf[j2*2+1][0], bf[j2*2+1][1],
                          vrow + (u32)(j2*32));
#pragma unroll
            for (int i = 0; i < 2; i++)
#pragma unroll
                for (int j = 0; j < 8; j++)
                    MMA_F16(av[i][j], af[i], bf[j][0], bf[j][1]);
        }
        // write product back over V region (warp-local rows)
#pragma unroll
        for (int i = 0; i < 2; i++) {
            int row = wid*32 + i*16 + (lane >> 2);
#pragma unroll
            for (int j = 0; j < 8; j++) {
                int c0 = j*8 + 2*(lane & 3);
                *(u32*)(smem + row*WO_BSTR + c0*2)     = packf16(av[i][j][0], av[i][j][1]);
                *(u32*)(smem + (row+8)*WO_BSTR + c0*2) = packf16(av[i][j][2], av[i][j][3]);
            }
        }
    }
    __syncthreads();

    // ---- mainloop: stream Wo weights vs static B region
    int wm = wid >> 1, wn = wid & 1;
    float acc[4][4][4];
#pragma unroll
    for (int i=0;i<4;i++)
#pragma unroll
        for (int j=0;j<4;j++)
#pragma unroll
            for (int r=0;r<4;r++) acc[i][j][r]=0.f;

    u32 a_lm_base = sbase + (u32)(WO_A + (wm*64 + (lane & 15)) * A_STR) + ((lane & 16) ? 16u : 0u);
    u32 b_lm_base = sbase + (u32)((lane & 15) * WO_BSTR)
                  + (u32)((wn*32 + ((lane & 16) ? 8 : 0)) * 2);

#pragma unroll 1
    for (int kc = 0; kc < 256; kc += 64) {
        int cur = (kc >> 6) & 1;
        if (kc + 64 < 256) {
            u32 so = sbase + (u32)(WO_A + (cur^1)*WO_STAGE);
#pragma unroll
            for (int ii = tid; ii < 256*8; ii += 256) {
                int row = ii >> 3, seg = ii & 7;
                CP16(so + (u32)(row*A_STR + seg*16),
                     g_Ao + (size_t)row*128 + ((kc+64)>>1) + seg*4);
            }
            CP_COMMIT();
            CP_WAIT(1);
        } else {
            CP_WAIT(0);
        }
        __syncthreads();
        u32 so = (u32)(cur * WO_STAGE);
#pragma unroll
        for (int ks = 0; ks < 64; ks += 16) {
            u32 af[4][4], bf[4][2];
            u32 ab = a_lm_base + so + (u32)(ks*2);
#pragma unroll
            for (int i = 0; i < 4; i++)
                LDSM_X4(af[i][0], af[i][1], af[i][2], af[i][3], ab + (u32)(i*16*A_STR));
            u32 bb0 = b_lm_base + (u32)((kc + ks)*WO_BSTR);
#pragma unroll
            for (int j2 = 0; j2 < 2; j2++)
                LDSM_X4_T(bf[j2*2][0], bf[j2*2][1], bf[j2*2+1][0], bf[j2*2+1][1], bb0 + (u32)(j2*32));
#pragma unroll
            for (int i = 0; i < 4; i++)
#pragma unroll
                for (int j = 0; j < 4; j++)
                    MMA_F16(acc[i][j], af[i], bf[j][0], bf[j][1]);
        }
        __syncthreads();
    }

    // ---- epilogue: +residual (fp32), write x16 fp16, LN stats
    float cs[4][4];
#pragma unroll
    for (int j=0;j<4;j++)
#pragma unroll
        for (int k=0;k<4;k++) cs[j][k]=0.f;
#pragma unroll
    for (int i = 0; i < 4; i++) {
        int r0 = wm*64 + i*16 + (lane >> 2);
        int r1 = r0 + 8;
#pragma unroll
        for (int j = 0; j < 4; j++) {
            int c0 = n0 + wn*32 + j*8 + 2*(lane & 3);
            const float* q0 = res + (size_t)b*CC*LL + (size_t)r0*LL + c0;
            const float* q1 = res + (size_t)b*CC*LL + (size_t)r1*LL + c0;
            float2 a0 = *(const float2*)q0, a1 = *(const float2*)q1;
            float y00 = acc[i][j][0] + a0.x, y01 = acc[i][j][1] + a0.y;
            float y10 = acc[i][j][2] + a1.x, y11 = acc[i][j][3] + a1.y;
            g_x16[((size_t)b*CC + r0)*(LL/2) + (c0>>1)] = packf16(y00, y01);
            g_x16[((size_t)b*CC + r1)*(LL/2) + (c0>>1)] = packf16(y10, y11);
            cs[j][0] += y00 + y10;
            cs[j][1] += y00*y00 + y10*y10;
            cs[j][2] += y01 + y11;
            cs[j][3] += y01*y01 + y11*y11;
        }
    }
    {
        float4 (*red)[32] = (float4(*)[32])smem;
#pragma unroll
        for (int j = 0; j < 4; j++)
#pragma unroll
            for (int o = 4; o < 32; o <<= 1) {
                cs[j][0] += __shfl_xor_sync(0xffffffffu, cs[j][0], o);
                cs[j][1] += __shfl_xor_sync(0xffffffffu, cs[j][1], o);
                cs[j][2] += __shfl_xor_sync(0xffffffffu, cs[j][2], o);
                cs[j][3] += __shfl_xor_sync(0xffffffffu, cs[j][3], o);
            }
        if (lane < 4) {
#pragma unroll
            for (int j = 0; j < 4; j++) {
                int cp = wn*16 + j*4 + lane;
                red[wm][cp] = make_float4(cs[j][0], cs[j][1], cs[j][2], cs[j][3]);
            }
        }
        __syncthreads();
        if (tid < 32) {
            float4 t0 = red[0][tid], t1 = red[1][tid], t2 = red[2][tid], t3 = red[3][tid];
            float sx  = t0.x+t1.x+t2.x+t3.x;
            float sx2 = t0.y+t1.y+t2.y+t3.y;
            float sy  = t0.z+t1.z+t2.z+t3.z;
            float sy2 = t0.w+t1.w+t2.w+t3.w;
            float mx = sx*(1.f/CC), my = sy*(1.f/CC);
            int p = b*LL + n0 + 2*tid;
            g_mu_x[p]   = mx; g_rs_x[p]   = rsqrtf(fmaf(-mx, mx, sx2*(1.f/CC)) + 1e-5f);
            g_mu_x[p+1] = my; g_rs_x[p+1] = rsqrtf(fmaf(-my, my, sy2*(1.f/CC)) + 1e-5f);
        }
    }
}

// ---------------------------------------------------------------------------
// Attention S via mma.sync (unchanged from R11) + softmax -> packed fp16 A
// ---------------------------------------------------------------------------
#define QSTR 528
#define ATILE (32*QSTR)
#define ASTAGE (2*ATILE)
#define AS_SMEM (2*ASTAGE)

__global__ __launch_bounds__(256, 2)
void attn_s_kernel()
{
    extern __shared__ __align__(128) char smem[];
    const u32 sbase = smem_u32(smem);
    int bh = blockIdx.x, sp = blockIdx.y;
    int b = bh >> 3, h = bh & 7;
    int tid = threadIdx.x, lane = tid & 31, wid = tid >> 5;
    const u32* qp = g_q16  + ((size_t)b*CC   + h*HCC)*(LL/2) + sp*1024;
    const u32* kp = g_kv16 + ((size_t)b*2*CC + h*HCC)*(LL/2) + sp*1024;

    float acc[2][4][4];
#pragma unroll
    for (int i=0;i<2;i++)
#pragma unroll
        for (int j=0;j<4;j++)
#pragma unroll
            for (int r=0;r<4;r++) acc[i][j][r]=0.f;

#define ISSUEA(st, ch) do { \
        u32 so = sbase + (u32)((st)*ASTAGE); \
        _Pragma("unroll") \
        for (int ii = tid; ii < 1024; ii += 256) { \
            int row = ii >> 5, seg = ii & 31; \
            CP16(so + (u32)(row*QSTR + seg*16), \
                 qp + (size_t)row*(LL/2) + (ch)*128 + seg*4); \
            CP16(so + (u32)(ATILE + row*QSTR + seg*16), \
                 kp + (size_t)row*(LL/2) + (ch)*128 + seg*4); \
        } \
        CP_COMMIT(); \
    } while(0)

    ISSUEA(0, 0);
    u32 woff = (u32)(wid * 64);
#pragma unroll 1
    for (int ch = 0; ch < 8; ch++) {
        int cur = ch & 1;
        if (ch + 1 < 8) { ISSUEA(cur ^ 1, ch + 1); CP_WAIT(1); }
        else            { CP_WAIT(0); }
        __syncthreads();
        u32 qb = sbase + (u32)(cur*ASTAGE);
        u32 kb = qb + ATILE;
#pragma unroll
        for (int s = 0; s < 2; s++) {
            u32 koff = woff + (u32)(s*32);
            u32 af[2][4], bf[4][2];
            u32 aaddr = qb + (u32)((lane & 15)*QSTR) + ((lane & 16) ? 16u : 0u) + koff;
            LDSM_X4(af[0][0], af[0][1], af[0][2], af[0][3], aaddr);
            LDSM_X4(af[1][0], af[1][1], af[1][2], af[1][3], aaddr + (u32)(16*QSTR));
            u32 baddr = kb + (u32)(((lane & 7) + ((lane & 16) ? 8 : 0))*QSTR)
                      + ((lane & 8) ? 16u : 0u) + koff;
            LDSM_X4(bf[0][0], bf[0][1], bf[1][0], bf[1][1], baddr);
            LDSM_X4(bf[2][0], bf[2][1], bf[3][0], bf[3][1], baddr + (u32)(16*QSTR));
#pragma unroll
            for (int i = 0; i < 2; i++)
#pragma unroll
                for (int j = 0; j < 4; j++)
                    MMA_F16(acc[i][j], af[i], bf[j][0], bf[j][1]);
        }
        __syncthreads();
    }
#undef ISSUEA

    float* part = (float*)smem;
#pragma unroll
    for (int i = 0; i < 2; i++)
#pragma unroll
        for (int j = 0; j < 4; j++)
#pragma unroll
            for (int r = 0; r < 4; r++) {
                int row = i*16 + (lane >> 2) + ((r & 2) ? 8 : 0);
                int col = j*8 + (lane & 3)*2 + (r & 1);
                part[wid*1024 + row*32 + col] = acc[i][j][r];
            }
    __syncthreads();
    float* out = g_Sp + ((size_t)bh*NSP + sp)*1024;
#pragma unroll
    for (int e = tid; e < 1024; e += 256) {
        float s = 0.f;
#pragma unroll
        for (int w = 0; w < 8; w++) s += part[w*1024 + e];
        out[e] = s;
    }
}

__global__ void attn_softmax_kernel()   // grid BB*NHH, 1024 threads
{
    int bh = blockIdx.x, t = threadIdx.x;
    const float* sp = g_Sp + (size_t)bh*NSP*1024 + t;
    float s = sp[0] + sp[1024];
    s *= 0.17677669529663687f;
    float mx = s;
#pragma unroll
    for (int o = 16; o > 0; o >>= 1) mx = fmaxf(mx, __shfl_xor_sync(0xffffffffu, mx, o));
    float e = expf(s - mx);
    float sum = e;
#pragma unroll
    for (int o = 16; o > 0; o >>= 1) sum += __shfl_xor_sync(0xffffffffu, sum, o);
    float a = e / sum;
    float ap = __shfl_xor_sync(0xffffffffu, a, 1);
    int c = t >> 5, d = t & 31;
    if (!(d & 1)) g_A16[(size_t)bh*512 + c*16 + (d >> 1)] = packf16(a, ap);
}

// ---------------------------------------------------------------------------
// Launcher
// ---------------------------------------------------------------------------
#define GS_128 (2*(128*A_STR + 64*(128*2+16)))   // 71680

extern "C" void kernel_launch(void* const* d_in, const int* in_sizes, int n_in,
                              void* d_out, int out_size)
{
    (void)in_sizes; (void)n_in; (void)out_size;
    const float* optical = (const float*)d_in[0];
    const float* sar     = (const float*)d_in[1];
    const float* gopt    = (const float*)d_in[2];
    const float* bopt    = (const float*)d_in[3];
    const float* gsar    = (const float*)d_in[4];
    const float* bsar    = (const float*)d_in[5];
    const float* Wq      = (const float*)d_in[6];
    const float* Wk      = (const float*)d_in[7];
    const float* Wv      = (const float*)d_in[8];
    const float* Wo      = (const float*)d_in[9];
    const float* gffn    = (const float*)d_in[10];
    const float* bffn    = (const float*)d_in[11];
    const float* W1      = (const float*)d_in[12];
    const float* b1      = (const float*)d_in[13];
    const float* W2      = (const float*)d_in[14];
    const float* b2      = (const float*)d_in[15];
    float* out = (float*)d_out;

    float *p_ws1,*p_wb1,*p_mu_x,*p_rs_x;
    u32 *p_A1,*p_A2,*p_x16,*p_hg;
    cudaGetSymbolAddress((void**)&p_ws1, g_ws1);     cudaGetSymbolAddress((void**)&p_wb1, g_wb1v);
    cudaGetSymbolAddress((void**)&p_mu_x, g_mu_x);   cudaGetSymbolAddress((void**)&p_rs_x, g_rs_x);
    cudaGetSymbolAddress((void**)&p_A1, g_A1);       cudaGetSymbolAddress((void**)&p_A2, g_A2);
    cudaGetSymbolAddress((void**)&p_x16, g_x16);     cudaGetSymbolAddress((void**)&p_hg, g_hg);

    cudaFuncSetAttribute((void*)gemm_qkv,                    cudaFuncAttributeMaxDynamicSharedMemorySize, GS_128);
    cudaFuncSetAttribute((void*)gemm_wo_av,                  cudaFuncAttributeMaxDynamicSharedMemorySize, WO_SMEM);
    cudaFuncSetAttribute((void*)gemm_mma<3,256,FH2,128,128>, cudaFuncAttributeMaxDynamicSharedMemorySize, GS_128);
    cudaFuncSetAttribute((void*)gemm_mma<2,512,256,128,128>, cudaFuncAttributeMaxDynamicSharedMemorySize, GS_128);
    cudaFuncSetAttribute((void*)attn_s_kernel,               cudaFuncAttributeMaxDynamicSharedMemorySize, AS_SMEM);

    // 1) weight prep (one launch)
    prep_fold<<<2560, 256>>>(Wq, Wk, Wv, W1, Wo, W2,
                             gopt, bopt, gsar, bsar, gffn, bffn, b1);

    // 2) LN stats + fp16 conversion (both inputs, one launch)
    ln_conv_kernel<<<dim3((NPIX/2)/128, 2), 512>>>(optical, sar);

    // 3) fused Q + K/V projections -> fp16
    gemm_qkv<<<dim3(32, 6, BB), 256, GS_128>>>();

    // 4) channel attention: MMA partial S (2 L-splits), softmax -> fp16 A
    attn_s_kernel<<<dim3(BB*NHH, NSP), 256, AS_SMEM>>>();
    attn_softmax_kernel<<<BB*NHH, 1024>>>();

    // 5) Wo GEMM with inline A@V + residual(optical) + LN stats -> x16
    gemm_wo_av<<<dim3(64, 1, BB), 256, WO_SMEM>>>(optical);

    // 6) W1 (LN+b1 folded, row-paired) + fused SimpleGate -> hg (fp16)
    gemm_mma<3,256,FH2,128,128><<<dim3(32,8,BB),256,GS_128>>>(p_A1, p_x16, (void*)0, p_mu_x, p_rs_x, p_ws1, p_wb1, 0, 0);

    // 7) W2 + b2 + residual(x16) -> out fp32
    gemm_mma<2,512,256,128,128><<<dim3(32,2,BB),256,GS_128>>>(p_A2, p_hg, out, 0, 0, 0, 0, p_x16, b2);
}